// round 7
// baseline (speedup 1.0000x reference)
#include <cuda_runtime.h>
#include <math.h>

typedef unsigned long long ull;

// Problem constants
#define Bq 4
#define Tt 256
#define Dd 256
#define D2 512
#define BT 1024
#define SCALEF 0.0625f
#define BK 16

// ---------------- scratch (static device globals; no allocation) -------------
__device__ float g_xnorm[BT * Dd];
__device__ float g_xleft[BT * D2];
__device__ float g_xright[BT * D2];
__device__ float g_xtrans[BT * D2];
__device__ float g_o[BT * D2];
__device__ float g_q[BT * D2];
__device__ float g_k[BT * D2];
__device__ float g_v[BT * D2];
__device__ float g_hseq[BT * D2];
__device__ float g_h[BT * D2];
__device__ float g_convwt[4 * D2 * D2];
__device__ float g_cp[8 * BT * D2];     // split-K partials (8 x 2MB)
__device__ float g_A[Bq * Tt * Tt];
__device__ float g_ib[BT];
__device__ float g_fb[BT];
__device__ float g_alpha[BT];
__device__ float g_beta[BT];
__device__ float g_rowsum[BT];
__device__ float g_gnmu[16];
__device__ float g_gnrs[16];

#define PSLICE (BT * D2)   // 524288 floats per partial slice

__device__ __forceinline__ float sigm(float x) { return 1.f / (1.f + __expf(-x)); }

// ---------------- packed f32x2 helpers ----------------
__device__ __forceinline__ ull packf2(float lo, float hi) {
    ull r; asm("mov.b64 %0, {%1, %2};" : "=l"(r) : "f"(lo), "f"(hi)); return r;
}
__device__ __forceinline__ void fma2(ull& d, ull a, ull b) {
    asm("fma.rn.f32x2 %0, %1, %2, %0;" : "+l"(d) : "l"(a), "l"(b));
}
__device__ __forceinline__ float2 unpackf2(ull v) {
    float2 f; asm("mov.b64 {%0, %1}, %2;" : "=f"(f.x), "=f"(f.y) : "l"(v)); return f;
}

// =====================  64x128 high-intensity core  ==========================
struct SmemT {
    __align__(16) float As[2][BK][68];
    __align__(16) float Bs[2][BK][132];
};

// acc[r][c]: row (ty*4+r), cols (tx*8+2c, tx*8+2c+1)
__device__ __forceinline__ void mma128(const SmemT* s, int buf, int ty, int tx,
                                       ull (&acc)[4][4]) {
#pragma unroll
    for (int kk = 0; kk < BK; kk++) {
        float4 av = *(const float4*)&s->As[buf][kk][ty * 4];
        ull pa0 = packf2(av.x, av.x), pa1 = packf2(av.y, av.y);
        ull pa2 = packf2(av.z, av.z), pa3 = packf2(av.w, av.w);
        ulonglong2 q0 = *(const ulonglong2*)&s->Bs[buf][kk][tx * 8];
        ulonglong2 q1 = *(const ulonglong2*)&s->Bs[buf][kk][tx * 8 + 4];
        ull bp[4] = {q0.x, q0.y, q1.x, q1.y};
#pragma unroll
        for (int c = 0; c < 4; c++) {
            fma2(acc[0][c], pa0, bp[c]);
            fma2(acc[1][c], pa1, bp[c]);
            fma2(acc[2][c], pa2, bp[c]);
            fma2(acc[3][c], pa3, bp[c]);
        }
    }
}

// Double-buffered K loop. Ap: this thread's A ptr (row m0+(tid>>2), col kqA).
// Bp: this thread's W ptr (row n0+(tid>>1), col kqB). Both advance BK/iter.
__device__ __forceinline__ void gemm_loop(SmemT* s, const float* Ap, const float* Bp,
                                          int iters, bool avalid, ull (&acc)[4][4],
                                          int tid) {
    int kqA = (tid & 3) * 4, rowAs = tid >> 2;
    int kqB = (tid & 1) * 8, rowBs = tid >> 1;
    int ty = tid >> 4, tx = tid & 15;
    float4 a = avalid ? *(const float4*)Ap : make_float4(0.f, 0.f, 0.f, 0.f);
    float4 b0 = *(const float4*)Bp;
    float4 b1 = *(const float4*)(Bp + 4);
#pragma unroll
    for (int i = 0; i < 4; i++) s->As[0][kqA + i][rowAs] = (&a.x)[i];
#pragma unroll
    for (int i = 0; i < 4; i++) {
        s->Bs[0][kqB + i][rowBs] = (&b0.x)[i];
        s->Bs[0][kqB + 4 + i][rowBs] = (&b1.x)[i];
    }
    __syncthreads();
    int buf = 0;
    for (int it = 1; it < iters; it++) {
        a = avalid ? *(const float4*)(Ap + it * BK) : make_float4(0.f, 0.f, 0.f, 0.f);
        b0 = *(const float4*)(Bp + it * BK);
        b1 = *(const float4*)(Bp + it * BK + 4);
        mma128(s, buf, ty, tx, acc);
        int nb = buf ^ 1;
#pragma unroll
        for (int i = 0; i < 4; i++) s->As[nb][kqA + i][rowAs] = (&a.x)[i];
#pragma unroll
        for (int i = 0; i < 4; i++) {
            s->Bs[nb][kqB + i][rowBs] = (&b0.x)[i];
            s->Bs[nb][kqB + 4 + i][rowBs] = (&b1.x)[i];
        }
        __syncthreads();
        buf = nb;
    }
    mma128(s, buf, ty, tx, acc);
}

__device__ __forceinline__ void unpack_row(ull (&accr)[4], float (&o)[8]) {
#pragma unroll
    for (int c = 0; c < 4; c++) {
        float2 u = unpackf2(accr[c]);
        o[2 * c] = u.x; o[2 * c + 1] = u.y;
    }
}

// ---------------- fused dual projection: z picks (W,b,C) set -----------------
__global__ __launch_bounds__(256) void k_projdual(const float* __restrict__ A,
                                                  const float* __restrict__ W1,
                                                  const float* __restrict__ b1,
                                                  float* __restrict__ C1,
                                                  const float* __restrict__ W2,
                                                  const float* __restrict__ b2,
                                                  float* __restrict__ C2, int K) {
    __shared__ SmemT s;
    int tid = threadIdx.x;
    const float* W = blockIdx.z ? W2 : W1;
    const float* bias = blockIdx.z ? b2 : b1;
    float* C = blockIdx.z ? C2 : C1;
    int m0 = blockIdx.y * 64, n0 = blockIdx.x * 128;
    const float* Ap = A + (size_t)(m0 + (tid >> 2)) * K + (tid & 3) * 4;
    const float* Bp = W + (size_t)(n0 + (tid >> 1)) * K + (tid & 1) * 8;
    ull acc[4][4] = {};
    gemm_loop(&s, Ap, Bp, K / BK, true, acc, tid);
    int ty = tid >> 4, tx = tid & 15;
#pragma unroll
    for (int r = 0; r < 4; r++) {
        int m = m0 + ty * 4 + r, n = n0 + tx * 8;
        float o[8]; unpack_row(acc[r], o);
        float4 v0 = *(const float4*)&bias[n], v1 = *(const float4*)&bias[n + 4];
        *(float4*)&C[(size_t)m * D2 + n] =
            make_float4(o[0] + v0.x, o[1] + v0.y, o[2] + v0.z, o[3] + v0.w);
        *(float4*)&C[(size_t)m * D2 + n + 4] =
            make_float4(o[4] + v1.x, o[5] + v1.y, o[6] + v1.z, o[7] + v1.w);
    }
}

// ---------------- generic split-K partial GEMM -> g_cp slice -----------------
__global__ __launch_bounds__(256) void k_partial(const float* __restrict__ A,
                                                 const float* __restrict__ W,
                                                 int Ktot, int Ksub, int N) {
    __shared__ SmemT s;
    int tid = threadIdx.x;
    int m0 = blockIdx.y * 64, n0 = blockIdx.x * 128, sp = blockIdx.z;
    const float* Ap = A + (size_t)(m0 + (tid >> 2)) * Ktot + sp * Ksub + (tid & 3) * 4;
    const float* Bp = W + (size_t)(n0 + (tid >> 1)) * Ktot + sp * Ksub + (tid & 1) * 8;
    ull acc[4][4] = {};
    gemm_loop(&s, Ap, Bp, Ksub / BK, true, acc, tid);
    int ty = tid >> 4, tx = tid & 15;
    float* out = g_cp + (size_t)sp * PSLICE;
#pragma unroll
    for (int r = 0; r < 4; r++) {
        int m = m0 + ty * 4 + r, n = n0 + tx * 8;
        float o[8]; unpack_row(acc[r], o);
        *(float4*)&out[(size_t)m * N + n] = make_float4(o[0], o[1], o[2], o[3]);
        *(float4*)&out[(size_t)m * N + n + 4] = make_float4(o[4], o[5], o[6], o[7]);
    }
}

// ---------------- conv partial: z = tau*2 + khalf -----------------
__global__ __launch_bounds__(256) void k_convp() {
    __shared__ SmemT s;
    int tid = threadIdx.x;
    int tau = blockIdx.z >> 1, half = blockIdx.z & 1;
    int m0 = blockIdx.y * 64, n0 = blockIdx.x * 128;
    int row = m0 + (tid >> 2), b = row >> 8, t = row & 255;
    int tp = t - 3 + tau;
    bool avalid = (tp >= 0);
    int tpc = avalid ? tp : 0;
    const float* Ap = g_xleft + (size_t)(b * Tt + tpc) * D2 + half * 256 + (tid & 3) * 4;
    const float* Bp = g_convwt + (size_t)tau * 262144 +
                      (size_t)(n0 + (tid >> 1)) * D2 + half * 256 + (tid & 1) * 8;
    ull acc[4][4] = {};
    gemm_loop(&s, Ap, Bp, 256 / BK, avalid, acc, tid);
    int ty = tid >> 4, tx = tid & 15;
    float* out = g_cp + (size_t)blockIdx.z * PSLICE;
#pragma unroll
    for (int r = 0; r < 4; r++) {
        int m = m0 + ty * 4 + r, n = n0 + tx * 8;
        float o[8]; unpack_row(acc[r], o);
        *(float4*)&out[(size_t)m * D2 + n] = make_float4(o[0], o[1], o[2], o[3]);
        *(float4*)&out[(size_t)m * D2 + n + 4] = make_float4(o[4], o[5], o[6], o[7]);
    }
}

// ---------------- qkv on 64x128 core (whole head per tile) -------------------
__global__ __launch_bounds__(256) void k_qkv(const float* __restrict__ Wq,
                                             const float* __restrict__ Wk,
                                             const float* __restrict__ Wv) {
    __shared__ SmemT s;
    int tid = threadIdx.x;
    int z = blockIdx.z, which = z >> 2, h = z & 3;
    const float* src = (which == 2) ? g_xleft : g_xtrans;
    const float* W = (which == 0) ? Wq : ((which == 1) ? Wk : Wv);
    float* dst = (which == 0) ? g_q : ((which == 1) ? g_k : g_v);
    float sc = (which == 1) ? SCALEF : 1.f;
    int m0 = blockIdx.y * 64;
    const float* Ap = src + (size_t)(m0 + (tid >> 2)) * D2 + h * 128 + (tid & 3) * 4;
    const float* Bp = W + (size_t)h * 16384 + (size_t)(tid >> 1) * 128 + (tid & 1) * 8;
    ull acc[4][4] = {};
    gemm_loop(&s, Ap, Bp, 128 / BK, true, acc, tid);
    int ty = tid >> 4, tx = tid & 15;
#pragma unroll
    for (int r = 0; r < 4; r++) {
        int m = m0 + ty * 4 + r, n = h * 128 + tx * 8;
        float o[8]; unpack_row(acc[r], o);
        *(float4*)&dst[(size_t)m * D2 + n] =
            make_float4(sc * o[0], sc * o[1], sc * o[2], sc * o[3]);
        *(float4*)&dst[(size_t)m * D2 + n + 4] =
            make_float4(sc * o[4], sc * o[5], sc * o[6], sc * o[7]);
    }
}

// ====================  reduce / epilogue kernels  ============================
__global__ void k_cepi(const float* __restrict__ cb) {   // 8 parts + bias + swish
    int idx = blockIdx.x * 256 + threadIdx.x;            // float4 idx, 131072
    size_t off = (size_t)idx * 4;
    float4 sm = *(const float4*)(g_cp + off);
#pragma unroll
    for (int p = 1; p < 8; p++) {
        float4 q = *(const float4*)(g_cp + (size_t)p * PSLICE + off);
        sm.x += q.x; sm.y += q.y; sm.z += q.z; sm.w += q.w;
    }
    int n = (idx & 127) * 4;
    float4 b4 = *(const float4*)&cb[n];
    float z0 = sm.x + b4.x, z1 = sm.y + b4.y, z2 = sm.z + b4.z, z3 = sm.w + b4.w;
    *(float4*)(g_xtrans + off) = make_float4(z0 * sigm(z0), z1 * sigm(z1),
                                             z2 * sigm(z2), z3 * sigm(z3));
}

__global__ void k_wepi(const float* __restrict__ bo) {   // 2 parts + bias, sigmoid
    int idx = blockIdx.x * 256 + threadIdx.x;
    size_t off = (size_t)idx * 4;
    float4 s0 = *(const float4*)(g_cp + off);
    float4 s1 = *(const float4*)(g_cp + PSLICE + off);
    int n = (idx & 127) * 4;
    float4 b4 = *(const float4*)&bo[n];
    *(float4*)(g_o + off) = make_float4(sigm(s0.x + s1.x + b4.x), sigm(s0.y + s1.y + b4.y),
                                        sigm(s0.z + s1.z + b4.z), sigm(s0.w + s1.w + b4.w));
}

__global__ void k_sepi(const float* __restrict__ gn_g, const float* __restrict__ gn_b) {
    int idx = blockIdx.x * 256 + threadIdx.x;            // float4 idx over g_h
    size_t off = (size_t)idx * 4;
    float4 s0 = *(const float4*)(g_cp + off);
    float4 s1 = *(const float4*)(g_cp + PSLICE + off);
    int n = (idx & 127) * 4;
    int m = idx >> 7;
    int b = m >> 8, hh = n >> 7;
    float mu = g_gnmu[b * 4 + hh], rs = g_gnrs[b * 4 + hh];
    float4 hs = *(const float4*)(g_hseq + off);
    float4 xr = *(const float4*)(g_xright + off);
    float4 gg = *(const float4*)&gn_g[n];
    float4 gb = *(const float4*)&gn_b[n];
    float sv[4] = {s0.x + s1.x, s0.y + s1.y, s0.z + s1.z, s0.w + s1.w};
    float hv[4] = {hs.x, hs.y, hs.z, hs.w};
    float xv[4] = {xr.x, xr.y, xr.z, xr.w};
    float ggv[4] = {gg.x, gg.y, gg.z, gg.w};
    float gbv[4] = {gb.x, gb.y, gb.z, gb.w};
    float ov[4];
#pragma unroll
    for (int j = 0; j < 4; j++) {
        float zn = (hv[j] - mu) * rs;
        float hg = zn * ggv[j] + gbv[j] + sv[j];
        ov[j] = hg * xv[j] * sigm(xv[j]);
    }
    *(float4*)(g_h + off) = make_float4(ov[0], ov[1], ov[2], ov[3]);
}

__global__ void k_lepi(const float* __restrict__ bl, const float* __restrict__ x,
                       float* __restrict__ out) {        // 4 parts + bias + residual
    int idx = blockIdx.x * 256 + threadIdx.x;            // float4 idx, 65536
    size_t off = (size_t)idx * 4;
    float4 sm = *(const float4*)(g_cp + off);
#pragma unroll
    for (int p = 1; p < 4; p++) {
        float4 q = *(const float4*)(g_cp + (size_t)p * PSLICE + off);
        sm.x += q.x; sm.y += q.y; sm.z += q.z; sm.w += q.w;
    }
    int n = (idx & 63) * 4;
    float4 b4 = *(const float4*)&bl[n];
    float4 xv = *(const float4*)(x + off);
    *(float4*)(out + off) = make_float4(sm.x + b4.x + xv.x, sm.y + b4.y + xv.y,
                                        sm.z + b4.z + xv.z, sm.w + b4.w + xv.w);
}

// ====================  small kernels  ============================
__global__ void k_layernorm(const float* __restrict__ x, const float* __restrict__ g,
                            const float* __restrict__ b) {
    int row = blockIdx.x, tid = threadIdx.x;
    float v = x[row * Dd + tid];
    float s = v, s2 = v * v;
#pragma unroll
    for (int o = 16; o; o >>= 1) {
        s += __shfl_xor_sync(0xffffffffu, s, o);
        s2 += __shfl_xor_sync(0xffffffffu, s2, o);
    }
    __shared__ float sh[8], sh2[8];
    int w = tid >> 5, l = tid & 31;
    if (l == 0) { sh[w] = s; sh2[w] = s2; }
    __syncthreads();
    if (tid == 0) {
        float a = 0, a2 = 0;
#pragma unroll
        for (int i = 0; i < 8; i++) { a += sh[i]; a2 += sh2[i]; }
        sh[0] = a; sh2[0] = a2;
    }
    __syncthreads();
    float mu = sh[0] * (1.f / Dd);
    float var = sh2[0] * (1.f / Dd) - mu * mu;
    float r = rsqrtf(var + 1e-5f);
    g_xnorm[row * Dd + tid] = (v - mu) * r * g[tid] + b[tid];
}

__global__ void k_convwt(const float* __restrict__ cw) {
    int idx = blockIdx.x * 256 + threadIdx.x;
    float4 w = *(const float4*)(cw + (size_t)idx * 4);
    g_convwt[0 * 262144 + idx] = w.x;
    g_convwt[1 * 262144 + idx] = w.y;
    g_convwt[2 * 262144 + idx] = w.z;
    g_convwt[3 * 262144 + idx] = w.w;
}

__global__ void k_ibfb(const float* __restrict__ Wi, const float* __restrict__ Wf,
                       const float* __restrict__ bi, const float* __restrict__ bf) {
    int row = blockIdx.x * 8 + (threadIdx.x >> 5);
    int l = threadIdx.x & 31;
    const float* xr = g_xleft + (size_t)row * D2;
    float si = 0, sf = 0;
#pragma unroll 4
    for (int j = l; j < D2; j += 32) {
        float v = xr[j];
        si += v * Wi[j];
        sf += v * Wf[j];
    }
#pragma unroll
    for (int o = 16; o; o >>= 1) {
        si += __shfl_xor_sync(0xffffffffu, si, o);
        sf += __shfl_xor_sync(0xffffffffu, sf, o);
    }
    if (l == 0) {
        g_ib[row] = si + bi[0];
        g_fb[row] = sf + bf[0];
        g_rowsum[row] = 0.f;
    }
}

__global__ void k_scan() {
    int b = threadIdx.x;
    if (b < Bq) {
        float m = 0.f, F = 0.f;
        for (int t = 0; t < Tt; t++) {
            float ib = g_ib[b * Tt + t], fb = g_fb[b * Tt + t];
            float mn = fmaxf(fb + m, ib);
            F += fb;
            g_alpha[b * Tt + t] = ib - F;
            g_beta[b * Tt + t] = F - mn;
            m = mn;
        }
    }
}

// =============  attention kernels  =================
template <int BMt, int BNt>
__device__ __forceinline__ void mma_t(const float (*As)[BMt + 4], const float (*Bs)[BNt + 4],
                                      int ty, int tx, ull acc[BMt / 32][BNt / 16]) {
    constexpr int PAIRS = BMt / 32, CN = BNt / 16;
#pragma unroll
    for (int kk = 0; kk < BK; kk++) {
        ull ap[PAIRS];
        if constexpr (PAIRS == 2) {
            ulonglong2 av = *(const ulonglong2*)&As[kk][ty * 4];
            ap[0] = av.x; ap[1] = av.y;
        } else {
            ap[0] = *(const ull*)&As[kk][ty * 2];
        }
        float bv[CN];
        if constexpr (CN == 4) {
            float4 b4 = *(const float4*)&Bs[kk][tx * 4];
            bv[0] = b4.x; bv[1] = b4.y; bv[2] = b4.z; bv[3] = b4.w;
        } else {
            float2 b2 = *(const float2*)&Bs[kk][tx * 2];
            bv[0] = b2.x; bv[1] = b2.y;
        }
#pragma unroll
        for (int j = 0; j < CN; j++) {
            ull bp = packf2(bv[j], bv[j]);
#pragma unroll
            for (int p = 0; p < PAIRS; p++) fma2(acc[p][j], ap[p], bp);
        }
    }
}

#define STS_A(BUF, AV) \
    do { As[BUF][lk + 0][lrA] = (AV).x; As[BUF][lk + 1][lrA] = (AV).y; \
         As[BUF][lk + 2][lrA] = (AV).z; As[BUF][lk + 3][lrA] = (AV).w; } while (0)
#define STS_B(BUF, WV) \
    do { Bs[BUF][lk + 0][lrB] = (WV).x; Bs[BUF][lk + 1][lrB] = (WV).y; \
         Bs[BUF][lk + 2][lrB] = (WV).z; Bs[BUF][lk + 3][lrB] = (WV).w; } while (0)

__global__ __launch_bounds__(256) void k_attn1() {
    constexpr int BMt = 32, BNt = 32;
    int m0 = blockIdx.y * BMt, n0 = blockIdx.x * BNt;
    if (n0 > m0) return;
    __shared__ __align__(16) float As[2][BK][BMt + 4];
    __shared__ __align__(16) float Bs[2][BK][BNt + 4];
    int tid = threadIdx.x;
    int z = blockIdx.z;
    int ty = tid >> 4, tx = tid & 15;
    bool doA = (tid < 128), doB = (tid >= 128);
    int lrA = tid >> 2, lrB = (tid & 127) >> 2, lk = (tid & 3) * 4;
    const float* Ap = g_q + (size_t)(z * Tt + m0 + lrA) * D2 + lk;
    const float* Wp = g_k + (size_t)(z * Tt + n0 + lrB) * D2 + lk;
    ull acc[1][2] = {};
    float4 a, w;
    if (doA) a = *(const float4*)Ap;
    if (doB) w = *(const float4*)Wp;
    if (doA) STS_A(0, a);
    if (doB) STS_B(0, w);
    __syncthreads();
    int buf = 0;
    for (int k0 = BK; k0 < D2; k0 += BK) {
        if (doA) a = *(const float4*)(Ap + k0);
        if (doB) w = *(const float4*)(Wp + k0);
        mma_t<32, 32>(As[buf], Bs[buf], ty, tx, acc);
        if (doA) STS_A(buf ^ 1, a);
        if (doB) STS_B(buf ^ 1, w);
        __syncthreads();
        buf ^= 1;
    }
    mma_t<32, 32>(As[buf], Bs[buf], ty, tx, acc);

    float2 lohi0 = unpackf2(acc[0][0]), lohi1 = unpackf2(acc[0][1]);
    float al0 = g_alpha[z * Tt + n0 + tx * 2];
    float al1 = g_alpha[z * Tt + n0 + tx * 2 + 1];
#pragma unroll
    for (int half = 0; half < 2; half++) {
        int t = m0 + ty * 2 + half;
        float be = g_beta[z * Tt + t];
        int s0 = n0 + tx * 2, s1 = s0 + 1;
        float v0 = (s0 <= t) ? __expf(al0 + be) * (half ? lohi0.y : lohi0.x) : 0.f;
        float v1 = (s1 <= t) ? __expf(al1 + be) * (half ? lohi1.y : lohi1.x) : 0.f;
        *(float2*)&g_A[(size_t)z * Tt * Tt + (size_t)t * Tt + s0] = make_float2(v0, v1);
        float p = v0 + v1;
#pragma unroll
        for (int off = 1; off < 16; off <<= 1) p += __shfl_xor_sync(0xffffffffu, p, off);
        if (tx == 0) atomicAdd(&g_rowsum[z * Tt + t], p);
    }
}

__global__ __launch_bounds__(256) void k_attn2() {
    constexpr int BMt = 32, BNt = 64;
    __shared__ __align__(16) float As[2][BK][BMt + 4];
    __shared__ __align__(16) float Bs[2][BK][BNt + 4];
    int tid = threadIdx.x;
    int z = blockIdx.z;
    int m0 = blockIdx.y * BMt, n0 = blockIdx.x * BNt;
    int ty = tid >> 4, tx = tid & 15;
    bool doA = (tid < 128);
    int lrA = tid >> 2, lk = (tid & 3) * 4;
    int brow = tid >> 4, bcol = (tid & 15) * 4;
    int Kend = m0 + BMt;
    const float* Ap = g_A + (size_t)z * Tt * Tt + (size_t)(m0 + lrA) * Tt + lk;
    const float* Vb = g_v + (size_t)z * Tt * D2;
    ull acc[1][4] = {};
    float4 a, w;
    if (doA) a = *(const float4*)Ap;
    w = *(const float4*)(Vb + (size_t)brow * D2 + n0 + bcol);
    if (doA) STS_A(0, a);
    *(float4*)&Bs[0][brow][bcol] = w;
    __syncthreads();
    int buf = 0;
    for (int k0 = BK; k0 < Kend; k0 += BK) {
        if (doA) a = *(const float4*)(Ap + k0);
        w = *(const float4*)(Vb + (size_t)(k0 + brow) * D2 + n0 + bcol);
        mma_t<32, 64>(As[buf], Bs[buf], ty, tx, acc);
        if (doA) STS_A(buf ^ 1, a);
        *(float4*)&Bs[buf ^ 1][brow][bcol] = w;
        __syncthreads();
        buf ^= 1;
    }
    mma_t<32, 64>(As[buf], Bs[buf], ty, tx, acc);

    float2 lohi[4];
#pragma unroll
    for (int j = 0; j < 4; j++) lohi[j] = unpackf2(acc[0][j]);
#pragma unroll
    for (int half = 0; half < 2; half++) {
        int m = m0 + ty * 2 + half;
        int r = z * Tt + m;
        float rs = g_rowsum[r];
        float inv = 1.f / (fmaxf(fabsf(rs), 1.f) + 1e-8f);
        float4 og = *(const float4*)&g_o[(size_t)r * D2 + n0 + tx * 4];
        float4 ov = make_float4((half ? lohi[0].y : lohi[0].x) * inv * og.x,
                                (half ? lohi[1].y : lohi[1].x) * inv * og.y,
                                (half ? lohi[2].y : lohi[2].x) * inv * og.z,
                                (half ? lohi[3].y : lohi[3].x) * inv * og.w);
        *(float4*)&g_hseq[(size_t)r * D2 + n0 + tx * 4] = ov;
    }
}

__global__ void k_gnstats() {
    int bh = blockIdx.x;
    int b = bh >> 2, h = bh & 3;
    int tid = threadIdx.x;
    float s = 0, s2 = 0;
    const float* base = g_hseq + (size_t)(b * Tt) * D2 + h * 128;
    for (int i = tid; i < Tt * 128; i += 256) {
        int t = i >> 7, d = i & 127;
        float v = base[(size_t)t * D2 + d];
        s += v; s2 += v * v;
    }
#pragma unroll
    for (int o = 16; o; o >>= 1) {
        s += __shfl_xor_sync(0xffffffffu, s, o);
        s2 += __shfl_xor_sync(0xffffffffu, s2, o);
    }
    __shared__ float sh[8], sh2[8];
    int w = tid >> 5, l = tid & 31;
    if (l == 0) { sh[w] = s; sh2[w] = s2; }
    __syncthreads();
    if (tid == 0) {
        float a = 0, a2 = 0;
#pragma unroll
        for (int i = 0; i < 8; i++) { a += sh[i]; a2 += sh2[i]; }
        float mu = a * (1.f / (Tt * 128));
        float var = a2 * (1.f / (Tt * 128)) - mu * mu;
        g_gnmu[bh] = mu;
        g_gnrs[bh] = rsqrtf(var + 1e-5f);
    }
}

// ---------------- launch ----------------
extern "C" void kernel_launch(void* const* d_in, const int* in_sizes, int n_in,
                              void* d_out, int out_size) {
    const float* x       = (const float*)d_in[0];
    const float* ln_g    = (const float*)d_in[1];
    const float* ln_b    = (const float*)d_in[2];
    const float* W_left  = (const float*)d_in[3];
    const float* b_left  = (const float*)d_in[4];
    const float* W_right = (const float*)d_in[5];
    const float* b_right = (const float*)d_in[6];
    const float* Wi      = (const float*)d_in[7];
    const float* bi      = (const float*)d_in[8];
    const float* Wf      = (const float*)d_in[9];
    const float* bf      = (const float*)d_in[10];
    const float* Wo      = (const float*)d_in[11];
    const float* bo      = (const float*)d_in[12];
    const float* Wq      = (const float*)d_in[13];
    const float* Wk      = (const float*)d_in[14];
    const float* Wv      = (const float*)d_in[15];
    const float* conv_w  = (const float*)d_in[16];
    const float* conv_b  = (const float*)d_in[17];
    const float* skip_W  = (const float*)d_in[18];
    const float* gn_g    = (const float*)d_in[19];
    const float* gn_b    = (const float*)d_in[20];
    const float* W_last  = (const float*)d_in[21];
    const float* b_last  = (const float*)d_in[22];
    float* out = (float*)d_out;

    float *p_xnorm, *p_xleft, *p_xright, *p_xtrans, *p_h;
    cudaGetSymbolAddress((void**)&p_xnorm, g_xnorm);
    cudaGetSymbolAddress((void**)&p_xleft, g_xleft);
    cudaGetSymbolAddress((void**)&p_xright, g_xright);
    cudaGetSymbolAddress((void**)&p_xtrans, g_xtrans);
    cudaGetSymbolAddress((void**)&p_h, g_h);

    k_layernorm<<<BT, 256>>>(x, ln_g, ln_b);
    k_convwt<<<1024, 256>>>(conv_w);
    k_projdual<<<dim3(4, 16, 2), 256>>>(p_xnorm, W_left, b_left, p_xleft,
                                        W_right, b_right, p_xright, 256);
    k_convp<<<dim3(4, 16, 8), 256>>>();
    k_cepi<<<512, 256>>>(conv_b);
    k_partial<<<dim3(4, 16, 2), 256>>>(p_xleft, Wo, 512, 256, 512);
    k_wepi<<<512, 256>>>(bo);
    k_ibfb<<<128, 256>>>(Wi, Wf, bi, bf);
    k_scan<<<1, 32>>>();
    k_qkv<<<dim3(1, 16, 12), 256>>>(Wq, Wk, Wv);
    k_attn1<<<dim3(8, 8, 4), 256>>>();
    k_attn2<<<dim3(8, 8, 4), 256>>>();
    k_gnstats<<<16, 256>>>();
    k_partial<<<dim3(4, 16, 2), 256>>>(p_xtrans, skip_W, 512, 256, 512);
    k_sepi<<<512, 256>>>(gn_g, gn_b);
    k_partial<<<dim3(2, 16, 4), 256>>>(p_h, W_last, 512, 128, 256);
    k_lepi<<<256, 256>>>(b_last, x, out);
}

// round 8
// speedup vs baseline: 1.3722x; 1.3722x over previous
#include <cuda_runtime.h>
#include <math.h>

typedef unsigned long long ull;

// Problem constants
#define Bq 4
#define Tt 256
#define Dd 256
#define D2 512
#define BT 1024
#define SCALEF 0.0625f
#define BK 16

// ---------------- scratch (static device globals; no allocation) -------------
__device__ float g_xnorm[BT * Dd];
__device__ float g_xleft[BT * D2];
__device__ float g_xright[BT * D2];
__device__ float g_xtrans[BT * D2];
__device__ float g_o[BT * D2];
__device__ float g_q[BT * D2];
__device__ float g_k[BT * D2];
__device__ float g_v[BT * D2];
__device__ float g_hseq[BT * D2];
__device__ float g_h[BT * D2];
__device__ float g_convwt[4 * D2 * D2];
__device__ float g_cp[4 * BT * D2];     // split-K partials (4 x 2MB)
__device__ float g_A[Bq * Tt * Tt];
__device__ float g_ib[BT];
__device__ float g_fb[BT];
__device__ float g_alpha[BT];
__device__ float g_beta[BT];
__device__ float g_rowsum[BT];
__device__ float g_gnmu[16];
__device__ float g_gnrs[16];

#define PSLICE (BT * D2)   // 524288 floats per partial slice

__device__ __forceinline__ float sigm(float x) { return 1.f / (1.f + __expf(-x)); }

// ---------------- packed f32x2 helpers ----------------
__device__ __forceinline__ ull packf2(float lo, float hi) {
    ull r; asm("mov.b64 %0, {%1, %2};" : "=l"(r) : "f"(lo), "f"(hi)); return r;
}
__device__ __forceinline__ void fma2(ull& d, ull a, ull b) {
    asm("fma.rn.f32x2 %0, %1, %2, %0;" : "+l"(d) : "l"(a), "l"(b));
}
__device__ __forceinline__ float2 unpackf2(ull v) {
    float2 f; asm("mov.b64 {%0, %1}, %2;" : "=f"(f.x), "=f"(f.y) : "l"(v)); return f;
}

// ================  128x64 low-wavefront core (8 rows x 4 cols/thr) ==========
struct Sm2 {
    __align__(16) float As[2][BK][132];   // 128 rows + pad
    __align__(16) float Bs[2][BK][68];    // 64 rows + pad
};

// acc[p][c]: rows (ty*8+2p, +1), col (tx*4+c)
__device__ __forceinline__ void mma2(const Sm2* s, int buf, int ty, int tx,
                                     ull (&acc)[4][4]) {
#pragma unroll
    for (int kk = 0; kk < BK; kk++) {
        ulonglong2 a01 = *(const ulonglong2*)&s->As[buf][kk][ty * 8];
        ulonglong2 a23 = *(const ulonglong2*)&s->As[buf][kk][ty * 8 + 4];
        float4 b = *(const float4*)&s->Bs[buf][kk][tx * 4];
        ull ap[4] = {a01.x, a01.y, a23.x, a23.y};
        ull bp[4] = {packf2(b.x, b.x), packf2(b.y, b.y),
                     packf2(b.z, b.z), packf2(b.w, b.w)};
#pragma unroll
        for (int p = 0; p < 4; p++)
#pragma unroll
            for (int c = 0; c < 4; c++) fma2(acc[p][c], ap[p], bp[c]);
    }
}

// Double-buffered K loop. ApA: thread A ptr (row m0+(tid>>1), col (tid&1)*8).
// ApB: thread W ptr (row n0+(tid>>2), col (tid&3)*4). Both advance BK/iter.
__device__ __forceinline__ void gloop2(Sm2* s, const float* ApA, const float* ApB,
                                       int iters, bool avalid, ull (&acc)[4][4],
                                       int tid) {
    int rA = tid >> 1, kA = (tid & 1) * 8;
    int rB = tid >> 2, kB = (tid & 3) * 4;
    int ty = tid >> 4, tx = tid & 15;
    float4 z4 = make_float4(0.f, 0.f, 0.f, 0.f);
    float4 a0 = avalid ? *(const float4*)ApA : z4;
    float4 a1 = avalid ? *(const float4*)(ApA + 4) : z4;
    float4 b = *(const float4*)ApB;
#pragma unroll
    for (int i = 0; i < 4; i++) {
        s->As[0][kA + i][rA] = (&a0.x)[i];
        s->As[0][kA + 4 + i][rA] = (&a1.x)[i];
        s->Bs[0][kB + i][rB] = (&b.x)[i];
    }
    __syncthreads();
    int buf = 0;
    for (int it = 1; it < iters; it++) {
        a0 = avalid ? *(const float4*)(ApA + it * BK) : z4;
        a1 = avalid ? *(const float4*)(ApA + it * BK + 4) : z4;
        b = *(const float4*)(ApB + it * BK);
        mma2(s, buf, ty, tx, acc);
        int nb = buf ^ 1;
#pragma unroll
        for (int i = 0; i < 4; i++) {
            s->As[nb][kA + i][rA] = (&a0.x)[i];
            s->As[nb][kA + 4 + i][rA] = (&a1.x)[i];
            s->Bs[nb][kB + i][rB] = (&b.x)[i];
        }
        __syncthreads();
        buf = nb;
    }
    mma2(s, buf, ty, tx, acc);
}

// ---------------- fused dual projection (z picks weight set) -----------------
__global__ __launch_bounds__(256) void k_projdual(const float* __restrict__ A,
                                                  const float* __restrict__ W1,
                                                  const float* __restrict__ b1,
                                                  float* __restrict__ C1,
                                                  const float* __restrict__ W2,
                                                  const float* __restrict__ b2,
                                                  float* __restrict__ C2, int K) {
    __shared__ Sm2 s;
    int tid = threadIdx.x;
    const float* W = blockIdx.z ? W2 : W1;
    const float* bias = blockIdx.z ? b2 : b1;
    float* C = blockIdx.z ? C2 : C1;
    int m0 = blockIdx.y * 128, n0 = blockIdx.x * 64;
    const float* ApA = A + (size_t)(m0 + (tid >> 1)) * K + (tid & 1) * 8;
    const float* ApB = W + (size_t)(n0 + (tid >> 2)) * K + (tid & 3) * 4;
    ull acc[4][4] = {};
    gloop2(&s, ApA, ApB, K / BK, true, acc, tid);
    int ty = tid >> 4, tx = tid & 15;
    int n = n0 + tx * 4;
    float4 b4 = *(const float4*)&bias[n];
#pragma unroll
    for (int p = 0; p < 4; p++) {
        float2 u[4];
#pragma unroll
        for (int c = 0; c < 4; c++) u[c] = unpackf2(acc[p][c]);
#pragma unroll
        for (int half = 0; half < 2; half++) {
            int m = m0 + ty * 8 + 2 * p + half;
            *(float4*)&C[(size_t)m * D2 + n] = make_float4(
                (half ? u[0].y : u[0].x) + b4.x, (half ? u[1].y : u[1].x) + b4.y,
                (half ? u[2].y : u[2].x) + b4.z, (half ? u[3].y : u[3].x) + b4.w);
        }
    }
}

// ---------------- generic split-K partial GEMM -> g_cp slice -----------------
__global__ __launch_bounds__(256) void k_partial(const float* __restrict__ A,
                                                 const float* __restrict__ W,
                                                 int Ktot, int Ksub, int N) {
    __shared__ Sm2 s;
    int tid = threadIdx.x;
    int m0 = blockIdx.y * 128, n0 = blockIdx.x * 64, sp = blockIdx.z;
    const float* ApA = A + (size_t)(m0 + (tid >> 1)) * Ktot + sp * Ksub + (tid & 1) * 8;
    const float* ApB = W + (size_t)(n0 + (tid >> 2)) * Ktot + sp * Ksub + (tid & 3) * 4;
    ull acc[4][4] = {};
    gloop2(&s, ApA, ApB, Ksub / BK, true, acc, tid);
    int ty = tid >> 4, tx = tid & 15;
    int n = n0 + tx * 4;
    float* out = g_cp + (size_t)sp * PSLICE;
#pragma unroll
    for (int p = 0; p < 4; p++) {
        float2 u[4];
#pragma unroll
        for (int c = 0; c < 4; c++) u[c] = unpackf2(acc[p][c]);
#pragma unroll
        for (int half = 0; half < 2; half++) {
            int m = m0 + ty * 8 + 2 * p + half;
            *(float4*)&out[(size_t)m * N + n] = make_float4(
                half ? u[0].y : u[0].x, half ? u[1].y : u[1].x,
                half ? u[2].y : u[2].x, half ? u[3].y : u[3].x);
        }
    }
}

// ---------------- conv partial: z = tau, K=512 -----------------
__global__ __launch_bounds__(256) void k_convp() {
    __shared__ Sm2 s;
    int tid = threadIdx.x;
    int tau = blockIdx.z;
    int m0 = blockIdx.y * 128, n0 = blockIdx.x * 64;
    int row = m0 + (tid >> 1), b = row >> 8, t = row & 255;
    int tp = t - 3 + tau;
    bool avalid = (tp >= 0);
    int tpc = avalid ? tp : 0;
    const float* ApA = g_xleft + (size_t)(b * Tt + tpc) * D2 + (tid & 1) * 8;
    const float* ApB = g_convwt + (size_t)tau * 262144 +
                       (size_t)(n0 + (tid >> 2)) * D2 + (tid & 3) * 4;
    ull acc[4][4] = {};
    gloop2(&s, ApA, ApB, D2 / BK, avalid, acc, tid);
    int ty = tid >> 4, tx = tid & 15;
    int n = n0 + tx * 4;
    float* out = g_cp + (size_t)tau * PSLICE;
#pragma unroll
    for (int p = 0; p < 4; p++) {
        float2 u[4];
#pragma unroll
        for (int c = 0; c < 4; c++) u[c] = unpackf2(acc[p][c]);
#pragma unroll
        for (int half = 0; half < 2; half++) {
            int m = m0 + ty * 8 + 2 * p + half;
            *(float4*)&out[(size_t)m * D2 + n] = make_float4(
                half ? u[0].y : u[0].x, half ? u[1].y : u[1].x,
                half ? u[2].y : u[2].x, half ? u[3].y : u[3].x);
        }
    }
}

// ---------------- qkv on 128x64 core -----------------
__global__ __launch_bounds__(256) void k_qkv(const float* __restrict__ Wq,
                                             const float* __restrict__ Wk,
                                             const float* __restrict__ Wv) {
    __shared__ Sm2 s;
    int tid = threadIdx.x;
    int z = blockIdx.z, which = z >> 2, h = z & 3;
    const float* src = (which == 2) ? g_xleft : g_xtrans;
    const float* W = (which == 0) ? Wq : ((which == 1) ? Wk : Wv);
    float* dst = (which == 0) ? g_q : ((which == 1) ? g_k : g_v);
    float sc = (which == 1) ? SCALEF : 1.f;
    int m0 = blockIdx.y * 128, n0 = blockIdx.x * 64;
    const float* ApA = src + (size_t)(m0 + (tid >> 1)) * D2 + h * 128 + (tid & 1) * 8;
    const float* ApB = W + (size_t)h * 16384 + (size_t)(n0 + (tid >> 2)) * 128 + (tid & 3) * 4;
    ull acc[4][4] = {};
    gloop2(&s, ApA, ApB, 128 / BK, true, acc, tid);
    int ty = tid >> 4, tx = tid & 15;
    int n = h * 128 + n0 + tx * 4;
#pragma unroll
    for (int p = 0; p < 4; p++) {
        float2 u[4];
#pragma unroll
        for (int c = 0; c < 4; c++) u[c] = unpackf2(acc[p][c]);
#pragma unroll
        for (int half = 0; half < 2; half++) {
            int m = m0 + ty * 8 + 2 * p + half;
            *(float4*)&dst[(size_t)m * D2 + n] = make_float4(
                sc * (half ? u[0].y : u[0].x), sc * (half ? u[1].y : u[1].x),
                sc * (half ? u[2].y : u[2].x), sc * (half ? u[3].y : u[3].x));
        }
    }
}

// ====================  reduce / epilogue kernels  ============================
__global__ void k_cepi(const float* __restrict__ cb) {   // 4 parts + bias + swish
    int idx = blockIdx.x * 256 + threadIdx.x;            // float4 idx, 131072
    size_t off = (size_t)idx * 4;
    float4 sm = *(const float4*)(g_cp + off);
#pragma unroll
    for (int p = 1; p < 4; p++) {
        float4 q = *(const float4*)(g_cp + (size_t)p * PSLICE + off);
        sm.x += q.x; sm.y += q.y; sm.z += q.z; sm.w += q.w;
    }
    int n = (idx & 127) * 4;
    float4 b4 = *(const float4*)&cb[n];
    float z0 = sm.x + b4.x, z1 = sm.y + b4.y, z2 = sm.z + b4.z, z3 = sm.w + b4.w;
    *(float4*)(g_xtrans + off) = make_float4(z0 * sigm(z0), z1 * sigm(z1),
                                             z2 * sigm(z2), z3 * sigm(z3));
}

__global__ void k_wepi(const float* __restrict__ bo) {   // 2 parts + bias, sigmoid
    int idx = blockIdx.x * 256 + threadIdx.x;
    size_t off = (size_t)idx * 4;
    float4 s0 = *(const float4*)(g_cp + off);
    float4 s1 = *(const float4*)(g_cp + PSLICE + off);
    int n = (idx & 127) * 4;
    float4 b4 = *(const float4*)&bo[n];
    *(float4*)(g_o + off) = make_float4(sigm(s0.x + s1.x + b4.x), sigm(s0.y + s1.y + b4.y),
                                        sigm(s0.z + s1.z + b4.z), sigm(s0.w + s1.w + b4.w));
}

__global__ void k_sepi(const float* __restrict__ gn_g, const float* __restrict__ gn_b) {
    int idx = blockIdx.x * 256 + threadIdx.x;            // float4 idx over g_h
    size_t off = (size_t)idx * 4;
    float4 s0 = *(const float4*)(g_cp + off);
    float4 s1 = *(const float4*)(g_cp + PSLICE + off);
    int n = (idx & 127) * 4;
    int m = idx >> 7;
    int b = m >> 8, hh = n >> 7;
    float mu = g_gnmu[b * 4 + hh], rs = g_gnrs[b * 4 + hh];
    float4 hs = *(const float4*)(g_hseq + off);
    float4 xr = *(const float4*)(g_xright + off);
    float4 gg = *(const float4*)&gn_g[n];
    float4 gb = *(const float4*)&gn_b[n];
    float sv[4] = {s0.x + s1.x, s0.y + s1.y, s0.z + s1.z, s0.w + s1.w};
    float hv[4] = {hs.x, hs.y, hs.z, hs.w};
    float xv[4] = {xr.x, xr.y, xr.z, xr.w};
    float ggv[4] = {gg.x, gg.y, gg.z, gg.w};
    float gbv[4] = {gb.x, gb.y, gb.z, gb.w};
    float ov[4];
#pragma unroll
    for (int j = 0; j < 4; j++) {
        float zn = (hv[j] - mu) * rs;
        float hg = zn * ggv[j] + gbv[j] + sv[j];
        ov[j] = hg * xv[j] * sigm(xv[j]);
    }
    *(float4*)(g_h + off) = make_float4(ov[0], ov[1], ov[2], ov[3]);
}

__global__ void k_lepi(const float* __restrict__ bl, const float* __restrict__ x,
                       float* __restrict__ out) {        // 4 parts + bias + residual
    int idx = blockIdx.x * 256 + threadIdx.x;            // float4 idx, 65536
    size_t off = (size_t)idx * 4;
    float4 sm = *(const float4*)(g_cp + off);
#pragma unroll
    for (int p = 1; p < 4; p++) {
        float4 q = *(const float4*)(g_cp + (size_t)p * PSLICE + off);
        sm.x += q.x; sm.y += q.y; sm.z += q.z; sm.w += q.w;
    }
    int n = (idx & 63) * 4;
    float4 b4 = *(const float4*)&bl[n];
    float4 xv = *(const float4*)(x + off);
    *(float4*)(out + off) = make_float4(sm.x + b4.x + xv.x, sm.y + b4.y + xv.y,
                                        sm.z + b4.z + xv.z, sm.w + b4.w + xv.w);
}

// ====================  small kernels  ============================
__global__ void k_layernorm(const float* __restrict__ x, const float* __restrict__ g,
                            const float* __restrict__ b) {
    int row = blockIdx.x, tid = threadIdx.x;
    float v = x[row * Dd + tid];
    float s = v, s2 = v * v;
#pragma unroll
    for (int o = 16; o; o >>= 1) {
        s += __shfl_xor_sync(0xffffffffu, s, o);
        s2 += __shfl_xor_sync(0xffffffffu, s2, o);
    }
    __shared__ float sh[8], sh2[8];
    int w = tid >> 5, l = tid & 31;
    if (l == 0) { sh[w] = s; sh2[w] = s2; }
    __syncthreads();
    if (tid == 0) {
        float a = 0, a2 = 0;
#pragma unroll
        for (int i = 0; i < 8; i++) { a += sh[i]; a2 += sh2[i]; }
        sh[0] = a; sh2[0] = a2;
    }
    __syncthreads();
    float mu = sh[0] * (1.f / Dd);
    float var = sh2[0] * (1.f / Dd) - mu * mu;
    float r = rsqrtf(var + 1e-5f);
    g_xnorm[row * Dd + tid] = (v - mu) * r * g[tid] + b[tid];
}

__global__ void k_convwt(const float* __restrict__ cw) {
    int idx = blockIdx.x * 256 + threadIdx.x;
    float4 w = *(const float4*)(cw + (size_t)idx * 4);
    g_convwt[0 * 262144 + idx] = w.x;
    g_convwt[1 * 262144 + idx] = w.y;
    g_convwt[2 * 262144 + idx] = w.z;
    g_convwt[3 * 262144 + idx] = w.w;
}

__global__ void k_ibfb(const float* __restrict__ Wi, const float* __restrict__ Wf,
                       const float* __restrict__ bi, const float* __restrict__ bf) {
    int row = blockIdx.x * 8 + (threadIdx.x >> 5);
    int l = threadIdx.x & 31;
    const float* xr = g_xleft + (size_t)row * D2;
    float si = 0, sf = 0;
#pragma unroll 4
    for (int j = l; j < D2; j += 32) {
        float v = xr[j];
        si += v * Wi[j];
        sf += v * Wf[j];
    }
#pragma unroll
    for (int o = 16; o; o >>= 1) {
        si += __shfl_xor_sync(0xffffffffu, si, o);
        sf += __shfl_xor_sync(0xffffffffu, sf, o);
    }
    if (l == 0) {
        g_ib[row] = si + bi[0];
        g_fb[row] = sf + bf[0];
        g_rowsum[row] = 0.f;
    }
}

__global__ void k_scan() {
    int b = threadIdx.x;
    if (b < Bq) {
        float m = 0.f, F = 0.f;
        for (int t = 0; t < Tt; t++) {
            float ib = g_ib[b * Tt + t], fb = g_fb[b * Tt + t];
            float mn = fmaxf(fb + m, ib);
            F += fb;
            g_alpha[b * Tt + t] = ib - F;
            g_beta[b * Tt + t] = F - mn;
            m = mn;
        }
    }
}

// =============  attention kernels (R4 proven versions)  =================
template <int BMt, int BNt>
__device__ __forceinline__ void mma_t(const float (*As)[BMt + 4], const float (*Bs)[BNt + 4],
                                      int ty, int tx, ull acc[BMt / 32][BNt / 16]) {
    constexpr int PAIRS = BMt / 32, CN = BNt / 16;
#pragma unroll
    for (int kk = 0; kk < BK; kk++) {
        ull ap[PAIRS];
        if constexpr (PAIRS == 2) {
            ulonglong2 av = *(const ulonglong2*)&As[kk][ty * 4];
            ap[0] = av.x; ap[1] = av.y;
        } else {
            ap[0] = *(const ull*)&As[kk][ty * 2];
        }
        float bv[CN];
        if constexpr (CN == 4) {
            float4 b4 = *(const float4*)&Bs[kk][tx * 4];
            bv[0] = b4.x; bv[1] = b4.y; bv[2] = b4.z; bv[3] = b4.w;
        } else {
            float2 b2 = *(const float2*)&Bs[kk][tx * 2];
            bv[0] = b2.x; bv[1] = b2.y;
        }
#pragma unroll
        for (int j = 0; j < CN; j++) {
            ull bp = packf2(bv[j], bv[j]);
#pragma unroll
            for (int p = 0; p < PAIRS; p++) fma2(acc[p][j], ap[p], bp);
        }
    }
}

#define STS_A(BUF, AV) \
    do { As[BUF][lk + 0][lrA] = (AV).x; As[BUF][lk + 1][lrA] = (AV).y; \
         As[BUF][lk + 2][lrA] = (AV).z; As[BUF][lk + 3][lrA] = (AV).w; } while (0)
#define STS_B(BUF, WV) \
    do { Bs[BUF][lk + 0][lrB] = (WV).x; Bs[BUF][lk + 1][lrB] = (WV).y; \
         Bs[BUF][lk + 2][lrB] = (WV).z; Bs[BUF][lk + 3][lrB] = (WV).w; } while (0)

__global__ __launch_bounds__(256) void k_attn1() {
    constexpr int BMt = 32, BNt = 32;
    int m0 = blockIdx.y * BMt, n0 = blockIdx.x * BNt;
    if (n0 > m0) return;
    __shared__ __align__(16) float As[2][BK][BMt + 4];
    __shared__ __align__(16) float Bs[2][BK][BNt + 4];
    int tid = threadIdx.x;
    int z = blockIdx.z;
    int ty = tid >> 4, tx = tid & 15;
    bool doA = (tid < 128), doB = (tid >= 128);
    int lrA = tid >> 2, lrB = (tid & 127) >> 2, lk = (tid & 3) * 4;
    const float* Ap = g_q + (size_t)(z * Tt + m0 + lrA) * D2 + lk;
    const float* Wp = g_k + (size_t)(z * Tt + n0 + lrB) * D2 + lk;
    ull acc[1][2] = {};
    float4 a, w;
    if (doA) a = *(const float4*)Ap;
    if (doB) w = *(const float4*)Wp;
    if (doA) STS_A(0, a);
    if (doB) STS_B(0, w);
    __syncthreads();
    int buf = 0;
    for (int k0 = BK; k0 < D2; k0 += BK) {
        if (doA) a = *(const float4*)(Ap + k0);
        if (doB) w = *(const float4*)(Wp + k0);
        mma_t<32, 32>(As[buf], Bs[buf], ty, tx, acc);
        if (doA) STS_A(buf ^ 1, a);
        if (doB) STS_B(buf ^ 1, w);
        __syncthreads();
        buf ^= 1;
    }
    mma_t<32, 32>(As[buf], Bs[buf], ty, tx, acc);

    float2 lohi0 = unpackf2(acc[0][0]), lohi1 = unpackf2(acc[0][1]);
    float al0 = g_alpha[z * Tt + n0 + tx * 2];
    float al1 = g_alpha[z * Tt + n0 + tx * 2 + 1];
#pragma unroll
    for (int half = 0; half < 2; half++) {
        int t = m0 + ty * 2 + half;
        float be = g_beta[z * Tt + t];
        int s0 = n0 + tx * 2, s1 = s0 + 1;
        float v0 = (s0 <= t) ? __expf(al0 + be) * (half ? lohi0.y : lohi0.x) : 0.f;
        float v1 = (s1 <= t) ? __expf(al1 + be) * (half ? lohi1.y : lohi1.x) : 0.f;
        *(float2*)&g_A[(size_t)z * Tt * Tt + (size_t)t * Tt + s0] = make_float2(v0, v1);
        float p = v0 + v1;
#pragma unroll
        for (int off = 1; off < 16; off <<= 1) p += __shfl_xor_sync(0xffffffffu, p, off);
        if (tx == 0) atomicAdd(&g_rowsum[z * Tt + t], p);
    }
}

__global__ __launch_bounds__(256) void k_attn2() {
    constexpr int BMt = 32, BNt = 64;
    __shared__ __align__(16) float As[2][BK][BMt + 4];
    __shared__ __align__(16) float Bs[2][BK][BNt + 4];
    int tid = threadIdx.x;
    int z = blockIdx.z;
    int m0 = blockIdx.y * BMt, n0 = blockIdx.x * BNt;
    int ty = tid >> 4, tx = tid & 15;
    bool doA = (tid < 128);
    int lrA = tid >> 2, lk = (tid & 3) * 4;
    int brow = tid >> 4, bcol = (tid & 15) * 4;
    int Kend = m0 + BMt;
    const float* Ap = g_A + (size_t)z * Tt * Tt + (size_t)(m0 + lrA) * Tt + lk;
    const float* Vb = g_v + (size_t)z * Tt * D2;
    ull acc[1][4] = {};
    float4 a, w;
    if (doA) a = *(const float4*)Ap;
    w = *(const float4*)(Vb + (size_t)brow * D2 + n0 + bcol);
    if (doA) STS_A(0, a);
    *(float4*)&Bs[0][brow][bcol] = w;
    __syncthreads();
    int buf = 0;
    for (int k0 = BK; k0 < Kend; k0 += BK) {
        if (doA) a = *(const float4*)(Ap + k0);
        w = *(const float4*)(Vb + (size_t)(k0 + brow) * D2 + n0 + bcol);
        mma_t<32, 64>(As[buf], Bs[buf], ty, tx, acc);
        if (doA) STS_A(buf ^ 1, a);
        *(float4*)&Bs[buf ^ 1][brow][bcol] = w;
        __syncthreads();
        buf ^= 1;
    }
    mma_t<32, 64>(As[buf], Bs[buf], ty, tx, acc);

    float2 lohi[4];
#pragma unroll
    for (int j = 0; j < 4; j++) lohi[j] = unpackf2(acc[0][j]);
#pragma unroll
    for (int half = 0; half < 2; half++) {
        int m = m0 + ty * 2 + half;
        int r = z * Tt + m;
        float rs = g_rowsum[r];
        float inv = 1.f / (fmaxf(fabsf(rs), 1.f) + 1e-8f);
        float4 og = *(const float4*)&g_o[(size_t)r * D2 + n0 + tx * 4];
        float4 ov = make_float4((half ? lohi[0].y : lohi[0].x) * inv * og.x,
                                (half ? lohi[1].y : lohi[1].x) * inv * og.y,
                                (half ? lohi[2].y : lohi[2].x) * inv * og.z,
                                (half ? lohi[3].y : lohi[3].x) * inv * og.w);
        *(float4*)&g_hseq[(size_t)r * D2 + n0 + tx * 4] = ov;
    }
}

__global__ void k_gnstats() {
    int bh = blockIdx.x;
    int b = bh >> 2, h = bh & 3;
    int tid = threadIdx.x;
    float s = 0, s2 = 0;
    const float* base = g_hseq + (size_t)(b * Tt) * D2 + h * 128;
    for (int i = tid; i < Tt * 128; i += 256) {
        int t = i >> 7, d = i & 127;
        float v = base[(size_t)t * D2 + d];
        s += v; s2 += v * v;
    }
#pragma unroll
    for (int o = 16; o; o >>= 1) {
        s += __shfl_xor_sync(0xffffffffu, s, o);
        s2 += __shfl_xor_sync(0xffffffffu, s2, o);
    }
    __shared__ float sh[8], sh2[8];
    int w = tid >> 5, l = tid & 31;
    if (l == 0) { sh[w] = s; sh2[w] = s2; }
    __syncthreads();
    if (tid == 0) {
        float a = 0, a2 = 0;
#pragma unroll
        for (int i = 0; i < 8; i++) { a += sh[i]; a2 += sh2[i]; }
        float mu = a * (1.f / (Tt * 128));
        float var = a2 * (1.f / (Tt * 128)) - mu * mu;
        g_gnmu[bh] = mu;
        g_gnrs[bh] = rsqrtf(var + 1e-5f);
    }
}

// ---------------- launch ----------------
extern "C" void kernel_launch(void* const* d_in, const int* in_sizes, int n_in,
                              void* d_out, int out_size) {
    const float* x       = (const float*)d_in[0];
    const float* ln_g    = (const float*)d_in[1];
    const float* ln_b    = (const float*)d_in[2];
    const float* W_left  = (const float*)d_in[3];
    const float* b_left  = (const float*)d_in[4];
    const float* W_right = (const float*)d_in[5];
    const float* b_right = (const float*)d_in[6];
    const float* Wi      = (const float*)d_in[7];
    const float* bi      = (const float*)d_in[8];
    const float* Wf      = (const float*)d_in[9];
    const float* bf      = (const float*)d_in[10];
    const float* Wo      = (const float*)d_in[11];
    const float* bo      = (const float*)d_in[12];
    const float* Wq      = (const float*)d_in[13];
    const float* Wk      = (const float*)d_in[14];
    const float* Wv      = (const float*)d_in[15];
    const float* conv_w  = (const float*)d_in[16];
    const float* conv_b  = (const float*)d_in[17];
    const float* skip_W  = (const float*)d_in[18];
    const float* gn_g    = (const float*)d_in[19];
    const float* gn_b    = (const float*)d_in[20];
    const float* W_last  = (const float*)d_in[21];
    const float* b_last  = (const float*)d_in[22];
    float* out = (float*)d_out;

    float *p_xnorm, *p_xleft, *p_xright, *p_xtrans, *p_h;
    cudaGetSymbolAddress((void**)&p_xnorm, g_xnorm);
    cudaGetSymbolAddress((void**)&p_xleft, g_xleft);
    cudaGetSymbolAddress((void**)&p_xright, g_xright);
    cudaGetSymbolAddress((void**)&p_xtrans, g_xtrans);
    cudaGetSymbolAddress((void**)&p_h, g_h);

    k_layernorm<<<BT, 256>>>(x, ln_g, ln_b);
    k_convwt<<<1024, 256>>>(conv_w);
    k_projdual<<<dim3(8, 8, 2), 256>>>(p_xnorm, W_left, b_left, p_xleft,
                                       W_right, b_right, p_xright, 256);
    k_convp<<<dim3(8, 8, 4), 256>>>();
    k_cepi<<<512, 256>>>(conv_b);
    k_partial<<<dim3(8, 8, 2), 256>>>(p_xleft, Wo, 512, 256, 512);
    k_wepi<<<512, 256>>>(bo);
    k_ibfb<<<128, 256>>>(Wi, Wf, bi, bf);
    k_scan<<<1, 32>>>();
    k_qkv<<<dim3(2, 8, 12), 256>>>(Wq, Wk, Wv);
    k_attn1<<<dim3(8, 8, 4), 256>>>();
    k_attn2<<<dim3(8, 8, 4), 256>>>();
    k_gnstats<<<16, 256>>>();
    k_partial<<<dim3(8, 8, 2), 256>>>(p_xtrans, skip_W, 512, 256, 512);
    k_sepi<<<512, 256>>>(gn_g, gn_b);
    k_partial<<<dim3(4, 8, 4), 256>>>(p_h, W_last, 512, 128, 256);
    k_lepi<<<256, 256>>>(b_last, x, out);
}

// round 10
// speedup vs baseline: 1.4277x; 1.0405x over previous
#include <cuda_runtime.h>
#include <math.h>

typedef unsigned long long ull;

// Problem constants
#define Bq 4
#define Tt 256
#define Dd 256
#define D2 512
#define BT 1024
#define SCALEF 0.0625f
#define BK 16

// ---------------- scratch (static device globals; no allocation) -------------
__device__ float g_xnorm[BT * Dd];
__device__ float g_xleft[BT * D2];
__device__ float g_xright[BT * D2];
__device__ float g_xtrans[BT * D2];
__device__ float g_o[BT * D2];
__device__ float g_q[BT * D2];
__device__ float g_k[BT * D2];
__device__ float g_v[BT * D2];
__device__ float g_hseq[BT * D2];
__device__ float g_h[BT * D2];
__device__ float g_convwt[4 * D2 * D2];
__device__ float g_cp[10 * BT * D2];    // split-K partials (10 x 2MB)
__device__ float g_A[Bq * Tt * Tt];
__device__ float g_ib[BT];
__device__ float g_fb[BT];
__device__ float g_alpha[BT];
__device__ float g_beta[BT];
__device__ float g_rowsum[BT];
__device__ float g_gnmu[16];
__device__ float g_gnrs[16];

#define PSLICE (BT * D2)   // 524288 floats per partial slice

__device__ __forceinline__ float sigm(float x) { return 1.f / (1.f + __expf(-x)); }

// ---------------- packed f32x2 helpers ----------------
__device__ __forceinline__ ull packf2(float lo, float hi) {
    ull r; asm("mov.b64 %0, {%1, %2};" : "=l"(r) : "f"(lo), "f"(hi)); return r;
}
__device__ __forceinline__ void fma2(ull& d, ull a, ull b) {
    asm("fma.rn.f32x2 %0, %1, %2, %0;" : "+l"(d) : "l"(a), "l"(b));
}
__device__ __forceinline__ float2 unpackf2(ull v) {
    float2 f; asm("mov.b64 {%0, %1}, %2;" : "=f"(f.x), "=f"(f.y) : "l"(v)); return f;
}

// ================  128x64 low-wavefront core (8 rows x 4 cols/thr) ==========
struct Sm2 {
    __align__(16) float As[2][BK][132];   // 128 rows + pad
    __align__(16) float Bs[2][BK][68];    // 64 rows + pad
};

// acc[p][c]: rows (ty*8+2p, +1), col (tx*4+c)
__device__ __forceinline__ void mma2(const Sm2* s, int buf, int ty, int tx,
                                     ull (&acc)[4][4]) {
#pragma unroll
    for (int kk = 0; kk < BK; kk++) {
        ulonglong2 a01 = *(const ulonglong2*)&s->As[buf][kk][ty * 8];
        ulonglong2 a23 = *(const ulonglong2*)&s->As[buf][kk][ty * 8 + 4];
        float4 b = *(const float4*)&s->Bs[buf][kk][tx * 4];
        ull ap[4] = {a01.x, a01.y, a23.x, a23.y};
        ull bp[4] = {packf2(b.x, b.x), packf2(b.y, b.y),
                     packf2(b.z, b.z), packf2(b.w, b.w)};
#pragma unroll
        for (int p = 0; p < 4; p++)
#pragma unroll
            for (int c = 0; c < 4; c++) fma2(acc[p][c], ap[p], bp[c]);
    }
}

// Double-buffered K loop.
__device__ __forceinline__ void gloop2(Sm2* s, const float* ApA, const float* ApB,
                                       int iters, bool avalid, ull (&acc)[4][4],
                                       int tid) {
    int rA = tid >> 1, kA = (tid & 1) * 8;
    int rB = tid >> 2, kB = (tid & 3) * 4;
    int ty = tid >> 4, tx = tid & 15;
    float4 z4 = make_float4(0.f, 0.f, 0.f, 0.f);
    float4 a0 = avalid ? *(const float4*)ApA : z4;
    float4 a1 = avalid ? *(const float4*)(ApA + 4) : z4;
    float4 b = *(const float4*)ApB;
#pragma unroll
    for (int i = 0; i < 4; i++) {
        s->As[0][kA + i][rA] = (&a0.x)[i];
        s->As[0][kA + 4 + i][rA] = (&a1.x)[i];
        s->Bs[0][kB + i][rB] = (&b.x)[i];
    }
    __syncthreads();
    int buf = 0;
    for (int it = 1; it < iters; it++) {
        a0 = avalid ? *(const float4*)(ApA + it * BK) : z4;
        a1 = avalid ? *(const float4*)(ApA + it * BK + 4) : z4;
        b = *(const float4*)(ApB + it * BK);
        mma2(s, buf, ty, tx, acc);
        int nb = buf ^ 1;
#pragma unroll
        for (int i = 0; i < 4; i++) {
            s->As[nb][kA + i][rA] = (&a0.x)[i];
            s->As[nb][kA + 4 + i][rA] = (&a1.x)[i];
            s->Bs[nb][kB + i][rB] = (&b.x)[i];
        }
        __syncthreads();
        buf = nb;
    }
    mma2(s, buf, ty, tx, acc);
}

__device__ __forceinline__ void store_tile_n512(float* out, int m0, int n, int ty,
                                                ull (&acc)[4][4]) {
#pragma unroll
    for (int p = 0; p < 4; p++) {
        float2 u[4];
#pragma unroll
        for (int c = 0; c < 4; c++) u[c] = unpackf2(acc[p][c]);
#pragma unroll
        for (int half = 0; half < 2; half++) {
            int m = m0 + ty * 8 + 2 * p + half;
            *(float4*)&out[(size_t)m * D2 + n] = make_float4(
                half ? u[0].y : u[0].x, half ? u[1].y : u[1].x,
                half ? u[2].y : u[2].x, half ? u[3].y : u[3].x);
        }
    }
}

// ---------------- fused dual projection (z picks weight set) -----------------
__global__ __launch_bounds__(256) void k_projdual(const float* __restrict__ A,
                                                  const float* __restrict__ W1,
                                                  const float* __restrict__ b1,
                                                  float* __restrict__ C1,
                                                  const float* __restrict__ W2,
                                                  const float* __restrict__ b2,
                                                  float* __restrict__ C2, int K) {
    __shared__ Sm2 s;
    int tid = threadIdx.x;
    const float* W = blockIdx.z ? W2 : W1;
    const float* bias = blockIdx.z ? b2 : b1;
    float* C = blockIdx.z ? C2 : C1;
    int m0 = blockIdx.y * 128, n0 = blockIdx.x * 64;
    const float* ApA = A + (size_t)(m0 + (tid >> 1)) * K + (tid & 1) * 8;
    const float* ApB = W + (size_t)(n0 + (tid >> 2)) * K + (tid & 3) * 4;
    ull acc[4][4] = {};
    gloop2(&s, ApA, ApB, K / BK, true, acc, tid);
    int ty = tid >> 4, tx = tid & 15;
    int n = n0 + tx * 4;
    float4 b4 = *(const float4*)&bias[n];
#pragma unroll
    for (int p = 0; p < 4; p++) {
        float2 u[4];
#pragma unroll
        for (int c = 0; c < 4; c++) u[c] = unpackf2(acc[p][c]);
#pragma unroll
        for (int half = 0; half < 2; half++) {
            int m = m0 + ty * 8 + 2 * p + half;
            *(float4*)&C[(size_t)m * D2 + n] = make_float4(
                (half ? u[0].y : u[0].x) + b4.x, (half ? u[1].y : u[1].x) + b4.y,
                (half ? u[2].y : u[2].x) + b4.z, (half ? u[3].y : u[3].x) + b4.w);
        }
    }
}

// -------- conv (8 K-slices) + Wo (2 K-slices) merged launch ------------------
// z in [0,8): conv slice (tau = z>>1, khalf = z&1, K=256)
// z in [8,10): Wo slice (sp = z-8, K=256)
__global__ __launch_bounds__(256) void k_cwo(const float* __restrict__ Wo) {
    __shared__ Sm2 s;
    int tid = threadIdx.x;
    int z = blockIdx.z;
    int m0 = blockIdx.y * 128, n0 = blockIdx.x * 64;
    const float *ApA, *ApB;
    bool avalid = true;
    if (z < 8) {
        int tau = z >> 1, half = z & 1;
        int row = m0 + (tid >> 1), b = row >> 8, t = row & 255;
        int tp = t - 3 + tau;
        avalid = (tp >= 0);
        int tpc = avalid ? tp : 0;
        ApA = g_xleft + (size_t)(b * Tt + tpc) * D2 + half * 256 + (tid & 1) * 8;
        ApB = g_convwt + (size_t)tau * 262144 +
              (size_t)(n0 + (tid >> 2)) * D2 + half * 256 + (tid & 3) * 4;
    } else {
        int sp = z - 8;
        ApA = g_xleft + (size_t)(m0 + (tid >> 1)) * D2 + sp * 256 + (tid & 1) * 8;
        ApB = Wo + (size_t)(n0 + (tid >> 2)) * D2 + sp * 256 + (tid & 3) * 4;
    }
    ull acc[4][4] = {};
    gloop2(&s, ApA, ApB, 256 / BK, avalid, acc, tid);
    int ty = tid >> 4, tx = tid & 15;
    store_tile_n512(g_cp + (size_t)z * PSLICE, m0, n0 + tx * 4, ty, acc);
}

// ---------------- generic split-K partial GEMM -> g_cp slice -----------------
__global__ __launch_bounds__(256) void k_partial(const float* __restrict__ A,
                                                 const float* __restrict__ W,
                                                 int Ktot, int Ksub, int N) {
    __shared__ Sm2 s;
    int tid = threadIdx.x;
    int m0 = blockIdx.y * 128, n0 = blockIdx.x * 64, sp = blockIdx.z;
    const float* ApA = A + (size_t)(m0 + (tid >> 1)) * Ktot + sp * Ksub + (tid & 1) * 8;
    const float* ApB = W + (size_t)(n0 + (tid >> 2)) * Ktot + sp * Ksub + (tid & 3) * 4;
    ull acc[4][4] = {};
    gloop2(&s, ApA, ApB, Ksub / BK, true, acc, tid);
    int ty = tid >> 4, tx = tid & 15;
    int n = n0 + tx * 4;
    float* out = g_cp + (size_t)sp * PSLICE;
#pragma unroll
    for (int p = 0; p < 4; p++) {
        float2 u[4];
#pragma unroll
        for (int c = 0; c < 4; c++) u[c] = unpackf2(acc[p][c]);
#pragma unroll
        for (int half = 0; half < 2; half++) {
            int m = m0 + ty * 8 + 2 * p + half;
            *(float4*)&out[(size_t)m * N + n] = make_float4(
                half ? u[0].y : u[0].x, half ? u[1].y : u[1].x,
                half ? u[2].y : u[2].x, half ? u[3].y : u[3].x);
        }
    }
}

// ---------------- qkv on 128x64 core -----------------
__global__ __launch_bounds__(256) void k_qkv(const float* __restrict__ Wq,
                                             const float* __restrict__ Wk,
                                             const float* __restrict__ Wv) {
    __shared__ Sm2 s;
    int tid = threadIdx.x;
    int z = blockIdx.z, which = z >> 2, h = z & 3;
    const float* src = (which == 2) ? g_xleft : g_xtrans;
    const float* W = (which == 0) ? Wq : ((which == 1) ? Wk : Wv);
    float* dst = (which == 0) ? g_q : ((which == 1) ? g_k : g_v);
    float sc = (which == 1) ? SCALEF : 1.f;
    int m0 = blockIdx.y * 128, n0 = blockIdx.x * 64;
    const float* ApA = src + (size_t)(m0 + (tid >> 1)) * D2 + h * 128 + (tid & 1) * 8;
    const float* ApB = W + (size_t)h * 16384 + (size_t)(n0 + (tid >> 2)) * 128 + (tid & 3) * 4;
    ull acc[4][4] = {};
    gloop2(&s, ApA, ApB, 128 / BK, true, acc, tid);
    int ty = tid >> 4, tx = tid & 15;
    int n = h * 128 + n0 + tx * 4;
#pragma unroll
    for (int p = 0; p < 4; p++) {
        float2 u[4];
#pragma unroll
        for (int c = 0; c < 4; c++) u[c] = unpackf2(acc[p][c]);
#pragma unroll
        for (int half = 0; half < 2; half++) {
            int m = m0 + ty * 8 + 2 * p + half;
            *(float4*)&dst[(size_t)m * D2 + n] = make_float4(
                sc * (half ? u[0].y : u[0].x), sc * (half ? u[1].y : u[1].x),
                sc * (half ? u[2].y : u[2].x), sc * (half ? u[3].y : u[3].x));
        }
    }
}

// ====================  reduce / epilogue kernels  ============================
// conv-swish (slices 0..7 -> xtrans) + Wo-sigmoid (slices 8..9 -> o) fused
__global__ void k_cwepi(const float* __restrict__ cb, const float* __restrict__ bo) {
    int idx = blockIdx.x * 256 + threadIdx.x;            // float4 idx, 131072
    size_t off = (size_t)idx * 4;
    int n = (idx & 127) * 4;
    float4 sm = *(const float4*)(g_cp + off);
#pragma unroll
    for (int p = 1; p < 8; p++) {
        float4 q = *(const float4*)(g_cp + (size_t)p * PSLICE + off);
        sm.x += q.x; sm.y += q.y; sm.z += q.z; sm.w += q.w;
    }
    float4 b4 = *(const float4*)&cb[n];
    float z0 = sm.x + b4.x, z1 = sm.y + b4.y, z2 = sm.z + b4.z, z3 = sm.w + b4.w;
    *(float4*)(g_xtrans + off) = make_float4(z0 * sigm(z0), z1 * sigm(z1),
                                             z2 * sigm(z2), z3 * sigm(z3));
    float4 s0 = *(const float4*)(g_cp + 8 * (size_t)PSLICE + off);
    float4 s1 = *(const float4*)(g_cp + 9 * (size_t)PSLICE + off);
    float4 ob = *(const float4*)&bo[n];
    *(float4*)(g_o + off) = make_float4(sigm(s0.x + s1.x + ob.x), sigm(s0.y + s1.y + ob.y),
                                        sigm(s0.z + s1.z + ob.z), sigm(s0.w + s1.w + ob.w));
}

__global__ void k_sepi(const float* __restrict__ gn_g, const float* __restrict__ gn_b) {
    int idx = blockIdx.x * 256 + threadIdx.x;            // float4 idx over g_h
    size_t off = (size_t)idx * 4;
    float4 sm = *(const float4*)(g_cp + off);
#pragma unroll
    for (int p = 1; p < 4; p++) {
        float4 q = *(const float4*)(g_cp + (size_t)p * PSLICE + off);
        sm.x += q.x; sm.y += q.y; sm.z += q.z; sm.w += q.w;
    }
    int n = (idx & 127) * 4;
    int m = idx >> 7;
    int b = m >> 8, hh = n >> 7;
    float mu = g_gnmu[b * 4 + hh], rs = g_gnrs[b * 4 + hh];
    float4 hs = *(const float4*)(g_hseq + off);
    float4 xr = *(const float4*)(g_xright + off);
    float4 gg = *(const float4*)&gn_g[n];
    float4 gb = *(const float4*)&gn_b[n];
    float sv[4] = {sm.x, sm.y, sm.z, sm.w};
    float hv[4] = {hs.x, hs.y, hs.z, hs.w};
    float xv[4] = {xr.x, xr.y, xr.z, xr.w};
    float ggv[4] = {gg.x, gg.y, gg.z, gg.w};
    float gbv[4] = {gb.x, gb.y, gb.z, gb.w};
    float ov[4];
#pragma unroll
    for (int j = 0; j < 4; j++) {
        float zn = (hv[j] - mu) * rs;
        float hg = zn * ggv[j] + gbv[j] + sv[j];
        ov[j] = hg * xv[j] * sigm(xv[j]);
    }
    *(float4*)(g_h + off) = make_float4(ov[0], ov[1], ov[2], ov[3]);
}

__global__ void k_lepi(const float* __restrict__ bl, const float* __restrict__ x,
                       float* __restrict__ out) {        // 4 parts + bias + residual
    int idx = blockIdx.x * 256 + threadIdx.x;            // float4 idx, 65536
    size_t off = (size_t)idx * 4;
    float4 sm = *(const float4*)(g_cp + off);
#pragma unroll
    for (int p = 1; p < 4; p++) {
        float4 q = *(const float4*)(g_cp + (size_t)p * PSLICE + off);
        sm.x += q.x; sm.y += q.y; sm.z += q.z; sm.w += q.w;
    }
    int n = (idx & 63) * 4;
    float4 b4 = *(const float4*)&bl[n];
    float4 xv = *(const float4*)(x + off);
    *(float4*)(out + off) = make_float4(sm.x + b4.x + xv.x, sm.y + b4.y + xv.y,
                                        sm.z + b4.z + xv.z, sm.w + b4.w + xv.w);
}

// ====================  small kernels  ============================
__global__ void k_layernorm(const float* __restrict__ x, const float* __restrict__ g,
                            const float* __restrict__ b) {
    int row = blockIdx.x, tid = threadIdx.x;
    float v = x[row * Dd + tid];
    float s = v, s2 = v * v;
#pragma unroll
    for (int o = 16; o; o >>= 1) {
        s += __shfl_xor_sync(0xffffffffu, s, o);
        s2 += __shfl_xor_sync(0xffffffffu, s2, o);
    }
    __shared__ float sh[8], sh2[8];
    int w = tid >> 5, l = tid & 31;
    if (l == 0) { sh[w] = s; sh2[w] = s2; }
    __syncthreads();
    if (tid == 0) {
        float a = 0, a2 = 0;
#pragma unroll
        for (int i = 0; i < 8; i++) { a += sh[i]; a2 += sh2[i]; }
        sh[0] = a; sh2[0] = a2;
    }
    __syncthreads();
    float mu = sh[0] * (1.f / Dd);
    float var = sh2[0] * (1.f / Dd) - mu * mu;
    float r = rsqrtf(var + 1e-5f);
    g_xnorm[row * Dd + tid] = (v - mu) * r * g[tid] + b[tid];
}

__global__ void k_convwt(const float* __restrict__ cw) {
    int idx = blockIdx.x * 256 + threadIdx.x;
    float4 w = *(const float4*)(cw + (size_t)idx * 4);
    g_convwt[0 * 262144 + idx] = w.x;
    g_convwt[1 * 262144 + idx] = w.y;
    g_convwt[2 * 262144 + idx] = w.z;
    g_convwt[3 * 262144 + idx] = w.w;
}

__global__ void k_ibfb(const float* __restrict__ Wi, const float* __restrict__ Wf,
                       const float* __restrict__ bi, const float* __restrict__ bf) {
    int row = blockIdx.x * 8 + (threadIdx.x >> 5);
    int l = threadIdx.x & 31;
    const float* xr = g_xleft + (size_t)row * D2;
    float si = 0, sf = 0;
#pragma unroll 4
    for (int j = l; j < D2; j += 32) {
        float v = xr[j];
        si += v * Wi[j];
        sf += v * Wf[j];
    }
#pragma unroll
    for (int o = 16; o; o >>= 1) {
        si += __shfl_xor_sync(0xffffffffu, si, o);
        sf += __shfl_xor_sync(0xffffffffu, sf, o);
    }
    if (l == 0) {
        g_ib[row] = si + bi[0];
        g_fb[row] = sf + bf[0];
        g_rowsum[row] = 0.f;
    }
}

__global__ void k_scan() {
    int b = threadIdx.x;
    if (b < Bq) {
        float m = 0.f, F = 0.f;
        for (int t = 0; t < Tt; t++) {
            float ib = g_ib[b * Tt + t], fb = g_fb[b * Tt + t];
            float mn = fmaxf(fb + m, ib);
            F += fb;
            g_alpha[b * Tt + t] = ib - F;
            g_beta[b * Tt + t] = F - mn;
            m = mn;
        }
    }
}

// =============  attention kernels (proven versions)  =================
template <int BMt, int BNt>
__device__ __forceinline__ void mma_t(const float (*As)[BMt + 4], const float (*Bs)[BNt + 4],
                                      int ty, int tx, ull acc[BMt / 32][BNt / 16]) {
    constexpr int PAIRS = BMt / 32, CN = BNt / 16;
#pragma unroll
    for (int kk = 0; kk < BK; kk++) {
        ull ap[PAIRS];
        if constexpr (PAIRS == 2) {
            ulonglong2 av = *(const ulonglong2*)&As[kk][ty * 4];
            ap[0] = av.x; ap[1] = av.y;
        } else {
            ap[0] = *(const ull*)&As[kk][ty * 2];
        }
        float bv[CN];
        if constexpr (CN == 4) {
            float4 b4 = *(const float4*)&Bs[kk][tx * 4];
            bv[0] = b4.x; bv[1] = b4.y; bv[2] = b4.z; bv[3] = b4.w;
        } else {
            float2 b2 = *(const float2*)&Bs[kk][tx * 2];
            bv[0] = b2.x; bv[1] = b2.y;
        }
#pragma unroll
        for (int j = 0; j < CN; j++) {
            ull bp = packf2(bv[j], bv[j]);
#pragma unroll
            for (int p = 0; p < PAIRS; p++) fma2(acc[p][j], ap[p], bp);
        }
    }
}

#define STS_A(BUF, AV) \
    do { As[BUF][lk + 0][lrA] = (AV).x; As[BUF][lk + 1][lrA] = (AV).y; \
         As[BUF][lk + 2][lrA] = (AV).z; As[BUF][lk + 3][lrA] = (AV).w; } while (0)
#define STS_B(BUF, WV) \
    do { Bs[BUF][lk + 0][lrB] = (WV).x; Bs[BUF][lk + 1][lrB] = (WV).y; \
         Bs[BUF][lk + 2][lrB] = (WV).z; Bs[BUF][lk + 3][lrB] = (WV).w; } while (0)

__global__ __launch_bounds__(256) void k_attn1() {
    constexpr int BMt = 32, BNt = 32;
    int m0 = blockIdx.y * BMt, n0 = blockIdx.x * BNt;
    if (n0 > m0) return;
    __shared__ __align__(16) float As[2][BK][BMt + 4];
    __shared__ __align__(16) float Bs[2][BK][BNt + 4];
    int tid = threadIdx.x;
    int z = blockIdx.z;
    int ty = tid >> 4, tx = tid & 15;
    bool doA = (tid < 128), doB = (tid >= 128);
    int lrA = tid >> 2, lrB = (tid & 127) >> 2, lk = (tid & 3) * 4;
    const float* Ap = g_q + (size_t)(z * Tt + m0 + lrA) * D2 + lk;
    const float* Wp = g_k + (size_t)(z * Tt + n0 + lrB) * D2 + lk;
    ull acc[1][2] = {};
    float4 a, w;
    if (doA) a = *(const float4*)Ap;
    if (doB) w = *(const float4*)Wp;
    if (doA) STS_A(0, a);
    if (doB) STS_B(0, w);
    __syncthreads();
    int buf = 0;
    for (int k0 = BK; k0 < D2; k0 += BK) {
        if (doA) a = *(const float4*)(Ap + k0);
        if (doB) w = *(const float4*)(Wp + k0);
        mma_t<32, 32>(As[buf], Bs[buf], ty, tx, acc);
        if (doA) STS_A(buf ^ 1, a);
        if (doB) STS_B(buf ^ 1, w);
        __syncthreads();
        buf ^= 1;
    }
    mma_t<32, 32>(As[buf], Bs[buf], ty, tx, acc);

    float2 lohi0 = unpackf2(acc[0][0]), lohi1 = unpackf2(acc[0][1]);
    float al0 = g_alpha[z * Tt + n0 + tx * 2];
    float al1 = g_alpha[z * Tt + n0 + tx * 2 + 1];
#pragma unroll
    for (int half = 0; half < 2; half++) {
        int t = m0 + ty * 2 + half;
        float be = g_beta[z * Tt + t];
        int s0 = n0 + tx * 2, s1 = s0 + 1;
        float v0 = (s0 <= t) ? __expf(al0 + be) * (half ? lohi0.y : lohi0.x) : 0.f;
        float v1 = (s1 <= t) ? __expf(al1 + be) * (half ? lohi1.y : lohi1.x) : 0.f;
        *(float2*)&g_A[(size_t)z * Tt * Tt + (size_t)t * Tt + s0] = make_float2(v0, v1);
        float p = v0 + v1;
#pragma unroll
        for (int off = 1; off < 16; off <<= 1) p += __shfl_xor_sync(0xffffffffu, p, off);
        if (tx == 0) atomicAdd(&g_rowsum[z * Tt + t], p);
    }
}

__global__ __launch_bounds__(256) void k_attn2() {
    constexpr int BMt = 32, BNt = 64;
    __shared__ __align__(16) float As[2][BK][BMt + 4];
    __shared__ __align__(16) float Bs[2][BK][BNt + 4];
    int tid = threadIdx.x;
    int z = blockIdx.z;
    int m0 = blockIdx.y * BMt, n0 = blockIdx.x * BNt;
    int ty = tid >> 4, tx = tid & 15;
    bool doA = (tid < 128);
    int lrA = tid >> 2, lk = (tid & 3) * 4;
    int brow = tid >> 4, bcol = (tid & 15) * 4;
    int Kend = m0 + BMt;
    const float* Ap = g_A + (size_t)z * Tt * Tt + (size_t)(m0 + lrA) * Tt + lk;
    const float* Vb = g_v + (size_t)z * Tt * D2;
    ull acc[1][4] = {};
    float4 a, w;
    if (doA) a = *(const float4*)Ap;
    w = *(const float4*)(Vb + (size_t)brow * D2 + n0 + bcol);
    if (doA) STS_A(0, a);
    *(float4*)&Bs[0][brow][bcol] = w;
    __syncthreads();
    int buf = 0;
    for (int k0 = BK; k0 < Kend; k0 += BK) {
        if (doA) a = *(const float4*)(Ap + k0);
        w = *(const float4*)(Vb + (size_t)(k0 + brow) * D2 + n0 + bcol);
        mma_t<32, 64>(As[buf], Bs[buf], ty, tx, acc);
        if (doA) STS_A(buf ^ 1, a);
        *(float4*)&Bs[buf ^ 1][brow][bcol] = w;
        __syncthreads();
        buf ^= 1;
    }
    mma_t<32, 64>(As[buf], Bs[buf], ty, tx, acc);

    float2 lohi[4];
#pragma unroll
    for (int j = 0; j < 4; j++) lohi[j] = unpackf2(acc[0][j]);
#pragma unroll
    for (int half = 0; half < 2; half++) {
        int m = m0 + ty * 2 + half;
        int r = z * Tt + m;
        float rs = g_rowsum[r];
        float inv = 1.f / (fmaxf(fabsf(rs), 1.f) + 1e-8f);
        float4 og = *(const float4*)&g_o[(size_t)r * D2 + n0 + tx * 4];
        float4 ov = make_float4((half ? lohi[0].y : lohi[0].x) * inv * og.x,
                                (half ? lohi[1].y : lohi[1].x) * inv * og.y,
                                (half ? lohi[2].y : lohi[2].x) * inv * og.z,
                                (half ? lohi[3].y : lohi[3].x) * inv * og.w);
        *(float4*)&g_hseq[(size_t)r * D2 + n0 + tx * 4] = ov;
    }
}

__global__ void k_gnstats() {
    int bh = blockIdx.x;
    int b = bh >> 2, h = bh & 3;
    int tid = threadIdx.x;
    float s = 0, s2 = 0;
    const float* base = g_hseq + (size_t)(b * Tt) * D2 + h * 128;
    for (int i = tid; i < Tt * 128; i += 256) {
        int t = i >> 7, d = i & 127;
        float v = base[(size_t)t * D2 + d];
        s += v; s2 += v * v;
    }
#pragma unroll
    for (int o = 16; o; o >>= 1) {
        s += __shfl_xor_sync(0xffffffffu, s, o);
        s2 += __shfl_xor_sync(0xffffffffu, s2, o);
    }
    __shared__ float sh[8], sh2[8];
    int w = tid >> 5, l = tid & 31;
    if (l == 0) { sh[w] = s; sh2[w] = s2; }
    __syncthreads();
    if (tid == 0) {
        float a = 0, a2 = 0;
#pragma unroll
        for (int i = 0; i < 8; i++) { a += sh[i]; a2 += sh2[i]; }
        float mu = a * (1.f / (Tt * 128));
        float var = a2 * (1.f / (Tt * 128)) - mu * mu;
        g_gnmu[bh] = mu;
        g_gnrs[bh] = rsqrtf(var + 1e-5f);
    }
}

// ---------------- launch ----------------
extern "C" void kernel_launch(void* const* d_in, const int* in_sizes, int n_in,
                              void* d_out, int out_size) {
    const float* x       = (const float*)d_in[0];
    const float* ln_g    = (const float*)d_in[1];
    const float* ln_b    = (const float*)d_in[2];
    const float* W_left  = (const float*)d_in[3];
    const float* b_left  = (const float*)d_in[4];
    const float* W_right = (const float*)d_in[5];
    const float* b_right = (const float*)d_in[6];
    const float* Wi      = (const float*)d_in[7];
    const float* bi      = (const float*)d_in[8];
    const float* Wf      = (const float*)d_in[9];
    const float* bf      = (const float*)d_in[10];
    const float* Wo      = (const float*)d_in[11];
    const float* bo      = (const float*)d_in[12];
    const float* Wq      = (const float*)d_in[13];
    const float* Wk      = (const float*)d_in[14];
    const float* Wv      = (const float*)d_in[15];
    const float* conv_w  = (const float*)d_in[16];
    const float* conv_b  = (const float*)d_in[17];
    const float* skip_W  = (const float*)d_in[18];
    const float* gn_g    = (const float*)d_in[19];
    const float* gn_b    = (const float*)d_in[20];
    const float* W_last  = (const float*)d_in[21];
    const float* b_last  = (const float*)d_in[22];
    float* out = (float*)d_out;

    float *p_xnorm, *p_xleft, *p_xright, *p_xtrans, *p_h;
    cudaGetSymbolAddress((void**)&p_xnorm, g_xnorm);
    cudaGetSymbolAddress((void**)&p_xleft, g_xleft);
    cudaGetSymbolAddress((void**)&p_xright, g_xright);
    cudaGetSymbolAddress((void**)&p_xtrans, g_xtrans);
    cudaGetSymbolAddress((void**)&p_h, g_h);

    k_layernorm<<<BT, 256>>>(x, ln_g, ln_b);
    k_convwt<<<1024, 256>>>(conv_w);
    k_projdual<<<dim3(8, 8, 2), 256>>>(p_xnorm, W_left, b_left, p_xleft,
                                       W_right, b_right, p_xright, 256);
    k_cwo<<<dim3(8, 8, 10), 256>>>(Wo);
    k_cwepi<<<512, 256>>>(conv_b, bo);
    k_ibfb<<<128, 256>>>(Wi, Wf, bi, bf);
    k_scan<<<1, 32>>>();
    k_qkv<<<dim3(2, 8, 12), 256>>>(Wq, Wk, Wv);
    k_attn1<<<dim3(8, 8, 4), 256>>>();
    k_attn2<<<dim3(8, 8, 4), 256>>>();
    k_gnstats<<<16, 256>>>();
    k_partial<<<dim3(8, 8, 4), 256>>>(p_xtrans, skip_W, 512, 128, 512);
    k_sepi<<<512, 256>>>(gn_g, gn_b);
    k_partial<<<dim3(4, 8, 4), 256>>>(p_h, W_last, 512, 128, 256);
    k_lepi<<<256, 256>>>(b_last, x, out);
}

// round 12
// speedup vs baseline: 1.5789x; 1.1059x over previous
#include <cuda_runtime.h>
#include <cuda_bf16.h>
#include <math.h>

typedef unsigned long long ull;

// Problem constants
#define Bq 4
#define Tt 256
#define Dd 256
#define D2 512
#define BT 1024
#define SCALEF 0.0625f
#define BK 16

// ---------------- scratch (static device globals; no allocation) -------------
__device__ float g_xnorm[BT * Dd];
__device__ float g_xleft[BT * D2];
__device__ float g_xright[BT * D2];
__device__ float g_xtrans[BT * D2];
__device__ float g_o[BT * D2];
__device__ float g_q[BT * D2];
__device__ float g_k[BT * D2];
__device__ float g_v[BT * D2];
__device__ float g_hseq[BT * D2];
__device__ float g_h[BT * D2];
__device__ float g_cp[10 * BT * D2];    // split-K partials (10 x 2MB)
__device__ float g_A[Bq * Tt * Tt];
__device__ float g_ib[BT];
__device__ float g_fb[BT];
__device__ float g_alpha[BT];
__device__ float g_beta[BT];
__device__ float g_rowsum[BT];
__device__ float g_gnmu[16];
__device__ float g_gnrs[16];

// bf16 hi/lo tensors (packed as uints: low half = even col, high = odd col)
__device__ __align__(16) unsigned int g_xlh_u[BT * D2 / 2];
__device__ __align__(16) unsigned int g_xll_u[BT * D2 / 2];
__device__ __align__(16) unsigned int g_cwh_u[4 * D2 * D2 / 2];
__device__ __align__(16) unsigned int g_cwl_u[4 * D2 * D2 / 2];
__device__ __align__(16) unsigned int g_woh_u[D2 * D2 / 2];
__device__ __align__(16) unsigned int g_wol_u[D2 * D2 / 2];

#define PSLICE (BT * D2)   // 524288 floats per partial slice

__device__ __forceinline__ float sigm(float x) { return 1.f / (1.f + __expf(-x)); }

// ---------------- packed f32x2 helpers ----------------
__device__ __forceinline__ ull packf2(float lo, float hi) {
    ull r; asm("mov.b64 %0, {%1, %2};" : "=l"(r) : "f"(lo), "f"(hi)); return r;
}
__device__ __forceinline__ void fma2(ull& d, ull a, ull b) {
    asm("fma.rn.f32x2 %0, %1, %2, %0;" : "+l"(d) : "l"(a), "l"(b));
}
__device__ __forceinline__ float2 unpackf2(ull v) {
    float2 f; asm("mov.b64 {%0, %1}, %2;" : "=f"(f.x), "=f"(f.y) : "l"(v)); return f;
}

// ---------------- warp-level bf16 HMMA (sm_80+; works on plain sm_100) -------
__device__ __forceinline__ void mma_bf16(float (&c)[4], const unsigned (&a)[4],
                                         unsigned b0, unsigned b1) {
    asm volatile(
        "mma.sync.aligned.m16n8k16.row.col.f32.bf16.bf16.f32 "
        "{%0,%1,%2,%3}, {%4,%5,%6,%7}, {%8,%9}, {%0,%1,%2,%3};"
        : "+f"(c[0]), "+f"(c[1]), "+f"(c[2]), "+f"(c[3])
        : "r"(a[0]), "r"(a[1]), "r"(a[2]), "r"(a[3]), "r"(b0), "r"(b1));
}

// =====  tensor-core conv (z<8: tau,khalf K=256) + Wo (z=8,9 K=256) ==========
// CTA: 128x64 tile, 8 warps (4 in M x 2 in N), warp = 32x32 = 2x4 m16n8k16.
__global__ __launch_bounds__(256) void k_cwo() {
    __shared__ unsigned int Ah[128][20], Al[128][20];
    __shared__ unsigned int Bh[64][20], Bl[64][20];
    int tid = threadIdx.x;
    int z = blockIdx.z;
    int m0 = blockIdx.y * 128, n0 = blockIdx.x * 64;
    int lane = tid & 31, w = tid >> 5;
    int warpM = w >> 1, warpN = w & 1;
    int g = lane >> 2, tig = lane & 3;

    // fill assignments
    int rA = tid >> 1, jA = (tid & 1) * 8;   // A: row rA, 8 uints from jA
    int nB = tid >> 2, jB = (tid & 3) * 4;   // B: row nB, 4 uints from jB

    size_t arow;
    bool valid = true;
    int cbase;
    const unsigned int *whp, *wlp;
    if (z < 8) {
        int tau = z >> 1, khalf = z & 1;
        int row = m0 + rA, b = row >> 8, t = row & 255;
        int tp = t - 3 + tau;
        valid = (tp >= 0);
        arow = (size_t)(b * Tt + (valid ? tp : 0)) * 256;
        cbase = khalf * 128;
        whp = g_cwh_u + (size_t)tau * 131072;
        wlp = g_cwl_u + (size_t)tau * 131072;
    } else {
        int sp = z - 8;
        arow = (size_t)(m0 + rA) * 256;
        cbase = sp * 128;
        whp = g_woh_u;
        wlp = g_wol_u;
    }

    float acc[2][4][4];
#pragma unroll
    for (int mt = 0; mt < 2; mt++)
#pragma unroll
        for (int nt = 0; nt < 4; nt++)
#pragma unroll
            for (int i = 0; i < 4; i++) acc[mt][nt][i] = 0.f;

    for (int it = 0; it < 8; it++) {
        int cb = cbase + it * 16;   // uint col base (32 bf16 this iter)
        // ---- fill ----
        if (valid) {
            uint4 h0 = *(const uint4*)&g_xlh_u[arow + cb + jA];
            uint4 h1 = *(const uint4*)&g_xlh_u[arow + cb + jA + 4];
            *(uint4*)&Ah[rA][jA] = h0;
            *(uint4*)&Ah[rA][jA + 4] = h1;
            uint4 l0 = *(const uint4*)&g_xll_u[arow + cb + jA];
            uint4 l1 = *(const uint4*)&g_xll_u[arow + cb + jA + 4];
            *(uint4*)&Al[rA][jA] = l0;
            *(uint4*)&Al[rA][jA + 4] = l1;
        } else {
            uint4 zz = make_uint4(0u, 0u, 0u, 0u);
            *(uint4*)&Ah[rA][jA] = zz;
            *(uint4*)&Ah[rA][jA + 4] = zz;
            *(uint4*)&Al[rA][jA] = zz;
            *(uint4*)&Al[rA][jA + 4] = zz;
        }
        {
            uint4 bh = *(const uint4*)&whp[(size_t)(n0 + nB) * 256 + cb + jB];
            uint4 bl = *(const uint4*)&wlp[(size_t)(n0 + nB) * 256 + cb + jB];
            *(uint4*)&Bh[nB][jB] = bh;
            *(uint4*)&Bl[nB][jB] = bl;
        }
        __syncthreads();
        // ---- compute: 2 k16 steps ----
#pragma unroll
        for (int half = 0; half < 2; half++) {
            int kb = half * 8;
            unsigned ah[2][4], al[2][4];
#pragma unroll
            for (int mt = 0; mt < 2; mt++) {
                int r0 = warpM * 32 + mt * 16 + g;
                ah[mt][0] = Ah[r0][kb + tig];
                ah[mt][1] = Ah[r0 + 8][kb + tig];
                ah[mt][2] = Ah[r0][kb + 4 + tig];
                ah[mt][3] = Ah[r0 + 8][kb + 4 + tig];
                al[mt][0] = Al[r0][kb + tig];
                al[mt][1] = Al[r0 + 8][kb + tig];
                al[mt][2] = Al[r0][kb + 4 + tig];
                al[mt][3] = Al[r0 + 8][kb + 4 + tig];
            }
#pragma unroll
            for (int nt = 0; nt < 4; nt++) {
                int c0 = warpN * 32 + nt * 8 + g;
                unsigned bh0 = Bh[c0][kb + tig], bh1 = Bh[c0][kb + 4 + tig];
                unsigned bl0 = Bl[c0][kb + tig], bl1 = Bl[c0][kb + 4 + tig];
#pragma unroll
                for (int mt = 0; mt < 2; mt++) {
                    mma_bf16(acc[mt][nt], ah[mt], bh0, bh1);
                    mma_bf16(acc[mt][nt], ah[mt], bl0, bl1);
                    mma_bf16(acc[mt][nt], al[mt], bh0, bh1);
                }
            }
        }
        __syncthreads();
    }

    // ---- store partial tile to g_cp slice ----
    float* out = g_cp + (size_t)z * PSLICE;
#pragma unroll
    for (int mt = 0; mt < 2; mt++) {
#pragma unroll
        for (int nt = 0; nt < 4; nt++) {
            int r0 = m0 + warpM * 32 + mt * 16 + g;
            int c = n0 + warpN * 32 + nt * 8 + tig * 2;
            *(float2*)&out[(size_t)r0 * D2 + c] = make_float2(acc[mt][nt][0], acc[mt][nt][1]);
            *(float2*)&out[(size_t)(r0 + 8) * D2 + c] = make_float2(acc[mt][nt][2], acc[mt][nt][3]);
        }
    }
}

// ------------- bf16 hi/lo weight conversion kernels -------------
__global__ void k_cvtw(const float* __restrict__ cw) {
    int idx = blockIdx.x * 256 + threadIdx.x;  // o*512+i, 262144
    float4 w = *(const float4*)(cw + (size_t)idx * 4);
    __nv_bfloat16* H = (__nv_bfloat16*)g_cwh_u;
    __nv_bfloat16* L = (__nv_bfloat16*)g_cwl_u;
    float v[4] = {w.x, w.y, w.z, w.w};
#pragma unroll
    for (int tau = 0; tau < 4; tau++) {
        __nv_bfloat16 h = __float2bfloat16(v[tau]);
        H[tau * 262144 + idx] = h;
        L[tau * 262144 + idx] = __float2bfloat16(v[tau] - __bfloat162float(h));
    }
}
__global__ void k_cvtwo(const float* __restrict__ Wo) {
    int idx = blockIdx.x * 256 + threadIdx.x;  // float4 idx, 65536
    float4 w = *(const float4*)(Wo + (size_t)idx * 4);
    __nv_bfloat16* H = (__nv_bfloat16*)g_woh_u;
    __nv_bfloat16* L = (__nv_bfloat16*)g_wol_u;
    int base = idx * 4;
    float v[4] = {w.x, w.y, w.z, w.w};
#pragma unroll
    for (int j = 0; j < 4; j++) {
        __nv_bfloat16 h = __float2bfloat16(v[j]);
        H[base + j] = h;
        L[base + j] = __float2bfloat16(v[j] - __bfloat162float(h));
    }
}

// ================  128x64 low-wavefront SIMT core (proven) ==========
struct Sm2 {
    __align__(16) float As[2][BK][132];
    __align__(16) float Bs[2][BK][68];
};

__device__ __forceinline__ void mma2(const Sm2* s, int buf, int ty, int tx,
                                     ull (&acc)[4][4]) {
#pragma unroll
    for (int kk = 0; kk < BK; kk++) {
        ulonglong2 a01 = *(const ulonglong2*)&s->As[buf][kk][ty * 8];
        ulonglong2 a23 = *(const ulonglong2*)&s->As[buf][kk][ty * 8 + 4];
        float4 b = *(const float4*)&s->Bs[buf][kk][tx * 4];
        ull ap[4] = {a01.x, a01.y, a23.x, a23.y};
        ull bp[4] = {packf2(b.x, b.x), packf2(b.y, b.y),
                     packf2(b.z, b.z), packf2(b.w, b.w)};
#pragma unroll
        for (int p = 0; p < 4; p++)
#pragma unroll
            for (int c = 0; c < 4; c++) fma2(acc[p][c], ap[p], bp[c]);
    }
}

__device__ __forceinline__ void gloop2(Sm2* s, const float* ApA, const float* ApB,
                                       int iters, bool avalid, ull (&acc)[4][4],
                                       int tid) {
    int rA = tid >> 1, kA = (tid & 1) * 8;
    int rB = tid >> 2, kB = (tid & 3) * 4;
    int ty = tid >> 4, tx = tid & 15;
    float4 z4 = make_float4(0.f, 0.f, 0.f, 0.f);
    float4 a0 = avalid ? *(const float4*)ApA : z4;
    float4 a1 = avalid ? *(const float4*)(ApA + 4) : z4;
    float4 b = *(const float4*)ApB;
#pragma unroll
    for (int i = 0; i < 4; i++) {
        s->As[0][kA + i][rA] = (&a0.x)[i];
        s->As[0][kA + 4 + i][rA] = (&a1.x)[i];
        s->Bs[0][kB + i][rB] = (&b.x)[i];
    }
    __syncthreads();
    int buf = 0;
    for (int it = 1; it < iters; it++) {
        a0 = avalid ? *(const float4*)(ApA + it * BK) : z4;
        a1 = avalid ? *(const float4*)(ApA + it * BK + 4) : z4;
        b = *(const float4*)(ApB + it * BK);
        mma2(s, buf, ty, tx, acc);
        int nb = buf ^ 1;
#pragma unroll
        for (int i = 0; i < 4; i++) {
            s->As[nb][kA + i][rA] = (&a0.x)[i];
            s->As[nb][kA + 4 + i][rA] = (&a1.x)[i];
            s->Bs[nb][kB + i][rB] = (&b.x)[i];
        }
        __syncthreads();
        buf = nb;
    }
    mma2(s, buf, ty, tx, acc);
}

// ---------------- fused dual projection; z==0 also emits bf16 hi/lo ----------
__global__ __launch_bounds__(256) void k_projdual(const float* __restrict__ A,
                                                  const float* __restrict__ W1,
                                                  const float* __restrict__ b1,
                                                  float* __restrict__ C1,
                                                  const float* __restrict__ W2,
                                                  const float* __restrict__ b2,
                                                  float* __restrict__ C2, int K) {
    __shared__ Sm2 s;
    int tid = threadIdx.x;
    const float* W = blockIdx.z ? W2 : W1;
    const float* bias = blockIdx.z ? b2 : b1;
    float* C = blockIdx.z ? C2 : C1;
    int m0 = blockIdx.y * 128, n0 = blockIdx.x * 64;
    const float* ApA = A + (size_t)(m0 + (tid >> 1)) * K + (tid & 1) * 8;
    const float* ApB = W + (size_t)(n0 + (tid >> 2)) * K + (tid & 3) * 4;
    ull acc[4][4] = {};
    gloop2(&s, ApA, ApB, K / BK, true, acc, tid);
    int ty = tid >> 4, tx = tid & 15;
    int n = n0 + tx * 4;
    float4 b4 = *(const float4*)&bias[n];
    bool emit = (blockIdx.z == 0);
#pragma unroll
    for (int p = 0; p < 4; p++) {
        float2 u[4];
#pragma unroll
        for (int c = 0; c < 4; c++) u[c] = unpackf2(acc[p][c]);
#pragma unroll
        for (int half = 0; half < 2; half++) {
            int m = m0 + ty * 8 + 2 * p + half;
            float o0 = (half ? u[0].y : u[0].x) + b4.x;
            float o1 = (half ? u[1].y : u[1].x) + b4.y;
            float o2 = (half ? u[2].y : u[2].x) + b4.z;
            float o3 = (half ? u[3].y : u[3].x) + b4.w;
            *(float4*)&C[(size_t)m * D2 + n] = make_float4(o0, o1, o2, o3);
            if (emit) {
                __nv_bfloat16 h0 = __float2bfloat16(o0), h1 = __float2bfloat16(o1);
                __nv_bfloat16 h2 = __float2bfloat16(o2), h3 = __float2bfloat16(o3);
                __nv_bfloat162 hh0; hh0.x = h0; hh0.y = h1;
                __nv_bfloat162 hh1; hh1.x = h2; hh1.y = h3;
                __nv_bfloat162 ll0;
                ll0.x = __float2bfloat16(o0 - __bfloat162float(h0));
                ll0.y = __float2bfloat16(o1 - __bfloat162float(h1));
                __nv_bfloat162 ll1;
                ll1.x = __float2bfloat16(o2 - __bfloat162float(h2));
                ll1.y = __float2bfloat16(o3 - __bfloat162float(h3));
                int ui = (m * D2 + n) >> 1;
                g_xlh_u[ui] = *reinterpret_cast<unsigned int*>(&hh0);
                g_xlh_u[ui + 1] = *reinterpret_cast<unsigned int*>(&hh1);
                g_xll_u[ui] = *reinterpret_cast<unsigned int*>(&ll0);
                g_xll_u[ui + 1] = *reinterpret_cast<unsigned int*>(&ll1);
            }
        }
    }
}

// ---------------- generic split-K partial GEMM -> g_cp slice -----------------
__global__ __launch_bounds__(256) void k_partial(const float* __restrict__ A,
                                                 const float* __restrict__ W,
                                                 int Ktot, int Ksub, int N) {
    __shared__ Sm2 s;
    int tid = threadIdx.x;
    int m0 = blockIdx.y * 128, n0 = blockIdx.x * 64, sp = blockIdx.z;
    const float* ApA = A + (size_t)(m0 + (tid >> 1)) * Ktot + sp * Ksub + (tid & 1) * 8;
    const float* ApB = W + (size_t)(n0 + (tid >> 2)) * Ktot + sp * Ksub + (tid & 3) * 4;
    ull acc[4][4] = {};
    gloop2(&s, ApA, ApB, Ksub / BK, true, acc, tid);
    int ty = tid >> 4, tx = tid & 15;
    int n = n0 + tx * 4;
    float* out = g_cp + (size_t)sp * PSLICE;
#pragma unroll
    for (int p = 0; p < 4; p++) {
        float2 u[4];
#pragma unroll
        for (int c = 0; c < 4; c++) u[c] = unpackf2(acc[p][c]);
#pragma unroll
        for (int half = 0; half < 2; half++) {
            int m = m0 + ty * 8 + 2 * p + half;
            *(float4*)&out[(size_t)m * N + n] = make_float4(
                half ? u[0].y : u[0].x, half ? u[1].y : u[1].x,
                half ? u[2].y : u[2].x, half ? u[3].y : u[3].x);
        }
    }
}

// ---------------- qkv on 128x64 core -----------------
__global__ __launch_bounds__(256) void k_qkv(const float* __restrict__ Wq,
                                             const float* __restrict__ Wk,
                                             const float* __restrict__ Wv) {
    __shared__ Sm2 s;
    int tid = threadIdx.x;
    int z = blockIdx.z, which = z >> 2, h = z & 3;
    const float* src = (which == 2) ? g_xleft : g_xtrans;
    const float* W = (which == 0) ? Wq : ((which == 1) ? Wk : Wv);
    float* dst = (which == 0) ? g_q : ((which == 1) ? g_k : g_v);
    float sc = (which == 1) ? SCALEF : 1.f;
    int m0 = blockIdx.y * 128, n0 = blockIdx.x * 64;
    const float* ApA = src + (size_t)(m0 + (tid >> 1)) * D2 + h * 128 + (tid & 1) * 8;
    const float* ApB = W + (size_t)h * 16384 + (size_t)(n0 + (tid >> 2)) * 128 + (tid & 3) * 4;
    ull acc[4][4] = {};
    gloop2(&s, ApA, ApB, 128 / BK, true, acc, tid);
    int ty = tid >> 4, tx = tid & 15;
    int n = h * 128 + n0 + tx * 4;
#pragma unroll
    for (int p = 0; p < 4; p++) {
        float2 u[4];
#pragma unroll
        for (int c = 0; c < 4; c++) u[c] = unpackf2(acc[p][c]);
#pragma unroll
        for (int half = 0; half < 2; half++) {
            int m = m0 + ty * 8 + 2 * p + half;
            *(float4*)&dst[(size_t)m * D2 + n] = make_float4(
                sc * (half ? u[0].y : u[0].x), sc * (half ? u[1].y : u[1].x),
                sc * (half ? u[2].y : u[2].x), sc * (half ? u[3].y : u[3].x));
        }
    }
}

// ====================  reduce / epilogue kernels  ============================
// conv-swish (slices 0..7 -> xtrans) + Wo-sigmoid (slices 8..9 -> o) fused
__global__ void k_cwepi(const float* __restrict__ cb, const float* __restrict__ bo) {
    int idx = blockIdx.x * 256 + threadIdx.x;            // float4 idx, 131072
    size_t off = (size_t)idx * 4;
    int n = (idx & 127) * 4;
    float4 sm = *(const float4*)(g_cp + off);
#pragma unroll
    for (int p = 1; p < 8; p++) {
        float4 q = *(const float4*)(g_cp + (size_t)p * PSLICE + off);
        sm.x += q.x; sm.y += q.y; sm.z += q.z; sm.w += q.w;
    }
    float4 b4 = *(const float4*)&cb[n];
    float z0 = sm.x + b4.x, z1 = sm.y + b4.y, z2 = sm.z + b4.z, z3 = sm.w + b4.w;
    *(float4*)(g_xtrans + off) = make_float4(z0 * sigm(z0), z1 * sigm(z1),
                                             z2 * sigm(z2), z3 * sigm(z3));
    float4 s0 = *(const float4*)(g_cp + 8 * (size_t)PSLICE + off);
    float4 s1 = *(const float4*)(g_cp + 9 * (size_t)PSLICE + off);
    float4 ob = *(const float4*)&bo[n];
    *(float4*)(g_o + off) = make_float4(sigm(s0.x + s1.x + ob.x), sigm(s0.y + s1.y + ob.y),
                                        sigm(s0.z + s1.z + ob.z), sigm(s0.w + s1.w + ob.w));
}

__global__ void k_sepi(const float* __restrict__ gn_g, const float* __restrict__ gn_b) {
    int idx = blockIdx.x * 256 + threadIdx.x;
    size_t off = (size_t)idx * 4;
    float4 sm = *(const float4*)(g_cp + off);
#pragma unroll
    for (int p = 1; p < 4; p++) {
        float4 q = *(const float4*)(g_cp + (size_t)p * PSLICE + off);
        sm.x += q.x; sm.y += q.y; sm.z += q.z; sm.w += q.w;
    }
    int n = (idx & 127) * 4;
    int m = idx >> 7;
    int b = m >> 8, hh = n >> 7;
    float mu = g_gnmu[b * 4 + hh], rs = g_gnrs[b * 4 + hh];
    float4 hs = *(const float4*)(g_hseq + off);
    float4 xr = *(const float4*)(g_xright + off);
    float4 gg = *(const float4*)&gn_g[n];
    float4 gb = *(const float4*)&gn_b[n];
    float sv[4] = {sm.x, sm.y, sm.z, sm.w};
    float hv[4] = {hs.x, hs.y, hs.z, hs.w};
    float xv[4] = {xr.x, xr.y, xr.z, xr.w};
    float ggv[4] = {gg.x, gg.y, gg.z, gg.w};
    float gbv[4] = {gb.x, gb.y, gb.z, gb.w};
    float ov[4];
#pragma unroll
    for (int j = 0; j < 4; j++) {
        float zn = (hv[j] - mu) * rs;
        float hg = zn * ggv[j] + gbv[j] + sv[j];
        ov[j] = hg * xv[j] * sigm(xv[j]);
    }
    *(float4*)(g_h + off) = make_float4(ov[0], ov[1], ov[2], ov[3]);
}

__global__ void k_lepi(const float* __restrict__ bl, const float* __restrict__ x,
                       float* __restrict__ out) {
    int idx = blockIdx.x * 256 + threadIdx.x;
    size_t off = (size_t)idx * 4;
    float4 sm = *(const float4*)(g_cp + off);
#pragma unroll
    for (int p = 1; p < 4; p++) {
        float4 q = *(const float4*)(g_cp + (size_t)p * PSLICE + off);
        sm.x += q.x; sm.y += q.y; sm.z += q.z; sm.w += q.w;
    }
    int n = (idx & 63) * 4;
    float4 b4 = *(const float4*)&bl[n];
    float4 xv = *(const float4*)(x + off);
    *(float4*)(out + off) = make_float4(sm.x + b4.x + xv.x, sm.y + b4.y + xv.y,
                                        sm.z + b4.z + xv.z, sm.w + b4.w + xv.w);
}

// ====================  small kernels  ============================
__global__ void k_layernorm(const float* __restrict__ x, const float* __restrict__ g,
                            const float* __restrict__ b) {
    int row = blockIdx.x, tid = threadIdx.x;
    float v = x[row * Dd + tid];
    float s = v, s2 = v * v;
#pragma unroll
    for (int o = 16; o; o >>= 1) {
        s += __shfl_xor_sync(0xffffffffu, s, o);
        s2 += __shfl_xor_sync(0xffffffffu, s2, o);
    }
    __shared__ float sh[8], sh2[8];
    int w = tid >> 5, l = tid & 31;
    if (l == 0) { sh[w] = s; sh2[w] = s2; }
    __syncthreads();
    if (tid == 0) {
        float a = 0, a2 = 0;
#pragma unroll
        for (int i = 0; i < 8; i++) { a += sh[i]; a2 += sh2[i]; }
        sh[0] = a; sh2[0] = a2;
    }
    __syncthreads();
    float mu = sh[0] * (1.f / Dd);
    float var = sh2[0] * (1.f / Dd) - mu * mu;
    float r = rsqrtf(var + 1e-5f);
    g_xnorm[row * Dd + tid] = (v - mu) * r * g[tid] + b[tid];
}

__global__ void k_ibfb(const float* __restrict__ Wi, const float* __restrict__ Wf,
                       const float* __restrict__ bi, const float* __restrict__ bf) {
    int row = blockIdx.x * 8 + (threadIdx.x >> 5);
    int l = threadIdx.x & 31;
    const float* xr = g_xleft + (size_t)row * D2;
    float si = 0, sf = 0;
#pragma unroll 4
    for (int j = l; j < D2; j += 32) {
        float v = xr[j];
        si += v * Wi[j];
        sf += v * Wf[j];
    }
#pragma unroll
    for (int o = 16; o; o >>= 1) {
        si += __shfl_xor_sync(0xffffffffu, si, o);
        sf += __shfl_xor_sync(0xffffffffu, sf, o);
    }
    if (l == 0) {
        g_ib[row] = si + bi[0];
        g_fb[row] = sf + bf[0];
        g_rowsum[row] = 0.f;
    }
}

__global__ void k_scan() {
    int b = threadIdx.x;
    if (b < Bq) {
        float m = 0.f, F = 0.f;
        for (int t = 0; t < Tt; t++) {
            float ib = g_ib[b * Tt + t], fb = g_fb[b * Tt + t];
            float mn = fmaxf(fb + m, ib);
            F += fb;
            g_alpha[b * Tt + t] = ib - F;
            g_beta[b * Tt + t] = F - mn;
            m = mn;
        }
    }
}

// =============  attention kernels (proven versions)  =================
template <int BMt, int BNt>
__device__ __forceinline__ void mma_t(const float (*As)[BMt + 4], const float (*Bs)[BNt + 4],
                                      int ty, int tx, ull acc[BMt / 32][BNt / 16]) {
    constexpr int PAIRS = BMt / 32, CN = BNt / 16;
#pragma unroll
    for (int kk = 0; kk < BK; kk++) {
        ull ap[PAIRS];
        if constexpr (PAIRS == 2) {
            ulonglong2 av = *(const ulonglong2*)&As[kk][ty * 4];
            ap[0] = av.x; ap[1] = av.y;
        } else {
            ap[0] = *(const ull*)&As[kk][ty * 2];
        }
        float bv[CN];
        if constexpr (CN == 4) {
            float4 b4 = *(const float4*)&Bs[kk][tx * 4];
            bv[0] = b4.x; bv[1] = b4.y; bv[2] = b4.z; bv[3] = b4.w;
        } else {
            float2 b2 = *(const float2*)&Bs[kk][tx * 2];
            bv[0] = b2.x; bv[1] = b2.y;
        }
#pragma unroll
        for (int j = 0; j < CN; j++) {
            ull bp = packf2(bv[j], bv[j]);
#pragma unroll
            for (int p = 0; p < PAIRS; p++) fma2(acc[p][j], ap[p], bp);
        }
    }
}

#define STS_A(BUF, AV) \
    do { As[BUF][lk + 0][lrA] = (AV).x; As[BUF][lk + 1][lrA] = (AV).y; \
         As[BUF][lk + 2][lrA] = (AV).z; As[BUF][lk + 3][lrA] = (AV).w; } while (0)
#define STS_B(BUF, WV) \
    do { Bs[BUF][lk + 0][lrB] = (WV).x; Bs[BUF][lk + 1][lrB] = (WV).y; \
         Bs[BUF][lk + 2][lrB] = (WV).z; Bs[BUF][lk + 3][lrB] = (WV).w; } while (0)

__global__ __launch_bounds__(256) void k_attn1() {
    constexpr int BMt = 32, BNt = 32;
    int m0 = blockIdx.y * BMt, n0 = blockIdx.x * BNt;
    if (n0 > m0) return;
    __shared__ __align__(16) float As[2][BK][BMt + 4];
    __shared__ __align__(16) float Bs[2][BK][BNt + 4];
    int tid = threadIdx.x;
    int z = blockIdx.z;
    int ty = tid >> 4, tx = tid & 15;
    bool doA = (tid < 128), doB = (tid >= 128);
    int lrA = tid >> 2, lrB = (tid & 127) >> 2, lk = (tid & 3) * 4;
    const float* Ap = g_q + (size_t)(z * Tt + m0 + lrA) * D2 + lk;
    const float* Wp = g_k + (size_t)(z * Tt + n0 + lrB) * D2 + lk;
    ull acc[1][2] = {};
    float4 a, w;
    if (doA) a = *(const float4*)Ap;
    if (doB) w = *(const float4*)Wp;
    if (doA) STS_A(0, a);
    if (doB) STS_B(0, w);
    __syncthreads();
    int buf = 0;
    for (int k0 = BK; k0 < D2; k0 += BK) {
        if (doA) a = *(const float4*)(Ap + k0);
        if (doB) w = *(const float4*)(Wp + k0);
        mma_t<32, 32>(As[buf], Bs[buf], ty, tx, acc);
        if (doA) STS_A(buf ^ 1, a);
        if (doB) STS_B(buf ^ 1, w);
        __syncthreads();
        buf ^= 1;
    }
    mma_t<32, 32>(As[buf], Bs[buf], ty, tx, acc);

    float2 lohi0 = unpackf2(acc[0][0]), lohi1 = unpackf2(acc[0][1]);
    float al0 = g_alpha[z * Tt + n0 + tx * 2];
    float al1 = g_alpha[z * Tt + n0 + tx * 2 + 1];
#pragma unroll
    for (int half = 0; half < 2; half++) {
        int t = m0 + ty * 2 + half;
        float be = g_beta[z * Tt + t];
        int s0 = n0 + tx * 2, s1 = s0 + 1;
        float v0 = (s0 <= t) ? __expf(al0 + be) * (half ? lohi0.y : lohi0.x) : 0.f;
        float v1 = (s1 <= t) ? __expf(al1 + be) * (half ? lohi1.y : lohi1.x) : 0.f;
        *(float2*)&g_A[(size_t)z * Tt * Tt + (size_t)t * Tt + s0] = make_float2(v0, v1);
        float p = v0 + v1;
#pragma unroll
        for (int off = 1; off < 16; off <<= 1) p += __shfl_xor_sync(0xffffffffu, p, off);
        if (tx == 0) atomicAdd(&g_rowsum[z * Tt + t], p);
    }
}

__global__ __launch_bounds__(256) void k_attn2() {
    constexpr int BMt = 32, BNt = 64;
    __shared__ __align__(16) float As[2][BK][BMt + 4];
    __shared__ __align__(16) float Bs[2][BK][BNt + 4];
    int tid = threadIdx.x;
    int z = blockIdx.z;
    int m0 = blockIdx.y * BMt, n0 = blockIdx.x * BNt;
    int ty = tid >> 4, tx = tid & 15;
    bool doA = (tid < 128);
    int lrA = tid >> 2, lk = (tid & 3) * 4;
    int brow = tid >> 4, bcol = (tid & 15) * 4;
    int Kend = m0 + BMt;
    const float* Ap = g_A + (size_t)z * Tt * Tt + (size_t)(m0 + lrA) * Tt + lk;
    const float* Vb = g_v + (size_t)z * Tt * D2;
    ull acc[1][4] = {};
    float4 a, w;
    if (doA) a = *(const float4*)Ap;
    w = *(const float4*)(Vb + (size_t)brow * D2 + n0 + bcol);
    if (doA) STS_A(0, a);
    *(float4*)&Bs[0][brow][bcol] = w;
    __syncthreads();
    int buf = 0;
    for (int k0 = BK; k0 < Kend; k0 += BK) {
        if (doA) a = *(const float4*)(Ap + k0);
        w = *(const float4*)(Vb + (size_t)(k0 + brow) * D2 + n0 + bcol);
        mma_t<32, 64>(As[buf], Bs[buf], ty, tx, acc);
        if (doA) STS_A(buf ^ 1, a);
        *(float4*)&Bs[buf ^ 1][brow][bcol] = w;
        __syncthreads();
        buf ^= 1;
    }
    mma_t<32, 64>(As[buf], Bs[buf], ty, tx, acc);

    float2 lohi[4];
#pragma unroll
    for (int j = 0; j < 4; j++) lohi[j] = unpackf2(acc[0][j]);
#pragma unroll
    for (int half = 0; half < 2; half++) {
        int m = m0 + ty * 2 + half;
        int r = z * Tt + m;
        float rs = g_rowsum[r];
        float inv = 1.f / (fmaxf(fabsf(rs), 1.f) + 1e-8f);
        float4 og = *(const float4*)&g_o[(size_t)r * D2 + n0 + tx * 4];
        float4 ov = make_float4((half ? lohi[0].y : lohi[0].x) * inv * og.x,
                                (half ? lohi[1].y : lohi[1].x) * inv * og.y,
                                (half ? lohi[2].y : lohi[2].x) * inv * og.z,
                                (half ? lohi[3].y : lohi[3].x) * inv * og.w);
        *(float4*)&g_hseq[(size_t)r * D2 + n0 + tx * 4] = ov;
    }
}

__global__ void k_gnstats() {
    int bh = blockIdx.x;
    int b = bh >> 2, h = bh & 3;
    int tid = threadIdx.x;
    float s = 0, s2 = 0;
    const float* base = g_hseq + (size_t)(b * Tt) * D2 + h * 128;
    for (int i = tid; i < Tt * 128; i += 256) {
        int t = i >> 7, d = i & 127;
        float v = base[(size_t)t * D2 + d];
        s += v; s2 += v * v;
    }
#pragma unroll
    for (int o = 16; o; o >>= 1) {
        s += __shfl_xor_sync(0xffffffffu, s, o);
        s2 += __shfl_xor_sync(0xffffffffu, s2, o);
    }
    __shared__ float sh[8], sh2[8];
    int w = tid >> 5, l = tid & 31;
    if (l == 0) { sh[w] = s; sh2[w] = s2; }
    __syncthreads();
    if (tid == 0) {
        float a = 0, a2 = 0;
#pragma unroll
        for (int i = 0; i < 8; i++) { a += sh[i]; a2 += sh2[i]; }
        float mu = a * (1.f / (Tt * 128));
        float var = a2 * (1.f / (Tt * 128)) - mu * mu;
        g_gnmu[bh] = mu;
        g_gnrs[bh] = rsqrtf(var + 1e-5f);
    }
}

// ---------------- launch ----------------
extern "C" void kernel_launch(void* const* d_in, const int* in_sizes, int n_in,
                              void* d_out, int out_size) {
    const float* x       = (const float*)d_in[0];
    const float* ln_g    = (const float*)d_in[1];
    const float* ln_b    = (const float*)d_in[2];
    const float* W_left  = (const float*)d_in[3];
    const float* b_left  = (const float*)d_in[4];
    const float* W_right = (const float*)d_in[5];
    const float* b_right = (const float*)d_in[6];
    const float* Wi      = (const float*)d_in[7];
    const float* bi      = (const float*)d_in[8];
    const float* Wf      = (const float*)d_in[9];
    const float* bf      = (const float*)d_in[10];
    const float* Wo      = (const float*)d_in[11];
    const float* bo      = (const float*)d_in[12];
    const float* Wq      = (const float*)d_in[13];
    const float* Wk      = (const float*)d_in[14];
    const float* Wv      = (const float*)d_in[15];
    const float* conv_w  = (const float*)d_in[16];
    const float* conv_b  = (const float*)d_in[17];
    const float* skip_W  = (const float*)d_in[18];
    const float* gn_g    = (const float*)d_in[19];
    const float* gn_b    = (const float*)d_in[20];
    const float* W_last  = (const float*)d_in[21];
    const float* b_last  = (const float*)d_in[22];
    float* out = (float*)d_out;

    float *p_xnorm, *p_xleft, *p_xright, *p_xtrans, *p_h;
    cudaGetSymbolAddress((void**)&p_xnorm, g_xnorm);
    cudaGetSymbolAddress((void**)&p_xleft, g_xleft);
    cudaGetSymbolAddress((void**)&p_xright, g_xright);
    cudaGetSymbolAddress((void**)&p_xtrans, g_xtrans);
    cudaGetSymbolAddress((void**)&p_h, g_h);

    k_layernorm<<<BT, 256>>>(x, ln_g, ln_b);
    k_cvtw<<<1024, 256>>>(conv_w);
    k_cvtwo<<<256, 256>>>(Wo);
    k_projdual<<<dim3(8, 8, 2), 256>>>(p_xnorm, W_left, b_left, p_xleft,
                                       W_right, b_right, p_xright, 256);
    k_cwo<<<dim3(8, 8, 10), 256>>>();
    k_cwepi<<<512, 256>>>(conv_b, bo);
    k_ibfb<<<128, 256>>>(Wi, Wf, bi, bf);
    k_scan<<<1, 32>>>();
    k_qkv<<<dim3(2, 8, 12), 256>>>(Wq, Wk, Wv);
    k_attn1<<<dim3(8, 8, 4), 256>>>();
    k_attn2<<<dim3(8, 8, 4), 256>>>();
    k_gnstats<<<16, 256>>>();
    k_partial<<<dim3(8, 8, 4), 256>>>(p_xtrans, skip_W, 512, 128, 512);
    k_sepi<<<512, 256>>>(gn_g, gn_b);
    k_partial<<<dim3(4, 8, 4), 256>>>(p_h, W_last, 512, 128, 256);
    k_lepi<<<256, 256>>>(b_last, x, out);
}

// round 13
// speedup vs baseline: 1.6848x; 1.0670x over previous
#include <cuda_runtime.h>
#include <cuda_bf16.h>
#include <math.h>

typedef unsigned long long ull;
typedef unsigned int uint;

// Problem constants
#define Bq 4
#define Tt 256
#define Dd 256
#define D2 512
#define BT 1024
#define SCALEF 0.0625f
#define BK 16

// ---------------- scratch (static device globals; no allocation) -------------
__device__ float g_xleft[BT * D2];
__device__ float g_xright[BT * D2];
__device__ float g_o[BT * D2];
__device__ float g_q[BT * D2];
__device__ float g_k[BT * D2];
__device__ float g_v[BT * D2];
__device__ float g_hseq[BT * D2];
__device__ float g_cp[10 * BT * D2];
__device__ float g_A[Bq * Tt * Tt];
__device__ float g_ib[BT];
__device__ float g_fb[BT];
__device__ float g_alpha[BT];
__device__ float g_beta[BT];
__device__ float g_rowsum[BT];
__device__ float g_gnmu[16];
__device__ float g_gnrs[16];

// bf16 hi/lo tensors (packed uint pairs; low 16 bits = even column)
__device__ __align__(16) uint g_xnh_u[BT * Dd / 2];
__device__ __align__(16) uint g_xnl_u[BT * Dd / 2];
__device__ __align__(16) uint g_xlh_u[BT * D2 / 2];
__device__ __align__(16) uint g_xll_u[BT * D2 / 2];
__device__ __align__(16) uint g_xth_u[BT * D2 / 2];
__device__ __align__(16) uint g_xtl_u[BT * D2 / 2];
__device__ __align__(16) uint g_hh_u[BT * D2 / 2];
__device__ __align__(16) uint g_hl_u[BT * D2 / 2];
__device__ __align__(16) uint g_cwh_u[4 * D2 * D2 / 2];
__device__ __align__(16) uint g_cwl_u[4 * D2 * D2 / 2];
__device__ __align__(16) uint g_woh_u[D2 * D2 / 2];
__device__ __align__(16) uint g_wol_u[D2 * D2 / 2];

// packed weight hi/lo pool (uint pair-index offsets)
#define OFF_WL 0
#define OFF_WR 65536
#define OFF_WQ 131072
#define OFF_WK 163840
#define OFF_WV 196608
#define OFF_SK 229376
#define OFF_LA 360448
#define WT_TOTAL 425984
__device__ __align__(16) uint g_wt_h[WT_TOTAL];
__device__ __align__(16) uint g_wt_l[WT_TOTAL];

#define PSLICE (BT * D2)

__device__ __forceinline__ float sigm(float x) { return 1.f / (1.f + __expf(-x)); }

// ---------------- packed f32x2 helpers (for SIMT attn kernels) ---------------
__device__ __forceinline__ ull packf2(float lo, float hi) {
    ull r; asm("mov.b64 %0, {%1, %2};" : "=l"(r) : "f"(lo), "f"(hi)); return r;
}
__device__ __forceinline__ void fma2(ull& d, ull a, ull b) {
    asm("fma.rn.f32x2 %0, %1, %2, %0;" : "+l"(d) : "l"(a), "l"(b));
}
__device__ __forceinline__ float2 unpackf2(ull v) {
    float2 f; asm("mov.b64 {%0, %1}, %2;" : "=f"(f.x), "=f"(f.y) : "l"(v)); return f;
}

// ---------------- HMMA helpers ----------------
__device__ __forceinline__ uint smem_u32(const void* p) {
    uint a;
    asm("{ .reg .u64 t; cvta.to.shared.u64 t, %1; cvt.u32.u64 %0, t; }" : "=r"(a) : "l"(p));
    return a;
}
__device__ __forceinline__ void mma_bf16(float (&c)[4], const uint (&a)[4],
                                         uint b0, uint b1) {
    asm volatile(
        "mma.sync.aligned.m16n8k16.row.col.f32.bf16.bf16.f32 "
        "{%0,%1,%2,%3}, {%4,%5,%6,%7}, {%8,%9}, {%0,%1,%2,%3};"
        : "+f"(c[0]), "+f"(c[1]), "+f"(c[2]), "+f"(c[3])
        : "r"(a[0]), "r"(a[1]), "r"(a[2]), "r"(a[3]), "r"(b0), "r"(b1));
}
__device__ __forceinline__ void ldm4(uint* r, uint a) {
    asm volatile("ldmatrix.sync.aligned.m8n8.x4.shared.b16 {%0,%1,%2,%3}, [%4];"
                 : "=r"(r[0]), "=r"(r[1]), "=r"(r[2]), "=r"(r[3]) : "r"(a));
}
__device__ __forceinline__ void emit_pair(uint* H, uint* L, size_t uidx, float v0, float v1) {
    __nv_bfloat16 h0 = __float2bfloat16(v0), h1 = __float2bfloat16(v1);
    __nv_bfloat162 hh; hh.x = h0; hh.y = h1;
    __nv_bfloat162 ll;
    ll.x = __float2bfloat16(v0 - __bfloat162float(h0));
    ll.y = __float2bfloat16(v1 - __bfloat162float(h1));
    H[uidx] = *reinterpret_cast<uint*>(&hh);
    L[uidx] = *reinterpret_cast<uint*>(&ll);
}

// shared tile: A 128x32bf16 hi/lo, B 64x32bf16 hi/lo, row pad 20 uints
struct HS {
    __align__(16) uint Ah[128][20];
    __align__(16) uint Al[128][20];
    __align__(16) uint Bh[64][20];
    __align__(16) uint Bl[64][20];
};

#define HMMA_ADDR_SETUP()                                                            \
    uint bAh_ = smem_u32(s.Ah), bAl_ = smem_u32(s.Al);                               \
    uint bBh_ = smem_u32(s.Bh), bBl_ = smem_u32(s.Bl);                               \
    int rowAf = (lane & 7) + ((lane >> 3) & 1) * 8, colAf = (lane >> 4) * 4;         \
    int rowBf = (lane & 7) + ((lane >> 4) & 1) * 8, colBf = ((lane >> 3) & 1) * 4;   \
    uint aA0 = bAh_ + (uint)(((warpM * 32 + rowAf) * 20 + colAf) * 4);               \
    uint aA1 = aA0 + 16 * 20 * 4;                                                    \
    uint aL0 = bAl_ + (uint)(((warpM * 32 + rowAf) * 20 + colAf) * 4);               \
    uint aL1 = aL0 + 16 * 20 * 4;                                                    \
    uint aB0 = bBh_ + (uint)(((warpN * 32 + rowBf) * 20 + colBf) * 4);               \
    uint aB1 = aB0 + 16 * 20 * 4;                                                    \
    uint aC0 = bBl_ + (uint)(((warpN * 32 + rowBf) * 20 + colBf) * 4);               \
    uint aC1 = aC0 + 16 * 20 * 4;

#define HMMA_STORE_SMEM()                                                            \
    *(uint4*)&s.Ah[rA][jA] = fah0; *(uint4*)&s.Ah[rA][jA + 4] = fah1;                \
    *(uint4*)&s.Al[rA][jA] = fal0; *(uint4*)&s.Al[rA][jA + 4] = fal1;                \
    *(uint4*)&s.Bh[nB][jB] = fbh;  *(uint4*)&s.Bl[nB][jB] = fbl;

#define HMMA_TILE_COMPUTE()                                                          \
    _Pragma("unroll")                                                                \
    for (int half = 0; half < 2; half++) {                                           \
        uint koff = (uint)(half * 8 * 4);                                            \
        uint ah[2][4], al[2][4], bh[8], bl[8];                                       \
        ldm4(ah[0], aA0 + koff); ldm4(ah[1], aA1 + koff);                            \
        ldm4(al[0], aL0 + koff); ldm4(al[1], aL1 + koff);                            \
        ldm4(&bh[0], aB0 + koff); ldm4(&bh[4], aB1 + koff);                          \
        ldm4(&bl[0], aC0 + koff); ldm4(&bl[4], aC1 + koff);                          \
        _Pragma("unroll")                                                            \
        for (int nt = 0; nt < 4; nt++) {                                             \
            uint h0 = bh[nt * 2], h1 = bh[nt * 2 + 1];                               \
            uint l0 = bl[nt * 2], l1 = bl[nt * 2 + 1];                               \
            _Pragma("unroll")                                                        \
            for (int mt = 0; mt < 2; mt++) {                                         \
                mma_bf16(acc[mt][nt], ah[mt], h0, h1);                               \
                mma_bf16(acc[mt][nt], ah[mt], l0, l1);                               \
                mma_bf16(acc[mt][nt], al[mt], h0, h1);                               \
            }                                                                        \
        }                                                                            \
    }

// =====  conv (z<8) + Wo (z=8,9) -> g_cp partial slices  =====================
__global__ __launch_bounds__(256) void k_cwo() {
    __shared__ HS s;
    int tid = threadIdx.x, lane = tid & 31, w = tid >> 5;
    int warpM = w >> 1, warpN = w & 1;
    int z = blockIdx.z;
    int m0 = blockIdx.y * 128, n0 = blockIdx.x * 64;
    int rA = tid >> 1, jA = (tid & 1) * 8;
    int nB = tid >> 2, jB = (tid & 3) * 4;
    size_t arow; bool valid = true; int cbase;
    const uint *whp, *wlp;
    if (z < 8) {
        int tau = z >> 1, kh = z & 1;
        int row = m0 + rA, b = row >> 8, t = row & 255;
        int tp = t - 3 + tau;
        valid = (tp >= 0);
        arow = (size_t)(b * Tt + (valid ? tp : 0)) * 256;
        cbase = kh * 128;
        whp = g_cwh_u + (size_t)tau * 131072;
        wlp = g_cwl_u + (size_t)tau * 131072;
    } else {
        int sp = z - 8;
        arow = (size_t)(m0 + rA) * 256;
        cbase = sp * 128;
        whp = g_woh_u;
        wlp = g_wol_u;
    }
    const uint* pAh = g_xlh_u + arow + cbase + jA;
    const uint* pAl = g_xll_u + arow + cbase + jA;
    const uint* pBh = whp + (size_t)(n0 + nB) * 256 + cbase + jB;
    const uint* pBl = wlp + (size_t)(n0 + nB) * 256 + cbase + jB;
    float acc[2][4][4] = {};
    uint4 z4 = make_uint4(0u, 0u, 0u, 0u);
    uint4 fah0 = valid ? *(const uint4*)pAh : z4;
    uint4 fah1 = valid ? *(const uint4*)(pAh + 4) : z4;
    uint4 fal0 = valid ? *(const uint4*)pAl : z4;
    uint4 fal1 = valid ? *(const uint4*)(pAl + 4) : z4;
    uint4 fbh = *(const uint4*)pBh, fbl = *(const uint4*)pBl;
    HMMA_ADDR_SETUP();
    for (int it = 0; it < 8; it++) {
        HMMA_STORE_SMEM();
        __syncthreads();
        if (it + 1 < 8) {
            int cb = (it + 1) * 16;
            fah0 = valid ? *(const uint4*)(pAh + cb) : z4;
            fah1 = valid ? *(const uint4*)(pAh + cb + 4) : z4;
            fal0 = valid ? *(const uint4*)(pAl + cb) : z4;
            fal1 = valid ? *(const uint4*)(pAl + cb + 4) : z4;
            fbh = *(const uint4*)(pBh + cb);
            fbl = *(const uint4*)(pBl + cb);
        }
        HMMA_TILE_COMPUTE();
        __syncthreads();
    }
    int g = lane >> 2, tig = lane & 3;
    float* out = g_cp + (size_t)z * PSLICE;
#pragma unroll
    for (int mt = 0; mt < 2; mt++)
#pragma unroll
        for (int nt = 0; nt < 4; nt++) {
            int r = m0 + warpM * 32 + mt * 16 + g;
            int c = n0 + warpN * 32 + nt * 8 + tig * 2;
            *(float2*)&out[(size_t)r * D2 + c] = make_float2(acc[mt][nt][0], acc[mt][nt][1]);
            *(float2*)&out[(size_t)(r + 8) * D2 + c] = make_float2(acc[mt][nt][2], acc[mt][nt][3]);
        }
}

// =====  generic HMMA GEMM with fused epilogues  ==============================
// epi 0: projdual (z=0: +bias -> C, emit xleft hi/lo; z=1: +bias -> C2)
// epi 2: skip GEMM + groupnorm/swish epilogue -> emit h hi/lo
// epi 3: last GEMM: +bias +resid -> C
__global__ __launch_bounds__(256) void k_hgemm(
    const uint* __restrict__ Ah, const uint* __restrict__ Al, int Astr,
    const uint* __restrict__ Wh, const uint* __restrict__ Wl, int Wstr,
    int iters, const float* __restrict__ bias, float* __restrict__ C, int Cstr,
    int epi,
    const uint* __restrict__ W2h, const uint* __restrict__ W2l,
    const float* __restrict__ bias2, float* __restrict__ C2,
    const float* __restrict__ resid) {
    __shared__ HS s;
    int tid = threadIdx.x, lane = tid & 31, w = tid >> 5;
    int warpM = w >> 1, warpN = w & 1;
    int m0 = blockIdx.y * 128, n0 = blockIdx.x * 64;
    bool second = (blockIdx.z == 1);
    if (second) { Wh = W2h; Wl = W2l; bias = bias2; C = C2; }
    int rA = tid >> 1, jA = (tid & 1) * 8;
    int nB = tid >> 2, jB = (tid & 3) * 4;
    const uint* pAh = Ah + (size_t)(m0 + rA) * Astr + jA;
    const uint* pAl = Al + (size_t)(m0 + rA) * Astr + jA;
    const uint* pBh = Wh + (size_t)(n0 + nB) * Wstr + jB;
    const uint* pBl = Wl + (size_t)(n0 + nB) * Wstr + jB;
    float acc[2][4][4] = {};
    uint4 fah0 = *(const uint4*)pAh, fah1 = *(const uint4*)(pAh + 4);
    uint4 fal0 = *(const uint4*)pAl, fal1 = *(const uint4*)(pAl + 4);
    uint4 fbh = *(const uint4*)pBh, fbl = *(const uint4*)pBl;
    HMMA_ADDR_SETUP();
    for (int it = 0; it < iters; it++) {
        HMMA_STORE_SMEM();
        __syncthreads();
        if (it + 1 < iters) {
            int cb = (it + 1) * 16;
            fah0 = *(const uint4*)(pAh + cb);
            fah1 = *(const uint4*)(pAh + cb + 4);
            fal0 = *(const uint4*)(pAl + cb);
            fal1 = *(const uint4*)(pAl + cb + 4);
            fbh = *(const uint4*)(pBh + cb);
            fbl = *(const uint4*)(pBl + cb);
        }
        HMMA_TILE_COMPUTE();
        __syncthreads();
    }
    int g = lane >> 2, tig = lane & 3;
#pragma unroll
    for (int mt = 0; mt < 2; mt++)
#pragma unroll
        for (int nt = 0; nt < 4; nt++) {
            int r = m0 + warpM * 32 + mt * 16 + g;
            int c = n0 + warpN * 32 + nt * 8 + tig * 2;
            float b0v = bias[c], b1v = bias[c + 1];
            if (epi == 0) {
                float o00 = acc[mt][nt][0] + b0v, o01 = acc[mt][nt][1] + b1v;
                float o10 = acc[mt][nt][2] + b0v, o11 = acc[mt][nt][3] + b1v;
                *(float2*)&C[(size_t)r * Cstr + c] = make_float2(o00, o01);
                *(float2*)&C[(size_t)(r + 8) * Cstr + c] = make_float2(o10, o11);
                if (!second) {
                    emit_pair(g_xlh_u, g_xll_u, ((size_t)r * D2 + c) >> 1, o00, o01);
                    emit_pair(g_xlh_u, g_xll_u, ((size_t)(r + 8) * D2 + c) >> 1, o10, o11);
                }
            } else if (epi == 2) {
                int b = r >> 8, hh = c >> 7;
                float mu = g_gnmu[b * 4 + hh], rs = g_gnrs[b * 4 + hh];
                float g2v = bias2[c], g3v = bias2[c + 1];
#pragma unroll
                for (int hrow = 0; hrow < 2; hrow++) {
                    int rr = r + hrow * 8;
                    float a0 = acc[mt][nt][hrow * 2], a1 = acc[mt][nt][hrow * 2 + 1];
                    float hs0 = g_hseq[(size_t)rr * D2 + c], hs1 = g_hseq[(size_t)rr * D2 + c + 1];
                    float xr0 = g_xright[(size_t)rr * D2 + c], xr1 = g_xright[(size_t)rr * D2 + c + 1];
                    float h0v = ((hs0 - mu) * rs) * b0v + g2v + a0;
                    float h1v = ((hs1 - mu) * rs) * b1v + g3v + a1;
                    h0v = h0v * xr0 * sigm(xr0);
                    h1v = h1v * xr1 * sigm(xr1);
                    emit_pair(g_hh_u, g_hl_u, ((size_t)rr * D2 + c) >> 1, h0v, h1v);
                }
            } else {
                float o00 = acc[mt][nt][0] + b0v + resid[(size_t)r * Cstr + c];
                float o01 = acc[mt][nt][1] + b1v + resid[(size_t)r * Cstr + c + 1];
                float o10 = acc[mt][nt][2] + b0v + resid[(size_t)(r + 8) * Cstr + c];
                float o11 = acc[mt][nt][3] + b1v + resid[(size_t)(r + 8) * Cstr + c + 1];
                *(float2*)&C[(size_t)r * Cstr + c] = make_float2(o00, o01);
                *(float2*)&C[(size_t)(r + 8) * Cstr + c] = make_float2(o10, o11);
            }
        }
}

// =====  q/k/v block-diagonal projections on the HMMA core  ===================
__global__ __launch_bounds__(256) void k_hqkv() {
    __shared__ HS s;
    int tid = threadIdx.x, lane = tid & 31, w = tid >> 5;
    int warpM = w >> 1, warpN = w & 1;
    int z = blockIdx.z, which = z >> 2, h = z & 3;
    int m0 = blockIdx.y * 128, n0 = blockIdx.x * 64;
    const uint* Ahp = (which == 2) ? g_xlh_u : g_xth_u;
    const uint* Alp = (which == 2) ? g_xll_u : g_xtl_u;
    size_t woff = (which == 0) ? OFF_WQ : ((which == 1) ? OFF_WK : OFF_WV);
    const uint* Whp = g_wt_h + woff + (size_t)h * 8192;
    const uint* Wlp = g_wt_l + woff + (size_t)h * 8192;
    float* dst = (which == 0) ? g_q : ((which == 1) ? g_k : g_v);
    float sc = (which == 1) ? SCALEF : 1.f;
    int rA = tid >> 1, jA = (tid & 1) * 8;
    int nB = tid >> 2, jB = (tid & 3) * 4;
    const uint* pAh = Ahp + (size_t)(m0 + rA) * 256 + h * 64 + jA;
    const uint* pAl = Alp + (size_t)(m0 + rA) * 256 + h * 64 + jA;
    const uint* pBh = Whp + (size_t)(n0 + nB) * 64 + jB;
    const uint* pBl = Wlp + (size_t)(n0 + nB) * 64 + jB;
    float acc[2][4][4] = {};
    uint4 fah0 = *(const uint4*)pAh, fah1 = *(const uint4*)(pAh + 4);
    uint4 fal0 = *(const uint4*)pAl, fal1 = *(const uint4*)(pAl + 4);
    uint4 fbh = *(const uint4*)pBh, fbl = *(const uint4*)pBl;
    HMMA_ADDR_SETUP();
    for (int it = 0; it < 4; it++) {
        HMMA_STORE_SMEM();
        __syncthreads();
        if (it + 1 < 4) {
            int cb = (it + 1) * 16;
            fah0 = *(const uint4*)(pAh + cb);
            fah1 = *(const uint4*)(pAh + cb + 4);
            fal0 = *(const uint4*)(pAl + cb);
            fal1 = *(const uint4*)(pAl + cb + 4);
            fbh = *(const uint4*)(pBh + cb);
            fbl = *(const uint4*)(pBl + cb);
        }
        HMMA_TILE_COMPUTE();
        __syncthreads();
    }
    int g = lane >> 2, tig = lane & 3;
#pragma unroll
    for (int mt = 0; mt < 2; mt++)
#pragma unroll
        for (int nt = 0; nt < 4; nt++) {
            int r = m0 + warpM * 32 + mt * 16 + g;
            int c = h * 128 + n0 + warpN * 32 + nt * 8 + tig * 2;
            *(float2*)&dst[(size_t)r * D2 + c] =
                make_float2(sc * acc[mt][nt][0], sc * acc[mt][nt][1]);
            *(float2*)&dst[(size_t)(r + 8) * D2 + c] =
                make_float2(sc * acc[mt][nt][2], sc * acc[mt][nt][3]);
        }
}

// ------------- bf16 hi/lo conversion kernels -------------
__global__ void k_cvtw(const float* __restrict__ cw) {
    int idx = blockIdx.x * 256 + threadIdx.x;
    float4 w = *(const float4*)(cw + (size_t)idx * 4);
    __nv_bfloat16* H = (__nv_bfloat16*)g_cwh_u;
    __nv_bfloat16* L = (__nv_bfloat16*)g_cwl_u;
    float v[4] = {w.x, w.y, w.z, w.w};
#pragma unroll
    for (int tau = 0; tau < 4; tau++) {
        __nv_bfloat16 h = __float2bfloat16(v[tau]);
        H[tau * 262144 + idx] = h;
        L[tau * 262144 + idx] = __float2bfloat16(v[tau] - __bfloat162float(h));
    }
}
__global__ void k_cvtwo(const float* __restrict__ Wo) {
    int idx = blockIdx.x * 256 + threadIdx.x;
    float2 w = *(const float2*)(Wo + (size_t)idx * 2);
    emit_pair(g_woh_u, g_wol_u, idx, w.x, w.y);
}
__global__ void k_cvt7(const float* __restrict__ wl, const float* __restrict__ wr,
                       const float* __restrict__ wq, const float* __restrict__ wk,
                       const float* __restrict__ wv, const float* __restrict__ sk,
                       const float* __restrict__ la) {
    int i = blockIdx.x * 256 + threadIdx.x;
    if (i >= WT_TOTAL) return;
    const float* sp; int base;
    if (i < 65536)       { sp = wl; base = i; }
    else if (i < 131072) { sp = wr; base = i - 65536; }
    else if (i < 163840) { sp = wq; base = i - 131072; }
    else if (i < 196608) { sp = wk; base = i - 163840; }
    else if (i < 229376) { sp = wv; base = i - 196608; }
    else if (i < 360448) { sp = sk; base = i - 229376; }
    else                 { sp = la; base = i - 360448; }
    float2 v = *(const float2*)&sp[(size_t)base * 2];
    emit_pair(g_wt_h, g_wt_l, i, v.x, v.y);
}

// ====================  small kernels  ============================
__global__ void k_layernorm(const float* __restrict__ x, const float* __restrict__ g,
                            const float* __restrict__ b) {
    int row = blockIdx.x, tid = threadIdx.x;
    float v = x[row * Dd + tid];
    float s = v, s2 = v * v;
#pragma unroll
    for (int o = 16; o; o >>= 1) {
        s += __shfl_xor_sync(0xffffffffu, s, o);
        s2 += __shfl_xor_sync(0xffffffffu, s2, o);
    }
    __shared__ float sh[8], sh2[8];
    int w = tid >> 5, l = tid & 31;
    if (l == 0) { sh[w] = s; sh2[w] = s2; }
    __syncthreads();
    if (tid == 0) {
        float a = 0, a2 = 0;
#pragma unroll
        for (int i = 0; i < 8; i++) { a += sh[i]; a2 += sh2[i]; }
        sh[0] = a; sh2[0] = a2;
    }
    __syncthreads();
    float mu = sh[0] * (1.f / Dd);
    float var = sh2[0] * (1.f / Dd) - mu * mu;
    float r = rsqrtf(var + 1e-5f);
    float y = (v - mu) * r * g[tid] + b[tid];
    __nv_bfloat16 hb = __float2bfloat16(y);
    ((__nv_bfloat16*)g_xnh_u)[row * Dd + tid] = hb;
    ((__nv_bfloat16*)g_xnl_u)[row * Dd + tid] = __float2bfloat16(y - __bfloat162float(hb));
}

// conv-swish (slices 0..7 -> xtrans hi/lo) + Wo-sigmoid (8..9 -> o)
__global__ void k_cwepi(const float* __restrict__ cb, const float* __restrict__ bo) {
    int idx = blockIdx.x * 256 + threadIdx.x;
    size_t off = (size_t)idx * 4;
    int n = (idx & 127) * 4;
    float4 sm = *(const float4*)(g_cp + off);
#pragma unroll
    for (int p = 1; p < 8; p++) {
        float4 q = *(const float4*)(g_cp + (size_t)p * PSLICE + off);
        sm.x += q.x; sm.y += q.y; sm.z += q.z; sm.w += q.w;
    }
    float4 b4 = *(const float4*)&cb[n];
    float z0 = sm.x + b4.x, z1 = sm.y + b4.y, z2 = sm.z + b4.z, z3 = sm.w + b4.w;
    float t0 = z0 * sigm(z0), t1 = z1 * sigm(z1), t2 = z2 * sigm(z2), t3 = z3 * sigm(z3);
    emit_pair(g_xth_u, g_xtl_u, off >> 1, t0, t1);
    emit_pair(g_xth_u, g_xtl_u, (off >> 1) + 1, t2, t3);
    float4 s0 = *(const float4*)(g_cp + 8 * (size_t)PSLICE + off);
    float4 s1 = *(const float4*)(g_cp + 9 * (size_t)PSLICE + off);
    float4 ob = *(const float4*)&bo[n];
    *(float4*)(g_o + off) = make_float4(sigm(s0.x + s1.x + ob.x), sigm(s0.y + s1.y + ob.y),
                                        sigm(s0.z + s1.z + ob.z), sigm(s0.w + s1.w + ob.w));
}

__global__ void k_ibfb(const float* __restrict__ Wi, const float* __restrict__ Wf,
                       const float* __restrict__ bi, const float* __restrict__ bf) {
    int row = blockIdx.x * 8 + (threadIdx.x >> 5);
    int l = threadIdx.x & 31;
    const float* xr = g_xleft + (size_t)row * D2;
    float si = 0, sf = 0;
#pragma unroll 4
    for (int j = l; j < D2; j += 32) {
        float v = xr[j];
        si += v * Wi[j];
        sf += v * Wf[j];
    }
#pragma unroll
    for (int o = 16; o; o >>= 1) {
        si += __shfl_xor_sync(0xffffffffu, si, o);
        sf += __shfl_xor_sync(0xffffffffu, sf, o);
    }
    if (l == 0) {
        g_ib[row] = si + bi[0];
        g_fb[row] = sf + bf[0];
        g_rowsum[row] = 0.f;
    }
}

__global__ void k_scan() {
    int b = threadIdx.x;
    if (b < Bq) {
        float m = 0.f, F = 0.f;
        for (int t = 0; t < Tt; t++) {
            float ib = g_ib[b * Tt + t], fb = g_fb[b * Tt + t];
            float mn = fmaxf(fb + m, ib);
            F += fb;
            g_alpha[b * Tt + t] = ib - F;
            g_beta[b * Tt + t] = F - mn;
            m = mn;
        }
    }
}

// =============  attention kernels (proven SIMT fp32 versions)  ===============
template <int BMt, int BNt>
__device__ __forceinline__ void mma_t(const float (*As)[BMt + 4], const float (*Bs)[BNt + 4],
                                      int ty, int tx, ull acc[BMt / 32][BNt / 16]) {
    constexpr int PAIRS = BMt / 32, CN = BNt / 16;
#pragma unroll
    for (int kk = 0; kk < BK; kk++) {
        ull ap[PAIRS];
        if constexpr (PAIRS == 2) {
            ulonglong2 av = *(const ulonglong2*)&As[kk][ty * 4];
            ap[0] = av.x; ap[1] = av.y;
        } else {
            ap[0] = *(const ull*)&As[kk][ty * 2];
        }
        float bv[CN];
        if constexpr (CN == 4) {
            float4 b4 = *(const float4*)&Bs[kk][tx * 4];
            bv[0] = b4.x; bv[1] = b4.y; bv[2] = b4.z; bv[3] = b4.w;
        } else {
            float2 b2 = *(const float2*)&Bs[kk][tx * 2];
            bv[0] = b2.x; bv[1] = b2.y;
        }
#pragma unroll
        for (int j = 0; j < CN; j++) {
            ull bp = packf2(bv[j], bv[j]);
#pragma unroll
            for (int p = 0; p < PAIRS; p++) fma2(acc[p][j], ap[p], bp);
        }
    }
}

#define STS_A(BUF, AV) \
    do { As[BUF][lk + 0][lrA] = (AV).x; As[BUF][lk + 1][lrA] = (AV).y; \
         As[BUF][lk + 2][lrA] = (AV).z; As[BUF][lk + 3][lrA] = (AV).w; } while (0)
#define STS_B(BUF, WV) \
    do { Bs[BUF][lk + 0][lrB] = (WV).x; Bs[BUF][lk + 1][lrB] = (WV).y; \
         Bs[BUF][lk + 2][lrB] = (WV).z; Bs[BUF][lk + 3][lrB] = (WV).w; } while (0)

__global__ __launch_bounds__(256) void k_attn1() {
    constexpr int BMt = 32, BNt = 32;
    int m0 = blockIdx.y * BMt, n0 = blockIdx.x * BNt;
    if (n0 > m0) return;
    __shared__ __align__(16) float As[2][BK][BMt + 4];
    __shared__ __align__(16) float Bs[2][BK][BNt + 4];
    int tid = threadIdx.x;
    int z = blockIdx.z;
    int ty = tid >> 4, tx = tid & 15;
    bool doA = (tid < 128), doB = (tid >= 128);
    int lrA = tid >> 2, lrB = (tid & 127) >> 2, lk = (tid & 3) * 4;
    const float* Ap = g_q + (size_t)(z * Tt + m0 + lrA) * D2 + lk;
    const float* Wp = g_k + (size_t)(z * Tt + n0 + lrB) * D2 + lk;
    ull acc[1][2] = {};
    float4 a, w;
    if (doA) a = *(const float4*)Ap;
    if (doB) w = *(const float4*)Wp;
    if (doA) STS_A(0, a);
    if (doB) STS_B(0, w);
    __syncthreads();
    int buf = 0;
    for (int k0 = BK; k0 < D2; k0 += BK) {
        if (doA) a = *(const float4*)(Ap + k0);
        if (doB) w = *(const float4*)(Wp + k0);
        mma_t<32, 32>(As[buf], Bs[buf], ty, tx, acc);
        if (doA) STS_A(buf ^ 1, a);
        if (doB) STS_B(buf ^ 1, w);
        __syncthreads();
        buf ^= 1;
    }
    mma_t<32, 32>(As[buf], Bs[buf], ty, tx, acc);

    float2 lohi0 = unpackf2(acc[0][0]), lohi1 = unpackf2(acc[0][1]);
    float al0 = g_alpha[z * Tt + n0 + tx * 2];
    float al1 = g_alpha[z * Tt + n0 + tx * 2 + 1];
#pragma unroll
    for (int half = 0; half < 2; half++) {
        int t = m0 + ty * 2 + half;
        float be = g_beta[z * Tt + t];
        int s0 = n0 + tx * 2, s1 = s0 + 1;
        float v0 = (s0 <= t) ? __expf(al0 + be) * (half ? lohi0.y : lohi0.x) : 0.f;
        float v1 = (s1 <= t) ? __expf(al1 + be) * (half ? lohi1.y : lohi1.x) : 0.f;
        *(float2*)&g_A[(size_t)z * Tt * Tt + (size_t)t * Tt + s0] = make_float2(v0, v1);
        float p = v0 + v1;
#pragma unroll
        for (int off = 1; off < 16; off <<= 1) p += __shfl_xor_sync(0xffffffffu, p, off);
        if (tx == 0) atomicAdd(&g_rowsum[z * Tt + t], p);
    }
}

__global__ __launch_bounds__(256) void k_attn2() {
    constexpr int BMt = 32, BNt = 64;
    __shared__ __align__(16) float As[2][BK][BMt + 4];
    __shared__ __align__(16) float Bs[2][BK][BNt + 4];
    int tid = threadIdx.x;
    int z = blockIdx.z;
    int m0 = blockIdx.y * BMt, n0 = blockIdx.x * BNt;
    int ty = tid >> 4, tx = tid & 15;
    bool doA = (tid < 128);
    int lrA = tid >> 2, lk = (tid & 3) * 4;
    int brow = tid >> 4, bcol = (tid & 15) * 4;
    int Kend = m0 + BMt;
    const float* Ap = g_A + (size_t)z * Tt * Tt + (size_t)(m0 + lrA) * Tt + lk;
    const float* Vb = g_v + (size_t)z * Tt * D2;
    ull acc[1][4] = {};
    float4 a, w;
    if (doA) a = *(const float4*)Ap;
    w = *(const float4*)(Vb + (size_t)brow * D2 + n0 + bcol);
    if (doA) STS_A(0, a);
    *(float4*)&Bs[0][brow][bcol] = w;
    __syncthreads();
    int buf = 0;
    for (int k0 = BK; k0 < Kend; k0 += BK) {
        if (doA) a = *(const float4*)(Ap + k0);
        w = *(const float4*)(Vb + (size_t)(k0 + brow) * D2 + n0 + bcol);
        mma_t<32, 64>(As[buf], Bs[buf], ty, tx, acc);
        if (doA) STS_A(buf ^ 1, a);
        *(float4*)&Bs[buf ^ 1][brow][bcol] = w;
        __syncthreads();
        buf ^= 1;
    }
    mma_t<32, 64>(As[buf], Bs[buf], ty, tx, acc);

    float2 lohi[4];
#pragma unroll
    for (int j = 0; j < 4; j++) lohi[j] = unpackf2(acc[0][j]);
#pragma unroll
    for (int half = 0; half < 2; half++) {
        int m = m0 + ty * 2 + half;
        int r = z * Tt + m;
        float rs = g_rowsum[r];
        float inv = 1.f / (fmaxf(fabsf(rs), 1.f) + 1e-8f);
        float4 og = *(const float4*)&g_o[(size_t)r * D2 + n0 + tx * 4];
        float4 ov = make_float4((half ? lohi[0].y : lohi[0].x) * inv * og.x,
                                (half ? lohi[1].y : lohi[1].x) * inv * og.y,
                                (half ? lohi[2].y : lohi[2].x) * inv * og.z,
                                (half ? lohi[3].y : lohi[3].x) * inv * og.w);
        *(float4*)&g_hseq[(size_t)r * D2 + n0 + tx * 4] = ov;
    }
}

__global__ void k_gnstats() {
    int bh = blockIdx.x;
    int b = bh >> 2, h = bh & 3;
    int tid = threadIdx.x;
    float s = 0, s2 = 0;
    const float* base = g_hseq + (size_t)(b * Tt) * D2 + h * 128;
    for (int i = tid; i < Tt * 128; i += 256) {
        int t = i >> 7, d = i & 127;
        float v = base[(size_t)t * D2 + d];
        s += v; s2 += v * v;
    }
#pragma unroll
    for (int o = 16; o; o >>= 1) {
        s += __shfl_xor_sync(0xffffffffu, s, o);
        s2 += __shfl_xor_sync(0xffffffffu, s2, o);
    }
    __shared__ float sh[8], sh2[8];
    int w = tid >> 5, l = tid & 31;
    if (l == 0) { sh[w] = s; sh2[w] = s2; }
    __syncthreads();
    if (tid == 0) {
        float a = 0, a2 = 0;
#pragma unroll
        for (int i = 0; i < 8; i++) { a += sh[i]; a2 += sh2[i]; }
        float mu = a * (1.f / (Tt * 128));
        float var = a2 * (1.f / (Tt * 128)) - mu * mu;
        g_gnmu[bh] = mu;
        g_gnrs[bh] = rsqrtf(var + 1e-5f);
    }
}

// ---------------- launch ----------------
extern "C" void kernel_launch(void* const* d_in, const int* in_sizes, int n_in,
                              void* d_out, int out_size) {
    const float* x       = (const float*)d_in[0];
    const float* ln_g    = (const float*)d_in[1];
    const float* ln_b    = (const float*)d_in[2];
    const float* W_left  = (const float*)d_in[3];
    const float* b_left  = (const float*)d_in[4];
    const float* W_right = (const float*)d_in[5];
    const float* b_right = (const float*)d_in[6];
    const float* Wi      = (const float*)d_in[7];
    const float* bi      = (const float*)d_in[8];
    const float* Wf      = (const float*)d_in[9];
    const float* bf      = (const float*)d_in[10];
    const float* Wo      = (const float*)d_in[11];
    const float* bo      = (const float*)d_in[12];
    const float* Wq      = (const float*)d_in[13];
    const float* Wk      = (const float*)d_in[14];
    const float* Wv      = (const float*)d_in[15];
    const float* conv_w  = (const float*)d_in[16];
    const float* conv_b  = (const float*)d_in[17];
    const float* skip_W  = (const float*)d_in[18];
    const float* gn_g    = (const float*)d_in[19];
    const float* gn_b    = (const float*)d_in[20];
    const float* W_last  = (const float*)d_in[21];
    const float* b_last  = (const float*)d_in[22];
    float* out = (float*)d_out;

    float *p_xleft, *p_xright;
    uint *p_xnh, *p_xnl, *p_wth, *p_wtl, *p_xth, *p_xtl, *p_hh, *p_hl;
    cudaGetSymbolAddress((void**)&p_xleft, g_xleft);
    cudaGetSymbolAddress((void**)&p_xright, g_xright);
    cudaGetSymbolAddress((void**)&p_xnh, g_xnh_u);
    cudaGetSymbolAddress((void**)&p_xnl, g_xnl_u);
    cudaGetSymbolAddress((void**)&p_wth, g_wt_h);
    cudaGetSymbolAddress((void**)&p_wtl, g_wt_l);
    cudaGetSymbolAddress((void**)&p_xth, g_xth_u);
    cudaGetSymbolAddress((void**)&p_xtl, g_xtl_u);
    cudaGetSymbolAddress((void**)&p_hh, g_hh_u);
    cudaGetSymbolAddress((void**)&p_hl, g_hl_u);

    k_layernorm<<<BT, 256>>>(x, ln_g, ln_b);
    k_cvtw<<<1024, 256>>>(conv_w);
    k_cvtwo<<<512, 256>>>(Wo);
    k_cvt7<<<1664, 256>>>(W_left, W_right, Wq, Wk, Wv, skip_W, W_last);
    // left/right projections (emit xleft hi/lo on z=0)
    k_hgemm<<<dim3(8, 8, 2), 256>>>(p_xnh, p_xnl, 128,
                                    p_wth + OFF_WL, p_wtl + OFF_WL, 128,
                                    8, b_left, p_xleft, 512, 0,
                                    p_wth + OFF_WR, p_wtl + OFF_WR, b_right, p_xright,
                                    nullptr);
    k_cwo<<<dim3(8, 8, 10), 256>>>();
    k_cwepi<<<512, 256>>>(conv_b, bo);
    k_ibfb<<<128, 256>>>(Wi, Wf, bi, bf);
    k_scan<<<1, 32>>>();
    k_hqkv<<<dim3(2, 8, 12), 256>>>();
    k_attn1<<<dim3(8, 8, 4), 256>>>();
    k_attn2<<<dim3(8, 8, 4), 256>>>();
    k_gnstats<<<16, 256>>>();
    // skip GEMM + fused groupnorm/swish epilogue (emits h hi/lo)
    k_hgemm<<<dim3(8, 8, 1), 256>>>(p_xth, p_xtl, 256,
                                    p_wth + OFF_SK, p_wtl + OFF_SK, 256,
                                    16, gn_g, nullptr, 512, 2,
                                    nullptr, nullptr, gn_b, nullptr, nullptr);
    // last GEMM + bias + residual
    k_hgemm<<<dim3(4, 8, 1), 256>>>(p_hh, p_hl, 256,
                                    p_wth + OFF_LA, p_wtl + OFF_LA, 256,
                                    16, b_last, out, 256, 3,
                                    nullptr, nullptr, nullptr, nullptr, x);
}

// round 15
// speedup vs baseline: 1.8419x; 1.0932x over previous
#include <cuda_runtime.h>
#include <cuda_bf16.h>
#include <math.h>

typedef unsigned long long ull;
typedef unsigned int uint;

// Problem constants
#define Bq 4
#define Tt 256
#define Dd 256
#define D2 512
#define BT 1024
#define SCALEF 0.0625f
#define BK 16

// ---------------- scratch (static device globals; no allocation) -------------
__device__ float g_xleft[BT * D2];
__device__ float g_xright[BT * D2];
__device__ float g_o[BT * D2];
__device__ float g_q[BT * D2];
__device__ float g_k[BT * D2];
__device__ float g_v[BT * D2];
__device__ float g_hseq[BT * D2];
__device__ float g_cp[10 * BT * D2];
__device__ float g_A[Bq * Tt * Tt];
__device__ float g_ib[BT];
__device__ float g_fb[BT];
__device__ float g_alpha[BT];
__device__ float g_beta[BT];
__device__ float g_rowsum[BT];
__device__ float g_gnsum[16];
__device__ float g_gnsum2[16];

// bf16 hi/lo tensors (packed uint pairs; low 16 bits = even column)
__device__ __align__(16) uint g_xnh_u[BT * Dd / 2];
__device__ __align__(16) uint g_xnl_u[BT * Dd / 2];
__device__ __align__(16) uint g_xlh_u[BT * D2 / 2];
__device__ __align__(16) uint g_xll_u[BT * D2 / 2];
__device__ __align__(16) uint g_xth_u[BT * D2 / 2];
__device__ __align__(16) uint g_xtl_u[BT * D2 / 2];
__device__ __align__(16) uint g_hh_u[BT * D2 / 2];
__device__ __align__(16) uint g_hl_u[BT * D2 / 2];
__device__ __align__(16) uint g_cwh_u[4 * D2 * D2 / 2];
__device__ __align__(16) uint g_cwl_u[4 * D2 * D2 / 2];
__device__ __align__(16) uint g_woh_u[D2 * D2 / 2];
__device__ __align__(16) uint g_wol_u[D2 * D2 / 2];

// packed weight hi/lo pool (uint pair-index offsets)
#define OFF_WL 0
#define OFF_WR 65536
#define OFF_WQ 131072
#define OFF_WK 163840
#define OFF_WV 196608
#define OFF_SK 229376
#define OFF_LA 360448
#define WT_TOTAL 425984
__device__ __align__(16) uint g_wt_h[WT_TOTAL];
__device__ __align__(16) uint g_wt_l[WT_TOTAL];

#define PSLICE (BT * D2)

__device__ __forceinline__ float sigm(float x) { return 1.f / (1.f + __expf(-x)); }

// ---------------- packed f32x2 helpers (for SIMT attn kernels) ---------------
__device__ __forceinline__ ull packf2(float lo, float hi) {
    ull r; asm("mov.b64 %0, {%1, %2};" : "=l"(r) : "f"(lo), "f"(hi)); return r;
}
__device__ __forceinline__ void fma2(ull& d, ull a, ull b) {
    asm("fma.rn.f32x2 %0, %1, %2, %0;" : "+l"(d) : "l"(a), "l"(b));
}
__device__ __forceinline__ float2 unpackf2(ull v) {
    float2 f; asm("mov.b64 {%0, %1}, %2;" : "=f"(f.x), "=f"(f.y) : "l"(v)); return f;
}

// ---------------- HMMA helpers ----------------
__device__ __forceinline__ uint smem_u32(const void* p) {
    uint a;
    asm("{ .reg .u64 t; cvta.to.shared.u64 t, %1; cvt.u32.u64 %0, t; }" : "=r"(a) : "l"(p));
    return a;
}
__device__ __forceinline__ void mma_bf16(float (&c)[4], const uint (&a)[4],
                                         uint b0, uint b1) {
    asm volatile(
        "mma.sync.aligned.m16n8k16.row.col.f32.bf16.bf16.f32 "
        "{%0,%1,%2,%3}, {%4,%5,%6,%7}, {%8,%9}, {%0,%1,%2,%3};"
        : "+f"(c[0]), "+f"(c[1]), "+f"(c[2]), "+f"(c[3])
        : "r"(a[0]), "r"(a[1]), "r"(a[2]), "r"(a[3]), "r"(b0), "r"(b1));
}
__device__ __forceinline__ void ldm4(uint* r, uint a) {
    asm volatile("ldmatrix.sync.aligned.m8n8.x4.shared.b16 {%0,%1,%2,%3}, [%4];"
                 : "=r"(r[0]), "=r"(r[1]), "=r"(r[2]), "=r"(r[3]) : "r"(a));
}
__device__ __forceinline__ void emit_pair(uint* H, uint* L, size_t uidx, float v0, float v1) {
    __nv_bfloat16 h0 = __float2bfloat16(v0), h1 = __float2bfloat16(v1);
    __nv_bfloat162 hh; hh.x = h0; hh.y = h1;
    __nv_bfloat162 ll;
    ll.x = __float2bfloat16(v0 - __bfloat162float(h0));
    ll.y = __float2bfloat16(v1 - __bfloat162float(h1));
    H[uidx] = *reinterpret_cast<uint*>(&hh);
    L[uidx] = *reinterpret_cast<uint*>(&ll);
}

// shared tile: A 128x32bf16 hi/lo, B 64x32bf16 hi/lo, row pad 20 uints
struct HS {
    __align__(16) uint Ah[128][20];
    __align__(16) uint Al[128][20];
    __align__(16) uint Bh[64][20];
    __align__(16) uint Bl[64][20];
};

#define HMMA_ADDR_SETUP()                                                            \
    uint bAh_ = smem_u32(s.Ah), bAl_ = smem_u32(s.Al);                               \
    uint bBh_ = smem_u32(s.Bh), bBl_ = smem_u32(s.Bl);                               \
    int rowAf = (lane & 7) + ((lane >> 3) & 1) * 8, colAf = (lane >> 4) * 4;         \
    int rowBf = (lane & 7) + ((lane >> 4) & 1) * 8, colBf = ((lane >> 3) & 1) * 4;   \
    uint aA0 = bAh_ + (uint)(((warpM * 32 + rowAf) * 20 + colAf) * 4);               \
    uint aA1 = aA0 + 16 * 20 * 4;                                                    \
    uint aL0 = bAl_ + (uint)(((warpM * 32 + rowAf) * 20 + colAf) * 4);               \
    uint aL1 = aL0 + 16 * 20 * 4;                                                    \
    uint aB0 = bBh_ + (uint)(((warpN * 32 + rowBf) * 20 + colBf) * 4);               \
    uint aB1 = aB0 + 16 * 20 * 4;                                                    \
    uint aC0 = bBl_ + (uint)(((warpN * 32 + rowBf) * 20 + colBf) * 4);               \
    uint aC1 = aC0 + 16 * 20 * 4;

#define HMMA_STORE_SMEM()                                                            \
    *(uint4*)&s.Ah[rA][jA] = fah0; *(uint4*)&s.Ah[rA][jA + 4] = fah1;                \
    *(uint4*)&s.Al[rA][jA] = fal0; *(uint4*)&s.Al[rA][jA + 4] = fal1;                \
    *(uint4*)&s.Bh[nB][jB] = fbh;  *(uint4*)&s.Bl[nB][jB] = fbl;

#define HMMA_TILE_COMPUTE()                                                          \
    _Pragma("unroll")                                                                \
    for (int half = 0; half < 2; half++) {                                           \
        uint koff = (uint)(half * 8 * 4);                                            \
        uint ah[2][4], al[2][4], bh[8], bl[8];                                       \
        ldm4(ah[0], aA0 + koff); ldm4(ah[1], aA1 + koff);                            \
        ldm4(al[0], aL0 + koff); ldm4(al[1], aL1 + koff);                            \
        ldm4(&bh[0], aB0 + koff); ldm4(&bh[4], aB1 + koff);                          \
        ldm4(&bl[0], aC0 + koff); ldm4(&bl[4], aC1 + koff);                          \
        _Pragma("unroll")                                                            \
        for (int nt = 0; nt < 4; nt++) {                                             \
            uint h0 = bh[nt * 2], h1 = bh[nt * 2 + 1];                               \
            uint l0 = bl[nt * 2], l1 = bl[nt * 2 + 1];                               \
            _Pragma("unroll")                                                        \
            for (int mt = 0; mt < 2; mt++) {                                         \
                mma_bf16(acc[mt][nt], ah[mt], h0, h1);                               \
                mma_bf16(acc[mt][nt], ah[mt], l0, l1);                               \
                mma_bf16(acc[mt][nt], al[mt], h0, h1);                               \
            }                                                                        \
        }                                                                            \
    }

// =====  fused pre-pass: layernorm + all weight hi/lo converts  ===============
// blocks [0,1024): layernorm; [1024,2048): conv_w; [2048,2560): Wo;
// blocks [2560,4224): 7-weight pool convert
__global__ __launch_bounds__(256) void k_pre(
    const float* __restrict__ x, const float* __restrict__ ln_g,
    const float* __restrict__ ln_b, const float* __restrict__ cw,
    const float* __restrict__ Wo, const float* __restrict__ wl,
    const float* __restrict__ wr, const float* __restrict__ wq,
    const float* __restrict__ wk, const float* __restrict__ wv,
    const float* __restrict__ sk, const float* __restrict__ la) {
    int bx = blockIdx.x, tid = threadIdx.x;
    if (bx < 1024) {
        int row = bx;
        float v = x[row * Dd + tid];
        float s = v, s2 = v * v;
#pragma unroll
        for (int o = 16; o; o >>= 1) {
            s += __shfl_xor_sync(0xffffffffu, s, o);
            s2 += __shfl_xor_sync(0xffffffffu, s2, o);
        }
        __shared__ float sh[8], sh2[8];
        int w = tid >> 5, l = tid & 31;
        if (l == 0) { sh[w] = s; sh2[w] = s2; }
        __syncthreads();
        if (tid == 0) {
            float a = 0, a2 = 0;
#pragma unroll
            for (int i = 0; i < 8; i++) { a += sh[i]; a2 += sh2[i]; }
            sh[0] = a; sh2[0] = a2;
        }
        __syncthreads();
        float mu = sh[0] * (1.f / Dd);
        float var = sh2[0] * (1.f / Dd) - mu * mu;
        float r = rsqrtf(var + 1e-5f);
        float y = (v - mu) * r * ln_g[tid] + ln_b[tid];
        __nv_bfloat16 hb = __float2bfloat16(y);
        ((__nv_bfloat16*)g_xnh_u)[row * Dd + tid] = hb;
        ((__nv_bfloat16*)g_xnl_u)[row * Dd + tid] = __float2bfloat16(y - __bfloat162float(hb));
    } else if (bx < 2048) {
        int idx = (bx - 1024) * 256 + tid;
        float4 w = *(const float4*)(cw + (size_t)idx * 4);
        __nv_bfloat16* H = (__nv_bfloat16*)g_cwh_u;
        __nv_bfloat16* L = (__nv_bfloat16*)g_cwl_u;
        float v[4] = {w.x, w.y, w.z, w.w};
#pragma unroll
        for (int tau = 0; tau < 4; tau++) {
            __nv_bfloat16 h = __float2bfloat16(v[tau]);
            H[tau * 262144 + idx] = h;
            L[tau * 262144 + idx] = __float2bfloat16(v[tau] - __bfloat162float(h));
        }
    } else if (bx < 2560) {
        int idx = (bx - 2048) * 256 + tid;
        float2 w = *(const float2*)(Wo + (size_t)idx * 2);
        emit_pair(g_woh_u, g_wol_u, idx, w.x, w.y);
    } else {
        int i = (bx - 2560) * 256 + tid;
        if (i >= WT_TOTAL) return;
        const float* sp; int base;
        if (i < 65536)       { sp = wl; base = i; }
        else if (i < 131072) { sp = wr; base = i - 65536; }
        else if (i < 163840) { sp = wq; base = i - 131072; }
        else if (i < 196608) { sp = wk; base = i - 163840; }
        else if (i < 229376) { sp = wv; base = i - 196608; }
        else if (i < 360448) { sp = sk; base = i - 229376; }
        else                 { sp = la; base = i - 360448; }
        float2 v = *(const float2*)&sp[(size_t)base * 2];
        emit_pair(g_wt_h, g_wt_l, i, v.x, v.y);
    }
}

// =====  conv (z<8) + Wo (z=8,9) -> g_cp; z=10: ibfb GEMV + accum zeroing =====
__global__ __launch_bounds__(256) void k_cwo(const float* __restrict__ Wi,
                                             const float* __restrict__ Wf,
                                             const float* __restrict__ bi,
                                             const float* __restrict__ bf) {
    int tid = threadIdx.x;
    int z = blockIdx.z;
    if (z == 10) {
        int wid = tid >> 5, l = tid & 31;
        int blk = blockIdx.y * 8 + blockIdx.x;   // 0..63
        if (tid < 16) g_rowsum[blk * 16 + tid] = 0.f;
        if (blk == 0 && tid < 16) { g_gnsum[tid] = 0.f; g_gnsum2[tid] = 0.f; }
#pragma unroll
        for (int rr = 0; rr < 2; rr++) {
            int row = blk * 16 + wid * 2 + rr;
            const float* xr = g_xleft + (size_t)row * D2;
            float si = 0, sf = 0;
#pragma unroll 4
            for (int j = l; j < D2; j += 32) {
                float v = xr[j];
                si += v * Wi[j];
                sf += v * Wf[j];
            }
#pragma unroll
            for (int o = 16; o; o >>= 1) {
                si += __shfl_xor_sync(0xffffffffu, si, o);
                sf += __shfl_xor_sync(0xffffffffu, sf, o);
            }
            if (l == 0) {
                g_ib[row] = si + bi[0];
                g_fb[row] = sf + bf[0];
            }
        }
        return;
    }
    __shared__ HS s;
    int lane = tid & 31, w = tid >> 5;
    int warpM = w >> 1, warpN = w & 1;
    int m0 = blockIdx.y * 128, n0 = blockIdx.x * 64;
    int rA = tid >> 1, jA = (tid & 1) * 8;
    int nB = tid >> 2, jB = (tid & 3) * 4;
    size_t arow; bool valid = true; int cbase;
    const uint *whp, *wlp;
    if (z < 8) {
        int tau = z >> 1, kh = z & 1;
        int row = m0 + rA, b = row >> 8, t = row & 255;
        int tp = t - 3 + tau;
        valid = (tp >= 0);
        arow = (size_t)(b * Tt + (valid ? tp : 0)) * 256;
        cbase = kh * 128;
        whp = g_cwh_u + (size_t)tau * 131072;
        wlp = g_cwl_u + (size_t)tau * 131072;
    } else {
        int sp = z - 8;
        arow = (size_t)(m0 + rA) * 256;
        cbase = sp * 128;
        whp = g_woh_u;
        wlp = g_wol_u;
    }
    const uint* pAh = g_xlh_u + arow + cbase + jA;
    const uint* pAl = g_xll_u + arow + cbase + jA;
    const uint* pBh = whp + (size_t)(n0 + nB) * 256 + cbase + jB;
    const uint* pBl = wlp + (size_t)(n0 + nB) * 256 + cbase + jB;
    float acc[2][4][4] = {};
    uint4 z4 = make_uint4(0u, 0u, 0u, 0u);
    uint4 fah0 = valid ? *(const uint4*)pAh : z4;
    uint4 fah1 = valid ? *(const uint4*)(pAh + 4) : z4;
    uint4 fal0 = valid ? *(const uint4*)pAl : z4;
    uint4 fal1 = valid ? *(const uint4*)(pAl + 4) : z4;
    uint4 fbh = *(const uint4*)pBh, fbl = *(const uint4*)pBl;
    HMMA_ADDR_SETUP();
    for (int it = 0; it < 8; it++) {
        HMMA_STORE_SMEM();
        __syncthreads();
        if (it + 1 < 8) {
            int cb = (it + 1) * 16;
            fah0 = valid ? *(const uint4*)(pAh + cb) : z4;
            fah1 = valid ? *(const uint4*)(pAh + cb + 4) : z4;
            fal0 = valid ? *(const uint4*)(pAl + cb) : z4;
            fal1 = valid ? *(const uint4*)(pAl + cb + 4) : z4;
            fbh = *(const uint4*)(pBh + cb);
            fbl = *(const uint4*)(pBl + cb);
        }
        HMMA_TILE_COMPUTE();
        __syncthreads();
    }
    int g = lane >> 2, tig = lane & 3;
    float* out = g_cp + (size_t)z * PSLICE;
#pragma unroll
    for (int mt = 0; mt < 2; mt++)
#pragma unroll
        for (int nt = 0; nt < 4; nt++) {
            int r = m0 + warpM * 32 + mt * 16 + g;
            int c = n0 + warpN * 32 + nt * 8 + tig * 2;
            *(float2*)&out[(size_t)r * D2 + c] = make_float2(acc[mt][nt][0], acc[mt][nt][1]);
            *(float2*)&out[(size_t)(r + 8) * D2 + c] = make_float2(acc[mt][nt][2], acc[mt][nt][3]);
        }
}

// =====  generic HMMA GEMM with fused epilogues  ==============================
// epi 0: projdual (z=0: +bias -> C, emit xleft hi/lo; z=1: +bias -> C2)
// epi 2: skip GEMM + groupnorm/swish epilogue (stats from g_gnsum) -> h hi/lo
// epi 3: last GEMM: +bias +resid -> C
__global__ __launch_bounds__(256) void k_hgemm(
    const uint* __restrict__ Ah, const uint* __restrict__ Al, int Astr,
    const uint* __restrict__ Wh, const uint* __restrict__ Wl, int Wstr,
    int iters, const float* __restrict__ bias, float* __restrict__ C, int Cstr,
    int epi,
    const uint* __restrict__ W2h, const uint* __restrict__ W2l,
    const float* __restrict__ bias2, float* __restrict__ C2,
    const float* __restrict__ resid) {
    __shared__ HS s;
    int tid = threadIdx.x, lane = tid & 31, w = tid >> 5;
    int warpM = w >> 1, warpN = w & 1;
    int m0 = blockIdx.y * 128, n0 = blockIdx.x * 64;
    bool second = (blockIdx.z == 1);
    if (second) { Wh = W2h; Wl = W2l; bias = bias2; C = C2; }
    int rA = tid >> 1, jA = (tid & 1) * 8;
    int nB = tid >> 2, jB = (tid & 3) * 4;
    const uint* pAh = Ah + (size_t)(m0 + rA) * Astr + jA;
    const uint* pAl = Al + (size_t)(m0 + rA) * Astr + jA;
    const uint* pBh = Wh + (size_t)(n0 + nB) * Wstr + jB;
    const uint* pBl = Wl + (size_t)(n0 + nB) * Wstr + jB;
    float acc[2][4][4] = {};
    uint4 fah0 = *(const uint4*)pAh, fah1 = *(const uint4*)(pAh + 4);
    uint4 fal0 = *(const uint4*)pAl, fal1 = *(const uint4*)(pAl + 4);
    uint4 fbh = *(const uint4*)pBh, fbl = *(const uint4*)pBl;
    HMMA_ADDR_SETUP();
    for (int it = 0; it < iters; it++) {
        HMMA_STORE_SMEM();
        __syncthreads();
        if (it + 1 < iters) {
            int cb = (it + 1) * 16;
            fah0 = *(const uint4*)(pAh + cb);
            fah1 = *(const uint4*)(pAh + cb + 4);
            fal0 = *(const uint4*)(pAl + cb);
            fal1 = *(const uint4*)(pAl + cb + 4);
            fbh = *(const uint4*)(pBh + cb);
            fbl = *(const uint4*)(pBl + cb);
        }
        HMMA_TILE_COMPUTE();
        __syncthreads();
    }
    int g = lane >> 2, tig = lane & 3;
#pragma unroll
    for (int mt = 0; mt < 2; mt++)
#pragma unroll
        for (int nt = 0; nt < 4; nt++) {
            int r = m0 + warpM * 32 + mt * 16 + g;
            int c = n0 + warpN * 32 + nt * 8 + tig * 2;
            float b0v = bias[c], b1v = bias[c + 1];
            if (epi == 0) {
                float o00 = acc[mt][nt][0] + b0v, o01 = acc[mt][nt][1] + b1v;
                float o10 = acc[mt][nt][2] + b0v, o11 = acc[mt][nt][3] + b1v;
                *(float2*)&C[(size_t)r * Cstr + c] = make_float2(o00, o01);
                *(float2*)&C[(size_t)(r + 8) * Cstr + c] = make_float2(o10, o11);
                if (!second) {
                    emit_pair(g_xlh_u, g_xll_u, ((size_t)r * D2 + c) >> 1, o00, o01);
                    emit_pair(g_xlh_u, g_xll_u, ((size_t)(r + 8) * D2 + c) >> 1, o10, o11);
                }
            } else if (epi == 2) {
                int b = r >> 8, hh = c >> 7;
                float sm = g_gnsum[b * 4 + hh], sm2 = g_gnsum2[b * 4 + hh];
                float mu = sm * (1.f / 32768.f);
                float var = sm2 * (1.f / 32768.f) - mu * mu;
                float rs = rsqrtf(var + 1e-5f);
                float g2v = bias2[c], g3v = bias2[c + 1];
#pragma unroll
                for (int hrow = 0; hrow < 2; hrow++) {
                    int rr = r + hrow * 8;
                    float a0 = acc[mt][nt][hrow * 2], a1 = acc[mt][nt][hrow * 2 + 1];
                    float hs0 = g_hseq[(size_t)rr * D2 + c], hs1 = g_hseq[(size_t)rr * D2 + c + 1];
                    float xr0 = g_xright[(size_t)rr * D2 + c], xr1 = g_xright[(size_t)rr * D2 + c + 1];
                    float h0v = ((hs0 - mu) * rs) * b0v + g2v + a0;
                    float h1v = ((hs1 - mu) * rs) * b1v + g3v + a1;
                    h0v = h0v * xr0 * sigm(xr0);
                    h1v = h1v * xr1 * sigm(xr1);
                    emit_pair(g_hh_u, g_hl_u, ((size_t)rr * D2 + c) >> 1, h0v, h1v);
                }
            } else {
                float o00 = acc[mt][nt][0] + b0v + resid[(size_t)r * Cstr + c];
                float o01 = acc[mt][nt][1] + b1v + resid[(size_t)r * Cstr + c + 1];
                float o10 = acc[mt][nt][2] + b0v + resid[(size_t)(r + 8) * Cstr + c];
                float o11 = acc[mt][nt][3] + b1v + resid[(size_t)(r + 8) * Cstr + c + 1];
                *(float2*)&C[(size_t)r * Cstr + c] = make_float2(o00, o01);
                *(float2*)&C[(size_t)(r + 8) * Cstr + c] = make_float2(o10, o11);
            }
        }
}

// =====  q/k/v block-diagonal projections on the HMMA core  ===================
__global__ __launch_bounds__(256) void k_hqkv() {
    __shared__ HS s;
    int tid = threadIdx.x, lane = tid & 31, w = tid >> 5;
    int warpM = w >> 1, warpN = w & 1;
    int z = blockIdx.z, which = z >> 2, h = z & 3;
    int m0 = blockIdx.y * 128, n0 = blockIdx.x * 64;
    const uint* Ahp = (which == 2) ? g_xlh_u : g_xth_u;
    const uint* Alp = (which == 2) ? g_xll_u : g_xtl_u;
    size_t woff = (which == 0) ? OFF_WQ : ((which == 1) ? OFF_WK : OFF_WV);
    const uint* Whp = g_wt_h + woff + (size_t)h * 8192;
    const uint* Wlp = g_wt_l + woff + (size_t)h * 8192;
    float* dst = (which == 0) ? g_q : ((which == 1) ? g_k : g_v);
    float sc = (which == 1) ? SCALEF : 1.f;
    int rA = tid >> 1, jA = (tid & 1) * 8;
    int nB = tid >> 2, jB = (tid & 3) * 4;
    const uint* pAh = Ahp + (size_t)(m0 + rA) * 256 + h * 64 + jA;
    const uint* pAl = Alp + (size_t)(m0 + rA) * 256 + h * 64 + jA;
    const uint* pBh = Whp + (size_t)(n0 + nB) * 64 + jB;
    const uint* pBl = Wlp + (size_t)(n0 + nB) * 64 + jB;
    float acc[2][4][4] = {};
    uint4 fah0 = *(const uint4*)pAh, fah1 = *(const uint4*)(pAh + 4);
    uint4 fal0 = *(const uint4*)pAl, fal1 = *(const uint4*)(pAl + 4);
    uint4 fbh = *(const uint4*)pBh, fbl = *(const uint4*)pBl;
    HMMA_ADDR_SETUP();
    for (int it = 0; it < 4; it++) {
        HMMA_STORE_SMEM();
        __syncthreads();
        if (it + 1 < 4) {
            int cb = (it + 1) * 16;
            fah0 = *(const uint4*)(pAh + cb);
            fah1 = *(const uint4*)(pAh + cb + 4);
            fal0 = *(const uint4*)(pAl + cb);
            fal1 = *(const uint4*)(pAl + cb + 4);
            fbh = *(const uint4*)(pBh + cb);
            fbl = *(const uint4*)(pBl + cb);
        }
        HMMA_TILE_COMPUTE();
        __syncthreads();
    }
    int g = lane >> 2, tig = lane & 3;
#pragma unroll
    for (int mt = 0; mt < 2; mt++)
#pragma unroll
        for (int nt = 0; nt < 4; nt++) {
            int r = m0 + warpM * 32 + mt * 16 + g;
            int c = h * 128 + n0 + warpN * 32 + nt * 8 + tig * 2;
            *(float2*)&dst[(size_t)r * D2 + c] =
                make_float2(sc * acc[mt][nt][0], sc * acc[mt][nt][1]);
            *(float2*)&dst[(size_t)(r + 8) * D2 + c] =
                make_float2(sc * acc[mt][nt][2], sc * acc[mt][nt][3]);
        }
}

// ====================  conv epilogue + gate scan  ============================
__global__ void k_cwepi(const float* __restrict__ cb, const float* __restrict__ bo) {
    if (blockIdx.x == 512) {   // gate scan block
        int b = threadIdx.x;
        if (b < Bq) {
            float m = 0.f, F = 0.f;
            for (int t = 0; t < Tt; t++) {
                float ib = g_ib[b * Tt + t], fb = g_fb[b * Tt + t];
                float mn = fmaxf(fb + m, ib);
                F += fb;
                g_alpha[b * Tt + t] = ib - F;
                g_beta[b * Tt + t] = F - mn;
                m = mn;
            }
        }
        return;
    }
    int idx = blockIdx.x * 256 + threadIdx.x;
    size_t off = (size_t)idx * 4;
    int n = (idx & 127) * 4;
    float4 sm = *(const float4*)(g_cp + off);
#pragma unroll
    for (int p = 1; p < 8; p++) {
        float4 q = *(const float4*)(g_cp + (size_t)p * PSLICE + off);
        sm.x += q.x; sm.y += q.y; sm.z += q.z; sm.w += q.w;
    }
    float4 b4 = *(const float4*)&cb[n];
    float z0 = sm.x + b4.x, z1 = sm.y + b4.y, z2 = sm.z + b4.z, z3 = sm.w + b4.w;
    float t0 = z0 * sigm(z0), t1 = z1 * sigm(z1), t2 = z2 * sigm(z2), t3 = z3 * sigm(z3);
    emit_pair(g_xth_u, g_xtl_u, off >> 1, t0, t1);
    emit_pair(g_xth_u, g_xtl_u, (off >> 1) + 1, t2, t3);
    float4 s0 = *(const float4*)(g_cp + 8 * (size_t)PSLICE + off);
    float4 s1 = *(const float4*)(g_cp + 9 * (size_t)PSLICE + off);
    float4 ob = *(const float4*)&bo[n];
    *(float4*)(g_o + off) = make_float4(sigm(s0.x + s1.x + ob.x), sigm(s0.y + s1.y + ob.y),
                                        sigm(s0.z + s1.z + ob.z), sigm(s0.w + s1.w + ob.w));
}

// =============  attention kernels  ===============
template <int BMt, int BNt>
__device__ __forceinline__ void mma_t(const float (*As)[BMt + 4], const float (*Bs)[BNt + 4],
                                      int ty, int tx, ull acc[BMt / 32][BNt / 16]) {
    constexpr int PAIRS = BMt / 32, CN = BNt / 16;
#pragma unroll
    for (int kk = 0; kk < BK; kk++) {
        ull ap[PAIRS];
        if constexpr (PAIRS == 2) {
            ulonglong2 av = *(const ulonglong2*)&As[kk][ty * 4];
            ap[0] = av.x; ap[1] = av.y;
        } else {
            ap[0] = *(const ull*)&As[kk][ty * 2];
        }
        float bv[CN];
        if constexpr (CN == 4) {
            float4 b4 = *(const float4*)&Bs[kk][tx * 4];
            bv[0] = b4.x; bv[1] = b4.y; bv[2] = b4.z; bv[3] = b4.w;
        } else {
            float2 b2 = *(const float2*)&Bs[kk][tx * 2];
            bv[0] = b2.x; bv[1] = b2.y;
        }
#pragma unroll
        for (int j = 0; j < CN; j++) {
            ull bp = packf2(bv[j], bv[j]);
#pragma unroll
            for (int p = 0; p < PAIRS; p++) fma2(acc[p][j], ap[p], bp);
        }
    }
}

#define STS_A(BUF, AV) \
    do { As[BUF][lk + 0][lrA] = (AV).x; As[BUF][lk + 1][lrA] = (AV).y; \
         As[BUF][lk + 2][lrA] = (AV).z; As[BUF][lk + 3][lrA] = (AV).w; } while (0)
#define STS_B(BUF, WV) \
    do { Bs[BUF][lk + 0][lrB] = (WV).x; Bs[BUF][lk + 1][lrB] = (WV).y; \
         Bs[BUF][lk + 2][lrB] = (WV).z; Bs[BUF][lk + 3][lrB] = (WV).w; } while (0)

__global__ __launch_bounds__(256) void k_attn1() {
    constexpr int BMt = 32, BNt = 32;
    int m0 = blockIdx.y * BMt, n0 = blockIdx.x * BNt;
    if (n0 > m0) return;
    __shared__ __align__(16) float As[2][BK][BMt + 4];
    __shared__ __align__(16) float Bs[2][BK][BNt + 4];
    int tid = threadIdx.x;
    int z = blockIdx.z;
    int ty = tid >> 4, tx = tid & 15;
    bool doA = (tid < 128), doB = (tid >= 128);
    int lrA = tid >> 2, lrB = (tid & 127) >> 2, lk = (tid & 3) * 4;
    const float* Ap = g_q + (size_t)(z * Tt + m0 + lrA) * D2 + lk;
    const float* Wp = g_k + (size_t)(z * Tt + n0 + lrB) * D2 + lk;
    ull acc[1][2] = {};
    float4 a, w;
    if (doA) a = *(const float4*)Ap;
    if (doB) w = *(const float4*)Wp;
    if (doA) STS_A(0, a);
    if (doB) STS_B(0, w);
    __syncthreads();
    int buf = 0;
    for (int k0 = BK; k0 < D2; k0 += BK) {
        if (doA) a = *(const float4*)(Ap + k0);
        if (doB) w = *(const float4*)(Wp + k0);
        mma_t<32, 32>(As[buf], Bs[buf], ty, tx, acc);
        if (doA) STS_A(buf ^ 1, a);
        if (doB) STS_B(buf ^ 1, w);
        __syncthreads();
        buf ^= 1;
    }
    mma_t<32, 32>(As[buf], Bs[buf], ty, tx, acc);

    float2 lohi0 = unpackf2(acc[0][0]), lohi1 = unpackf2(acc[0][1]);
    float al0 = g_alpha[z * Tt + n0 + tx * 2];
    float al1 = g_alpha[z * Tt + n0 + tx * 2 + 1];
#pragma unroll
    for (int half = 0; half < 2; half++) {
        int t = m0 + ty * 2 + half;
        float be = g_beta[z * Tt + t];
        int s0 = n0 + tx * 2, s1 = s0 + 1;
        float v0 = (s0 <= t) ? __expf(al0 + be) * (half ? lohi0.y : lohi0.x) : 0.f;
        float v1 = (s1 <= t) ? __expf(al1 + be) * (half ? lohi1.y : lohi1.x) : 0.f;
        *(float2*)&g_A[(size_t)z * Tt * Tt + (size_t)t * Tt + s0] = make_float2(v0, v1);
        float p = v0 + v1;
#pragma unroll
        for (int off = 1; off < 16; off <<= 1) p += __shfl_xor_sync(0xffffffffu, p, off);
        if (tx == 0) atomicAdd(&g_rowsum[z * Tt + t], p);
    }
}

// attn2 + fused groupnorm partial stats (atomic into g_gnsum/g_gnsum2)
__global__ __launch_bounds__(256) void k_attn2() {
    constexpr int BMt = 32, BNt = 64;
    __shared__ __align__(16) float As[2][BK][BMt + 4];
    __shared__ __align__(16) float Bs[2][BK][BNt + 4];
    int tid = threadIdx.x;
    int z = blockIdx.z;
    int m0 = blockIdx.y * BMt, n0 = blockIdx.x * BNt;
    int ty = tid >> 4, tx = tid & 15;
    bool doA = (tid < 128);
    int lrA = tid >> 2, lk = (tid & 3) * 4;
    int brow = tid >> 4, bcol = (tid & 15) * 4;
    int Kend = m0 + BMt;
    const float* Ap = g_A + (size_t)z * Tt * Tt + (size_t)(m0 + lrA) * Tt + lk;
    const float* Vb = g_v + (size_t)z * Tt * D2;
    ull acc[1][4] = {};
    float4 a, w;
    if (doA) a = *(const float4*)Ap;
    w = *(const float4*)(Vb + (size_t)brow * D2 + n0 + bcol);
    if (doA) STS_A(0, a);
    *(float4*)&Bs[0][brow][bcol] = w;
    __syncthreads();
    int buf = 0;
    for (int k0 = BK; k0 < Kend; k0 += BK) {
        if (doA) a = *(const float4*)(Ap + k0);
        w = *(const float4*)(Vb + (size_t)(k0 + brow) * D2 + n0 + bcol);
        mma_t<32, 64>(As[buf], Bs[buf], ty, tx, acc);
        if (doA) STS_A(buf ^ 1, a);
        *(float4*)&Bs[buf ^ 1][brow][bcol] = w;
        __syncthreads();
        buf ^= 1;
    }
    mma_t<32, 64>(As[buf], Bs[buf], ty, tx, acc);

    float2 lohi[4];
#pragma unroll
    for (int j = 0; j < 4; j++) lohi[j] = unpackf2(acc[0][j]);
    float ps = 0.f, ps2 = 0.f;
#pragma unroll
    for (int half = 0; half < 2; half++) {
        int m = m0 + ty * 2 + half;
        int r = z * Tt + m;
        float rs = g_rowsum[r];
        float inv = 1.f / (fmaxf(fabsf(rs), 1.f) + 1e-8f);
        float4 og = *(const float4*)&g_o[(size_t)r * D2 + n0 + tx * 4];
        float4 ov = make_float4((half ? lohi[0].y : lohi[0].x) * inv * og.x,
                                (half ? lohi[1].y : lohi[1].x) * inv * og.y,
                                (half ? lohi[2].y : lohi[2].x) * inv * og.z,
                                (half ? lohi[3].y : lohi[3].x) * inv * og.w);
        *(float4*)&g_hseq[(size_t)r * D2 + n0 + tx * 4] = ov;
        ps += ov.x + ov.y + ov.z + ov.w;
        ps2 += ov.x * ov.x + ov.y * ov.y + ov.z * ov.z + ov.w * ov.w;
    }
    // groupnorm partial stats: this block lies entirely within one (batch, head)
#pragma unroll
    for (int off = 16; off; off >>= 1) {
        ps += __shfl_xor_sync(0xffffffffu, ps, off);
        ps2 += __shfl_xor_sync(0xffffffffu, ps2, off);
    }
    if ((tid & 31) == 0) {
        int bh = z * 4 + (n0 >> 7);
        atomicAdd(&g_gnsum[bh], ps);
        atomicAdd(&g_gnsum2[bh], ps2);
    }
}

// ---------------- launch ----------------
extern "C" void kernel_launch(void* const* d_in, const int* in_sizes, int n_in,
                              void* d_out, int out_size) {
    const float* x       = (const float*)d_in[0];
    const float* ln_g    = (const float*)d_in[1];
    const float* ln_b    = (const float*)d_in[2];
    const float* W_left  = (const float*)d_in[3];
    const float* b_left  = (const float*)d_in[4];
    const float* W_right = (const float*)d_in[5];
    const float* b_right = (const float*)d_in[6];
    const float* Wi      = (const float*)d_in[7];
    const float* bi      = (const float*)d_in[8];
    const float* Wf      = (const float*)d_in[9];
    const float* bf      = (const float*)d_in[10];
    const float* Wo      = (const float*)d_in[11];
    const float* bo      = (const float*)d_in[12];
    const float* Wq      = (const float*)d_in[13];
    const float* Wk      = (const float*)d_in[14];
    const float* Wv      = (const float*)d_in[15];
    const float* conv_w  = (const float*)d_in[16];
    const float* conv_b  = (const float*)d_in[17];
    const float* skip_W  = (const float*)d_in[18];
    const float* gn_g    = (const float*)d_in[19];
    const float* gn_b    = (const float*)d_in[20];
    const float* W_last  = (const float*)d_in[21];
    const float* b_last  = (const float*)d_in[22];
    float* out = (float*)d_out;

    float *p_xleft, *p_xright;
    uint *p_xnh, *p_xnl, *p_wth, *p_wtl, *p_xth, *p_xtl, *p_hh, *p_hl;
    cudaGetSymbolAddress((void**)&p_xleft, g_xleft);
    cudaGetSymbolAddress((void**)&p_xright, g_xright);
    cudaGetSymbolAddress((void**)&p_xnh, g_xnh_u);
    cudaGetSymbolAddress((void**)&p_xnl, g_xnl_u);
    cudaGetSymbolAddress((void**)&p_wth, g_wt_h);
    cudaGetSymbolAddress((void**)&p_wtl, g_wt_l);
    cudaGetSymbolAddress((void**)&p_xth, g_xth_u);
    cudaGetSymbolAddress((void**)&p_xtl, g_xtl_u);
    cudaGetSymbolAddress((void**)&p_hh, g_hh_u);
    cudaGetSymbolAddress((void**)&p_hl, g_hl_u);

    k_pre<<<4224, 256>>>(x, ln_g, ln_b, conv_w, Wo, W_left, W_right,
                         Wq, Wk, Wv, skip_W, W_last);
    k_hgemm<<<dim3(8, 8, 2), 256>>>(p_xnh, p_xnl, 128,
                                    p_wth + OFF_WL, p_wtl + OFF_WL, 128,
                                    8, b_left, p_xleft, 512, 0,
                                    p_wth + OFF_WR, p_wtl + OFF_WR, b_right, p_xright,
                                    nullptr);
    k_cwo<<<dim3(8, 8, 11), 256>>>(Wi, Wf, bi, bf);
    k_cwepi<<<513, 256>>>(conv_b, bo);
    k_hqkv<<<dim3(2, 8, 12), 256>>>();
    k_attn1<<<dim3(8, 8, 4), 256>>>();
    k_attn2<<<dim3(8, 8, 4), 256>>>();
    k_hgemm<<<dim3(8, 8, 1), 256>>>(p_xth, p_xtl, 256,
                                    p_wth + OFF_SK, p_wtl + OFF_SK, 256,
                                    16, gn_g, nullptr, 512, 2,
                                    nullptr, nullptr, gn_b, nullptr, nullptr);
    k_hgemm<<<dim3(4, 8, 1), 256>>>(p_hh, p_hl, 256,
                                    p_wth + OFF_LA, p_wtl + OFF_LA, 256,
                                    16, b_last, out, 256, 3,
                                    nullptr, nullptr, nullptr, nullptr, x);
}